// round 2
// baseline (speedup 1.0000x reference)
#include <cuda_runtime.h>
#include <math.h>

// ---------------- problem constants ----------------
constexpr int B_  = 2;
constexpr int L_  = 2048;
constexpr int DM  = 1024;
constexpr int DS  = 128;
constexpr int DC  = 4;
constexpr int HD  = 64;
constexpr int DI  = 2048;      // EXP*DM
constexpr int NH  = 32;        // DI/HD
constexpr int CONV = DI + 2*DS;        // 2304
constexpr int DIN  = 2*DI + 2*DS + NH; // 4384
constexpr int CS  = 256;
constexpr int NC  = L_ / CS;   // 8
constexpr int BL  = B_ * L_;   // 4096
constexpr float EPS = 1e-5f;

// ---------------- scratch (static device globals; no cudaMalloc allowed) ----
__device__ float g_xn[BL * DM];
__device__ float g_zx[(size_t)BL * DIN];
__device__ float g_xBC[(size_t)BL * CONV];
__device__ float g_dt[BL * NH];
__device__ float g_dA[BL * NH];
__device__ float g_Acs[B_ * NC * NH * CS];
__device__ float g_G[(size_t)B_ * NC * CS * CS];
__device__ float g_states[(size_t)B_ * NC * NH * HD * DS];
__device__ float g_Sprev[(size_t)B_ * NC * NH * HD * DS];
__device__ float g_Y[(size_t)BL * DI];
__device__ float g_yn[(size_t)BL * DI];

// ---------------- RMSNorm on input ----------------
__global__ void rms_kernel(const float* __restrict__ x, const float* __restrict__ norm_w) {
    int r = blockIdx.x, tid = threadIdx.x;
    __shared__ float red[256];
    float v[4]; float sum = 0.f;
#pragma unroll
    for (int j = 0; j < 4; j++) {
        int i = tid + j * 256;
        v[j] = x[(size_t)r * DM + i];
        sum += v[j] * v[j];
    }
    red[tid] = sum; __syncthreads();
    for (int s = 128; s > 0; s >>= 1) { if (tid < s) red[tid] += red[tid + s]; __syncthreads(); }
    float rinv = rsqrtf(red[0] / DM + EPS);
#pragma unroll
    for (int j = 0; j < 4; j++) {
        int i = tid + j * 256;
        g_xn[(size_t)r * DM + i] = v[j] * rinv * norm_w[i];
    }
}

// ---------------- generic SGEMM: C[M,N] = A[M,K] @ W[N,K]^T (+res) ----------
// BM=128, BN=64, BK=16, 256 threads, 8x4 per-thread tile.
__global__ __launch_bounds__(256) void sgemm_kernel(
    const float* __restrict__ A, int lda,
    const float* __restrict__ W, int ldw,
    float* __restrict__ C, int ldc,
    const float* __restrict__ res, int ldr,
    int M, int N, int K)
{
    __shared__ float As[16][128];
    __shared__ float Ws[16][64];
    int tid = threadIdx.x;
    int tx = tid & 15, ty = tid >> 4;
    int rowBase = blockIdx.y * 128;
    int colBase = blockIdx.x * 64;

    float acc[8][4];
#pragma unroll
    for (int i = 0; i < 8; i++)
#pragma unroll
        for (int j = 0; j < 4; j++) acc[i][j] = 0.f;

    for (int k0 = 0; k0 < K; k0 += 16) {
        // A tile: 128 rows x 16 k  (512 float4, 2 per thread)
#pragma unroll
        for (int i = 0; i < 2; i++) {
            int t = tid + i * 256;
            int r = t >> 2, kq = t & 3;
            float4 v = *(const float4*)&A[(size_t)(rowBase + r) * lda + k0 + kq * 4];
            As[kq * 4 + 0][r] = v.x; As[kq * 4 + 1][r] = v.y;
            As[kq * 4 + 2][r] = v.z; As[kq * 4 + 3][r] = v.w;
        }
        // W tile: 64 rows(n) x 16 k (256 float4, 1 per thread)
        {
            int r = tid >> 2, kq = tid & 3;
            int n = colBase + r;
            float4 v = make_float4(0.f, 0.f, 0.f, 0.f);
            if (n < N) v = *(const float4*)&W[(size_t)n * ldw + k0 + kq * 4];
            Ws[kq * 4 + 0][r] = v.x; Ws[kq * 4 + 1][r] = v.y;
            Ws[kq * 4 + 2][r] = v.z; Ws[kq * 4 + 3][r] = v.w;
        }
        __syncthreads();
#pragma unroll
        for (int kk = 0; kk < 16; kk++) {
            float4 a0 = *(const float4*)&As[kk][ty * 8];
            float4 a1 = *(const float4*)&As[kk][ty * 8 + 4];
            float4 b0 = *(const float4*)&Ws[kk][tx * 4];
            float a[8] = {a0.x, a0.y, a0.z, a0.w, a1.x, a1.y, a1.z, a1.w};
            float b[4] = {b0.x, b0.y, b0.z, b0.w};
#pragma unroll
            for (int i = 0; i < 8; i++)
#pragma unroll
                for (int j = 0; j < 4; j++) acc[i][j] += a[i] * b[j];
        }
        __syncthreads();
    }
#pragma unroll
    for (int i = 0; i < 8; i++) {
        int r = rowBase + ty * 8 + i;
#pragma unroll
        for (int j = 0; j < 4; j++) {
            int c = colBase + tx * 4 + j;
            if (c < N) {
                float v = acc[i][j];
                if (res) v += res[(size_t)r * ldr + c];
                C[(size_t)r * ldc + c] = v;
            }
        }
    }
}

// ---------------- depthwise causal conv(4) + SiLU ----------------
__global__ void conv_kernel(const float* __restrict__ conv_w, const float* __restrict__ conv_b) {
    int r = blockIdx.x;
    int bi = r / L_, l = r % L_;
    for (int c = threadIdx.x; c < CONV; c += 256) {
        float s = conv_b[c];
#pragma unroll
        for (int k = 0; k < DC; k++) {
            int lt = l + k - (DC - 1);
            if (lt >= 0)
                s += g_zx[(size_t)(bi * L_ + lt) * DIN + DI + c] * conv_w[c * DC + k];
        }
        float sig = 1.f / (1.f + __expf(-s));
        g_xBC[(size_t)r * CONV + c] = s * sig;
    }
}

// ---------------- dt = softplus(dt+bias), dA = dt*A ----------------
__global__ void dtprep_kernel(const float* __restrict__ dt_bias, const float* __restrict__ A_log) {
    int i = blockIdx.x * 256 + threadIdx.x;  // < BL*NH
    int h = i & (NH - 1);
    int r = i >> 5;
    float v = g_zx[(size_t)r * DIN + (DIN - NH) + h] + dt_bias[h];
    float dtv = (v > 20.f) ? v : log1pf(__expf(v));
    g_dt[i] = dtv;
    g_dA[i] = -__expf(A_log[h]) * dtv;
}

// ---------------- per-chunk inclusive cumsum of dA ----------------
__global__ void acs_kernel() {
    int blk = blockIdx.x, tid = threadIdx.x;
    int bi = blk / (NC * NH);
    int rem = blk % (NC * NH);
    int c = rem / NH, h = rem % NH;
    __shared__ float s[CS];
    int t = bi * L_ + c * CS + tid;
    s[tid] = g_dA[t * NH + h];
    __syncthreads();
    for (int off = 1; off < CS; off <<= 1) {
        float v = (tid >= off) ? s[tid - off] : 0.f;
        __syncthreads();
        s[tid] += v;
        __syncthreads();
    }
    g_Acs[blk * CS + tid] = s[tid];
}

// ---------------- Y_diag + D*xh : block per (b,chunk,head) ----------------
__global__ __launch_bounds__(256) void diag_kernel(const float* __restrict__ Dp) {
    int blk = blockIdx.x, tid = threadIdx.x;
    int bi = blk / (NC * NH);
    int rem = blk % (NC * NH);
    int c = rem / NH, h = rem % NH;
    __shared__ float Xs[128][64];    // 32 KB
    __shared__ float Acss[CS];
    int rowBase = bi * L_ + c * CS;
    Acss[tid] = g_Acs[blk * CS + tid];
    __syncthreads();
    int l = tid;
    float acsl = Acss[l];
    const float* Grow = &g_G[((size_t)(bi * NC + c) * CS + l) * CS];
    float dH = Dp[h];

    for (int ph = 0; ph < 2; ph++) {
        float y[32];
#pragma unroll
        for (int p = 0; p < 32; p++) y[p] = 0.f;
        for (int s0 = 0; s0 < CS; s0 += 128) {
            __syncthreads();
#pragma unroll
            for (int i = 0; i < 32; i++) {
                int lin = tid + i * 256;
                int s = lin >> 6, p = lin & 63;
                int t = rowBase + s0 + s;
                Xs[s][p] = g_xBC[(size_t)t * CONV + h * HD + p] * g_dt[t * NH + h];
            }
            __syncthreads();
            int smax = l - s0; if (smax > 127) smax = 127;
            for (int s = 0; s <= smax; s++) {
                float coef = Grow[s0 + s] * __expf(acsl - Acss[s0 + s]);
#pragma unroll
                for (int p = 0; p < 32; p++) y[p] += coef * Xs[s][ph * 32 + p];
            }
        }
        int t = rowBase + l;
        size_t ob = (size_t)t * DI + h * HD + ph * 32;
#pragma unroll
        for (int p = 0; p < 32; p++) {
            float xh = g_xBC[(size_t)t * CONV + h * HD + ph * 32 + p];
            g_Y[ob + p] = y[p] + dH * xh;
        }
    }
}

// ---------------- per-chunk state: states[p,n] = sum_l B[l,n]*decay*X[l,p] ---
__global__ __launch_bounds__(256) void states_kernel() {
    int blk = blockIdx.x, tid = threadIdx.x;
    int bi = blk / (NC * NH);
    int rem = blk % (NC * NH);
    int c = rem / NH, h = rem % NH;
    __shared__ float Xs[32][64];   // 8 KB (decay-scaled X)
    __shared__ float Bs[32][128];  // 16 KB
    int rowBase = bi * L_ + c * CS;
    float acsLast = g_Acs[blk * CS + (CS - 1)];
    int tn = tid & 31, tp = tid >> 5;
    float acc[8][4];
#pragma unroll
    for (int i = 0; i < 8; i++)
#pragma unroll
        for (int j = 0; j < 4; j++) acc[i][j] = 0.f;

    for (int l0 = 0; l0 < CS; l0 += 32) {
        __syncthreads();
#pragma unroll
        for (int i = 0; i < 8; i++) {
            int lin = tid + i * 256;
            int s = lin >> 6, p = lin & 63;
            int t = rowBase + l0 + s;
            float w = __expf(acsLast - g_Acs[blk * CS + l0 + s]);
            Xs[s][p] = g_xBC[(size_t)t * CONV + h * HD + p] * g_dt[t * NH + h] * w;
        }
#pragma unroll
        for (int i = 0; i < 16; i++) {
            int lin = tid + i * 256;
            int s = lin >> 7, n = lin & 127;
            Bs[s][n] = g_xBC[(size_t)(rowBase + l0 + s) * CONV + DI + n];
        }
        __syncthreads();
#pragma unroll 4
        for (int ll = 0; ll < 32; ll++) {
            float4 xa = *(const float4*)&Xs[ll][tp * 8];
            float4 xb = *(const float4*)&Xs[ll][tp * 8 + 4];
            float4 bv = *(const float4*)&Bs[ll][tn * 4];
            float xv[8] = {xa.x, xa.y, xa.z, xa.w, xb.x, xb.y, xb.z, xb.w};
            float bw[4] = {bv.x, bv.y, bv.z, bv.w};
#pragma unroll
            for (int i = 0; i < 8; i++)
#pragma unroll
                for (int j = 0; j < 4; j++) acc[i][j] += xv[i] * bw[j];
        }
    }
    size_t base = (size_t)blk * HD * DS;
#pragma unroll
    for (int i = 0; i < 8; i++) {
        int p = tp * 8 + i;
#pragma unroll
        for (int j = 0; j < 4; j++) {
            int n = tn * 4 + j;
            g_states[base + (size_t)p * DS + n] = acc[i][j];
        }
    }
}

// ---------------- inter-chunk scan: Sprev[c] = running state before chunk c --
__global__ void cscan_kernel() {
    int bi = blockIdx.x / NH, h = blockIdx.x % NH;
    int tid = threadIdx.x;
    float P[32];
#pragma unroll
    for (int j = 0; j < 32; j++) P[j] = 0.f;
    for (int c = 0; c < NC; c++) {
        int cb = (bi * NC + c) * NH + h;
        size_t sb = (size_t)cb * HD * DS;
        float T = __expf(g_Acs[cb * CS + (CS - 1)]);
#pragma unroll
        for (int j = 0; j < 32; j++) {
            int e = tid + j * 256;
            g_Sprev[sb + e] = P[j];
            P[j] = P[j] * T + g_states[sb + e];
        }
    }
}

// ---------------- Y_off: y += exp(Acs[l]) * C[l,:] @ Sprev[p,:]^T ------------
__global__ __launch_bounds__(256) void yoff_kernel() {
    int blk = blockIdx.x, tid = threadIdx.x;
    int bi = blk / (NC * NH);
    int rem = blk % (NC * NH);
    int c = rem / NH, h = rem % NH;
    __shared__ float Ss[64][128];  // 32 KB
    size_t sb = (size_t)blk * HD * DS;
#pragma unroll
    for (int i = 0; i < 32; i++) {
        int lin = tid + i * 256;
        Ss[lin >> 7][lin & 127] = g_Sprev[sb + lin];
    }
    int l = tid;
    int t = bi * L_ + c * CS + l;
    float scale = __expf(g_Acs[blk * CS + l]);
    const float* Crow = &g_xBC[(size_t)t * CONV + DI + DS];
    __syncthreads();

    for (int pg = 0; pg < 4; pg++) {
        float acc[16];
#pragma unroll
        for (int pi = 0; pi < 16; pi++) acc[pi] = 0.f;
        for (int n = 0; n < DS; n++) {
            float cv = Crow[n];
#pragma unroll
            for (int pi = 0; pi < 16; pi++) acc[pi] += cv * Ss[pg * 16 + pi][n];
        }
        size_t ob = (size_t)t * DI + h * HD + pg * 16;
#pragma unroll
        for (int pi = 0; pi < 16; pi++) g_Y[ob + pi] += scale * acc[pi];
    }
}

// ---------------- gate with silu(z) then group-RMS over DI -------------------
__global__ void gate_kernel(const float* __restrict__ gnorm_w) {
    int r = blockIdx.x, tid = threadIdx.x;
    __shared__ float red[256];
    float g[8]; float sum = 0.f;
#pragma unroll
    for (int j = 0; j < 8; j++) {
        int i = tid + j * 256;
        float yv = g_Y[(size_t)r * DI + i];
        float z = g_zx[(size_t)r * DIN + i];
        float s = 1.f / (1.f + __expf(-z));
        float gv = yv * z * s;
        g[j] = gv; sum += gv * gv;
    }
    red[tid] = sum; __syncthreads();
    for (int s = 128; s > 0; s >>= 1) { if (tid < s) red[tid] += red[tid + s]; __syncthreads(); }
    float rinv = rsqrtf(red[0] / DI + EPS);
#pragma unroll
    for (int j = 0; j < 8; j++) {
        int i = tid + j * 256;
        g_yn[(size_t)r * DI + i] = g[j] * rinv * gnorm_w[i];
    }
}

// ---------------- launch ----------------
extern "C" void kernel_launch(void* const* d_in, const int* in_sizes, int n_in,
                              void* d_out, int out_size) {
    const float* x          = (const float*)d_in[0];
    const float* norm_w     = (const float*)d_in[1];
    const float* in_proj_w  = (const float*)d_in[2];
    const float* conv_w     = (const float*)d_in[3];
    const float* conv_b     = (const float*)d_in[4];
    const float* dt_bias    = (const float*)d_in[5];
    const float* A_log      = (const float*)d_in[6];
    const float* Dp         = (const float*)d_in[7];
    const float* gnorm_w    = (const float*)d_in[8];
    const float* out_proj_w = (const float*)d_in[9];
    float* out = (float*)d_out;

    float *xn, *zx, *xBC, *Gb, *yn;
    cudaGetSymbolAddress((void**)&xn,  g_xn);
    cudaGetSymbolAddress((void**)&zx,  g_zx);
    cudaGetSymbolAddress((void**)&xBC, g_xBC);
    cudaGetSymbolAddress((void**)&Gb,  g_G);
    cudaGetSymbolAddress((void**)&yn,  g_yn);

    rms_kernel<<<BL, 256>>>(x, norm_w);

    // zxbcdt = xn @ in_proj_w^T   (4096 x 4384 x 1024)
    sgemm_kernel<<<dim3((DIN + 63) / 64, BL / 128), 256>>>(
        xn, DM, in_proj_w, DM, zx, DIN, nullptr, 0, BL, DIN, DM);

    conv_kernel<<<BL, 256>>>(conv_w, conv_b);
    dtprep_kernel<<<BL * NH / 256, 256>>>(dt_bias, A_log);
    acs_kernel<<<B_ * NC * NH, 256>>>();

    // G[b,c] = Cm @ Bm^T per chunk (256 x 256 x 128)
    for (int bi = 0; bi < B_; bi++)
        for (int c = 0; c < NC; c++) {
            const float* Cp = xBC + (size_t)(bi * L_ + c * CS) * CONV + DI + DS;
            const float* Bp = xBC + (size_t)(bi * L_ + c * CS) * CONV + DI;
            float* Gp = Gb + (size_t)(bi * NC + c) * CS * CS;
            sgemm_kernel<<<dim3(CS / 64, CS / 128), 256>>>(
                Cp, CONV, Bp, CONV, Gp, CS, nullptr, 0, CS, CS, DS);
        }

    diag_kernel<<<B_ * NC * NH, 256>>>(Dp);
    states_kernel<<<B_ * NC * NH, 256>>>();
    cscan_kernel<<<B_ * NH, 256>>>();
    yoff_kernel<<<B_ * NC * NH, 256>>>();
    gate_kernel<<<BL, 256>>>(gnorm_w);

    // out = x + yn @ out_proj_w^T   (4096 x 1024 x 2048)
    sgemm_kernel<<<dim3(DM / 64, BL / 128), 256>>>(
        yn, DI, out_proj_w, DI, out, DM, x, DM, BL, DM, DI);
}

// round 3
// speedup vs baseline: 1.1749x; 1.1749x over previous
#include <cuda_runtime.h>
#include <math.h>

// ---------------- problem constants ----------------
constexpr int B_  = 2;
constexpr int L_  = 2048;
constexpr int DM  = 1024;
constexpr int DS  = 128;
constexpr int DC  = 4;
constexpr int HD  = 64;
constexpr int DI  = 2048;      // EXP*DM
constexpr int NH  = 32;        // DI/HD
constexpr int CONV = DI + 2*DS;        // 2304
constexpr int DIN  = 2*DI + 2*DS + NH; // 4384
constexpr int CS  = 256;
constexpr int NC  = L_ / CS;   // 8
constexpr int BL  = B_ * L_;   // 4096
constexpr float EPS = 1e-5f;

// ---------------- scratch (static device globals; no cudaMalloc allowed) ----
__device__ float g_xn[BL * DM];
__device__ float g_zx[(size_t)BL * DIN];
__device__ float g_xBC[(size_t)BL * CONV];
__device__ float g_dt[BL * NH];
__device__ float g_Acs[B_ * NC * NH * CS];
__device__ float g_G[(size_t)B_ * NC * CS * CS];
__device__ float g_states[(size_t)B_ * NC * NH * HD * DS];
__device__ float g_Sprev[(size_t)B_ * NC * NH * HD * DS];
__device__ float g_Y[(size_t)BL * DI];
__device__ float g_yn[(size_t)BL * DI];

// ---------------- packed f32x2 helpers (Blackwell FFMA2 path) ----------------
typedef unsigned long long ull;

__device__ __forceinline__ void ffma2(ull &d, ull a, ull b) {
    asm("fma.rn.f32x2 %0, %1, %2, %0;" : "+l"(d) : "l"(a), "l"(b));
}
__device__ __forceinline__ ull dup2(float v) {
    ull r;
    asm("mov.b64 %0, {%1, %1};" : "=l"(r) : "f"(v));
    return r;
}
__device__ __forceinline__ void unpack2(ull v, float &lo, float &hi) {
    asm("mov.b64 {%0, %1}, %2;" : "=f"(lo), "=f"(hi) : "l"(v));
}

// ---------------- RMSNorm on input ----------------
__global__ void rms_kernel(const float* __restrict__ x, const float* __restrict__ norm_w) {
    int r = blockIdx.x, tid = threadIdx.x;
    __shared__ float red[256];
    float v[4]; float sum = 0.f;
#pragma unroll
    for (int j = 0; j < 4; j++) {
        int i = tid + j * 256;
        v[j] = x[(size_t)r * DM + i];
        sum += v[j] * v[j];
    }
    red[tid] = sum; __syncthreads();
    for (int s = 128; s > 0; s >>= 1) { if (tid < s) red[tid] += red[tid + s]; __syncthreads(); }
    float rinv = rsqrtf(red[0] / DM + EPS);
#pragma unroll
    for (int j = 0; j < 4; j++) {
        int i = tid + j * 256;
        g_xn[(size_t)r * DM + i] = v[j] * rinv * norm_w[i];
    }
}

// ---------------- SGEMM via packed f32x2: C[M,N] = A[M,K] @ W[N,K]^T (+res) --
// BM=128, BN=128, BK=16, 256 threads (16x16), 8x8 per-thread micro-tile.
// Accumulators are 32 packed f32x2 pairs (rows paired), inner loop 32 FFMA2.
__global__ __launch_bounds__(256, 2) void sgemm2_kernel(
    const float* __restrict__ A, int lda, size_t batchA,
    const float* __restrict__ W, int ldw, size_t batchW,
    float* __restrict__ C, int ldc, size_t batchC,
    const float* __restrict__ res, int ldr,
    int M, int N, int K)
{
    __shared__ float As[16][132];
    __shared__ float Ws[16][132];
    int tid = threadIdx.x;
    int tx = tid & 15, ty = tid >> 4;
    const float* Ab = A + (size_t)blockIdx.z * batchA;
    const float* Wb = W + (size_t)blockIdx.z * batchW;
    float*       Cb = C + (size_t)blockIdx.z * batchC;
    int rowBase = blockIdx.y * 128;
    int colBase = blockIdx.x * 128;

    ull acc[32];
#pragma unroll
    for (int i = 0; i < 32; i++) acc[i] = 0ULL;

    for (int k0 = 0; k0 < K; k0 += 16) {
        // A tile: 128 rows x 16 k  (512 float4, 2 per thread), stored k-major
#pragma unroll
        for (int i = 0; i < 2; i++) {
            int t = tid + i * 256;
            int r = t >> 2, kq = t & 3;
            float4 v = *(const float4*)&Ab[(size_t)(rowBase + r) * lda + k0 + kq * 4];
            As[kq * 4 + 0][r] = v.x; As[kq * 4 + 1][r] = v.y;
            As[kq * 4 + 2][r] = v.z; As[kq * 4 + 3][r] = v.w;
        }
        // W tile: 128 n-rows x 16 k, stored k-major, zero-fill beyond N
#pragma unroll
        for (int i = 0; i < 2; i++) {
            int t = tid + i * 256;
            int r = t >> 2, kq = t & 3;
            int n = colBase + r;
            float4 v = make_float4(0.f, 0.f, 0.f, 0.f);
            if (n < N) v = *(const float4*)&Wb[(size_t)n * ldw + k0 + kq * 4];
            Ws[kq * 4 + 0][r] = v.x; Ws[kq * 4 + 1][r] = v.y;
            Ws[kq * 4 + 2][r] = v.z; Ws[kq * 4 + 3][r] = v.w;
        }
        __syncthreads();
#pragma unroll
        for (int kk = 0; kk < 16; kk++) {
            // 8 A rows as 4 packed pairs
            ulonglong2 a01 = *(const ulonglong2*)&As[kk][ty * 8];
            ulonglong2 a23 = *(const ulonglong2*)&As[kk][ty * 8 + 4];
            ull a[4] = {a01.x, a01.y, a23.x, a23.y};
            // 8 W cols, duplicated into packed pairs
            float4 b0 = *(const float4*)&Ws[kk][tx * 8];
            float4 b1 = *(const float4*)&Ws[kk][tx * 8 + 4];
            ull bd[8] = {dup2(b0.x), dup2(b0.y), dup2(b0.z), dup2(b0.w),
                         dup2(b1.x), dup2(b1.y), dup2(b1.z), dup2(b1.w)};
#pragma unroll
            for (int ip = 0; ip < 4; ip++)
#pragma unroll
                for (int j = 0; j < 8; j++)
                    ffma2(acc[ip * 8 + j], a[ip], bd[j]);
        }
        __syncthreads();
    }

    // epilogue: coalesced float4 stores, 8 cols per thread
    int c0 = colBase + tx * 8;
    bool cok = (c0 < N);  // N % 8 == 0 for all uses here
#pragma unroll
    for (int ip = 0; ip < 4; ip++) {
        float vlo[8], vhi[8];
#pragma unroll
        for (int j = 0; j < 8; j++) unpack2(acc[ip * 8 + j], vlo[j], vhi[j]);
        int r0 = rowBase + ty * 8 + ip * 2;
        if (cok) {
            if (res) {
                float4 e0 = *(const float4*)&res[(size_t)r0 * ldr + c0];
                float4 e1 = *(const float4*)&res[(size_t)r0 * ldr + c0 + 4];
                vlo[0]+=e0.x; vlo[1]+=e0.y; vlo[2]+=e0.z; vlo[3]+=e0.w;
                vlo[4]+=e1.x; vlo[5]+=e1.y; vlo[6]+=e1.z; vlo[7]+=e1.w;
                float4 f0 = *(const float4*)&res[(size_t)(r0+1) * ldr + c0];
                float4 f1 = *(const float4*)&res[(size_t)(r0+1) * ldr + c0 + 4];
                vhi[0]+=f0.x; vhi[1]+=f0.y; vhi[2]+=f0.z; vhi[3]+=f0.w;
                vhi[4]+=f1.x; vhi[5]+=f1.y; vhi[6]+=f1.z; vhi[7]+=f1.w;
            }
            *(float4*)&Cb[(size_t)r0 * ldc + c0]     = make_float4(vlo[0], vlo[1], vlo[2], vlo[3]);
            *(float4*)&Cb[(size_t)r0 * ldc + c0 + 4] = make_float4(vlo[4], vlo[5], vlo[6], vlo[7]);
            *(float4*)&Cb[(size_t)(r0+1) * ldc + c0]     = make_float4(vhi[0], vhi[1], vhi[2], vhi[3]);
            *(float4*)&Cb[(size_t)(r0+1) * ldc + c0 + 4] = make_float4(vhi[4], vhi[5], vhi[6], vhi[7]);
        }
    }
}

// ---------------- depthwise causal conv(4) + SiLU ----------------
__global__ void conv_kernel(const float* __restrict__ conv_w, const float* __restrict__ conv_b) {
    int r = blockIdx.x;
    int bi = r / L_, l = r % L_;
    for (int c = threadIdx.x; c < CONV; c += 256) {
        float s = conv_b[c];
#pragma unroll
        for (int k = 0; k < DC; k++) {
            int lt = l + k - (DC - 1);
            if (lt >= 0)
                s += g_zx[(size_t)(bi * L_ + lt) * DIN + DI + c] * conv_w[c * DC + k];
        }
        float sig = 1.f / (1.f + __expf(-s));
        g_xBC[(size_t)r * CONV + c] = s * sig;
    }
}

// ---------------- fused: dt=softplus(dt+bias), dA=dt*A, per-chunk cumsum ----
__global__ void acs_kernel(const float* __restrict__ dt_bias, const float* __restrict__ A_log) {
    int blk = blockIdx.x, tid = threadIdx.x;
    int bi = blk / (NC * NH);
    int rem = blk % (NC * NH);
    int c = rem / NH, h = rem % NH;
    __shared__ float s[CS];
    int t = bi * L_ + c * CS + tid;
    float v = g_zx[(size_t)t * DIN + (DIN - NH) + h] + dt_bias[h];
    float dtv = (v > 20.f) ? v : log1pf(__expf(v));
    g_dt[t * NH + h] = dtv;
    s[tid] = -__expf(A_log[h]) * dtv;
    __syncthreads();
    for (int off = 1; off < CS; off <<= 1) {
        float p = (tid >= off) ? s[tid - off] : 0.f;
        __syncthreads();
        s[tid] += p;
        __syncthreads();
    }
    g_Acs[blk * CS + tid] = s[tid];
}

// ---------------- Y_diag + D*xh : block per (b,chunk,head) ----------------
__global__ __launch_bounds__(256) void diag_kernel(const float* __restrict__ Dp) {
    int blk = blockIdx.x, tid = threadIdx.x;
    int bi = blk / (NC * NH);
    int rem = blk % (NC * NH);
    int c = rem / NH, h = rem % NH;
    __shared__ float Xs[128][64];
    __shared__ float Acss[CS];
    int rowBase = bi * L_ + c * CS;
    Acss[tid] = g_Acs[blk * CS + tid];
    __syncthreads();
    int l = tid;
    float acsl = Acss[l];
    const float* Grow = &g_G[((size_t)(bi * NC + c) * CS + l) * CS];
    float dH = Dp[h];

    for (int ph = 0; ph < 2; ph++) {
        float y[32];
#pragma unroll
        for (int p = 0; p < 32; p++) y[p] = 0.f;
        for (int s0 = 0; s0 < CS; s0 += 128) {
            __syncthreads();
#pragma unroll
            for (int i = 0; i < 32; i++) {
                int lin = tid + i * 256;
                int s = lin >> 6, p = lin & 63;
                int t = rowBase + s0 + s;
                Xs[s][p] = g_xBC[(size_t)t * CONV + h * HD + p] * g_dt[t * NH + h];
            }
            __syncthreads();
            int smax = l - s0; if (smax > 127) smax = 127;
            for (int s = 0; s <= smax; s++) {
                float coef = Grow[s0 + s] * __expf(acsl - Acss[s0 + s]);
#pragma unroll
                for (int p = 0; p < 32; p++) y[p] += coef * Xs[s][ph * 32 + p];
            }
        }
        int t = rowBase + l;
        size_t ob = (size_t)t * DI + h * HD + ph * 32;
#pragma unroll
        for (int p = 0; p < 32; p++) {
            float xh = g_xBC[(size_t)t * CONV + h * HD + ph * 32 + p];
            g_Y[ob + p] = y[p] + dH * xh;
        }
    }
}

// ---------------- per-chunk state: states[p,n] = sum_l B[l,n]*decay*X[l,p] ---
__global__ __launch_bounds__(256) void states_kernel() {
    int blk = blockIdx.x, tid = threadIdx.x;
    int bi = blk / (NC * NH);
    int rem = blk % (NC * NH);
    int c = rem / NH, h = rem % NH;
    __shared__ float Xs[32][64];
    __shared__ float Bs[32][128];
    int rowBase = bi * L_ + c * CS;
    float acsLast = g_Acs[blk * CS + (CS - 1)];
    int tn = tid & 31, tp = tid >> 5;
    float acc[8][4];
#pragma unroll
    for (int i = 0; i < 8; i++)
#pragma unroll
        for (int j = 0; j < 4; j++) acc[i][j] = 0.f;

    for (int l0 = 0; l0 < CS; l0 += 32) {
        __syncthreads();
#pragma unroll
        for (int i = 0; i < 8; i++) {
            int lin = tid + i * 256;
            int s = lin >> 6, p = lin & 63;
            int t = rowBase + l0 + s;
            float w = __expf(acsLast - g_Acs[blk * CS + l0 + s]);
            Xs[s][p] = g_xBC[(size_t)t * CONV + h * HD + p] * g_dt[t * NH + h] * w;
        }
#pragma unroll
        for (int i = 0; i < 16; i++) {
            int lin = tid + i * 256;
            int s = lin >> 7, n = lin & 127;
            Bs[s][n] = g_xBC[(size_t)(rowBase + l0 + s) * CONV + DI + n];
        }
        __syncthreads();
#pragma unroll 4
        for (int ll = 0; ll < 32; ll++) {
            float4 xa = *(const float4*)&Xs[ll][tp * 8];
            float4 xb = *(const float4*)&Xs[ll][tp * 8 + 4];
            float4 bv = *(const float4*)&Bs[ll][tn * 4];
            float xv[8] = {xa.x, xa.y, xa.z, xa.w, xb.x, xb.y, xb.z, xb.w};
            float bw[4] = {bv.x, bv.y, bv.z, bv.w};
#pragma unroll
            for (int i = 0; i < 8; i++)
#pragma unroll
                for (int j = 0; j < 4; j++) acc[i][j] += xv[i] * bw[j];
        }
    }
    size_t base = (size_t)blk * HD * DS;
#pragma unroll
    for (int i = 0; i < 8; i++) {
        int p = tp * 8 + i;
#pragma unroll
        for (int j = 0; j < 4; j++) {
            int n = tn * 4 + j;
            g_states[base + (size_t)p * DS + n] = acc[i][j];
        }
    }
}

// ---------------- inter-chunk scan: Sprev[c] = running state before chunk c --
__global__ void cscan_kernel() {
    int bi = blockIdx.x / NH, h = blockIdx.x % NH;
    int tid = threadIdx.x;
    float P[32];
#pragma unroll
    for (int j = 0; j < 32; j++) P[j] = 0.f;
    for (int c = 0; c < NC; c++) {
        int cb = (bi * NC + c) * NH + h;
        size_t sb = (size_t)cb * HD * DS;
        float T = __expf(g_Acs[cb * CS + (CS - 1)]);
#pragma unroll
        for (int j = 0; j < 32; j++) {
            int e = tid + j * 256;
            g_Sprev[sb + e] = P[j];
            P[j] = P[j] * T + g_states[sb + e];
        }
    }
}

// ---------------- Y_off: y += exp(Acs[l]) * C[l,:] @ Sprev[p,:]^T ------------
__global__ __launch_bounds__(256) void yoff_kernel() {
    int blk = blockIdx.x, tid = threadIdx.x;
    int bi = blk / (NC * NH);
    int rem = blk % (NC * NH);
    int c = rem / NH, h = rem % NH;
    __shared__ float Ss[64][128];
    size_t sb = (size_t)blk * HD * DS;
#pragma unroll
    for (int i = 0; i < 32; i++) {
        int lin = tid + i * 256;
        Ss[lin >> 7][lin & 127] = g_Sprev[sb + lin];
    }
    int l = tid;
    int t = bi * L_ + c * CS + l;
    float scale = __expf(g_Acs[blk * CS + l]);
    const float* Crow = &g_xBC[(size_t)t * CONV + DI + DS];
    __syncthreads();

    for (int pg = 0; pg < 4; pg++) {
        float acc[16];
#pragma unroll
        for (int pi = 0; pi < 16; pi++) acc[pi] = 0.f;
        for (int n = 0; n < DS; n++) {
            float cv = Crow[n];
#pragma unroll
            for (int pi = 0; pi < 16; pi++) acc[pi] += cv * Ss[pg * 16 + pi][n];
        }
        size_t ob = (size_t)t * DI + h * HD + pg * 16;
#pragma unroll
        for (int pi = 0; pi < 16; pi++) g_Y[ob + pi] += scale * acc[pi];
    }
}

// ---------------- gate with silu(z) then group-RMS over DI -------------------
__global__ void gate_kernel(const float* __restrict__ gnorm_w) {
    int r = blockIdx.x, tid = threadIdx.x;
    __shared__ float red[256];
    float g[8]; float sum = 0.f;
#pragma unroll
    for (int j = 0; j < 8; j++) {
        int i = tid + j * 256;
        float yv = g_Y[(size_t)r * DI + i];
        float z = g_zx[(size_t)r * DIN + i];
        float s = 1.f / (1.f + __expf(-z));
        float gv = yv * z * s;
        g[j] = gv; sum += gv * gv;
    }
    red[tid] = sum; __syncthreads();
    for (int s = 128; s > 0; s >>= 1) { if (tid < s) red[tid] += red[tid + s]; __syncthreads(); }
    float rinv = rsqrtf(red[0] / DI + EPS);
#pragma unroll
    for (int j = 0; j < 8; j++) {
        int i = tid + j * 256;
        g_yn[(size_t)r * DI + i] = g[j] * rinv * gnorm_w[i];
    }
}

// ---------------- launch ----------------
extern "C" void kernel_launch(void* const* d_in, const int* in_sizes, int n_in,
                              void* d_out, int out_size) {
    const float* x          = (const float*)d_in[0];
    const float* norm_w     = (const float*)d_in[1];
    const float* in_proj_w  = (const float*)d_in[2];
    const float* conv_w     = (const float*)d_in[3];
    const float* conv_b     = (const float*)d_in[4];
    const float* dt_bias    = (const float*)d_in[5];
    const float* A_log      = (const float*)d_in[6];
    const float* Dp         = (const float*)d_in[7];
    const float* gnorm_w    = (const float*)d_in[8];
    const float* out_proj_w = (const float*)d_in[9];
    float* out = (float*)d_out;

    float *xn, *zx, *xBC, *Gb, *yn;
    cudaGetSymbolAddress((void**)&xn,  g_xn);
    cudaGetSymbolAddress((void**)&zx,  g_zx);
    cudaGetSymbolAddress((void**)&xBC, g_xBC);
    cudaGetSymbolAddress((void**)&Gb,  g_G);
    cudaGetSymbolAddress((void**)&yn,  g_yn);

    rms_kernel<<<BL, 256>>>(x, norm_w);

    // zxbcdt = xn @ in_proj_w^T   (4096 x 4384 x 1024)
    sgemm2_kernel<<<dim3((DIN + 127) / 128, BL / 128, 1), 256>>>(
        xn, DM, 0, in_proj_w, DM, 0, zx, DIN, 0, nullptr, 0, BL, DIN, DM);

    conv_kernel<<<BL, 256>>>(conv_w, conv_b);
    acs_kernel<<<B_ * NC * NH, 256>>>(dt_bias, A_log);

    // G[b,c] = Cm @ Bm^T per chunk (256 x 256 x 128), batched over 16 chunks
    sgemm2_kernel<<<dim3(CS / 128, CS / 128, B_ * NC), 256>>>(
        xBC + DI + DS, CONV, (size_t)CS * CONV,
        xBC + DI,      CONV, (size_t)CS * CONV,
        Gb, CS, (size_t)CS * CS,
        nullptr, 0, CS, CS, DS);

    diag_kernel<<<B_ * NC * NH, 256>>>(Dp);
    states_kernel<<<B_ * NC * NH, 256>>>();
    cscan_kernel<<<B_ * NH, 256>>>();
    yoff_kernel<<<B_ * NC * NH, 256>>>();
    gate_kernel<<<BL, 256>>>(gnorm_w);

    // out = x + yn @ out_proj_w^T   (4096 x 1024 x 2048)
    sgemm2_kernel<<<dim3(DM / 128, BL / 128, 1), 256>>>(
        yn, DI, 0, out_proj_w, DI, 0, out, DM, 0, x, DM, BL, DM, DI);
}

// round 4
// speedup vs baseline: 1.6289x; 1.3865x over previous
#include <cuda_runtime.h>
#include <cuda_bf16.h>
#include <math.h>
#include <stdint.h>

// ---------------- problem constants ----------------
constexpr int B_  = 2;
constexpr int L_  = 2048;
constexpr int DM  = 1024;
constexpr int DS  = 128;
constexpr int DC  = 4;
constexpr int HD  = 64;
constexpr int DI  = 2048;      // EXP*DM
constexpr int NH  = 32;        // DI/HD
constexpr int CONV = DI + 2*DS;        // 2304
constexpr int DIN  = 2*DI + 2*DS + NH; // 4384
constexpr int CS  = 256;
constexpr int NC  = L_ / CS;   // 8
constexpr int BL  = B_ * L_;   // 4096
constexpr float EPS = 1e-5f;

// ---------------- scratch (static device globals; no cudaMalloc allowed) ----
__device__ float g_zx[(size_t)BL * DIN];
__device__ float g_xBC[(size_t)BL * CONV];
__device__ float g_dt[BL * NH];
__device__ float g_Acs[B_ * NC * NH * CS];
__device__ float g_G[(size_t)B_ * NC * CS * CS];
__device__ float g_states[(size_t)B_ * NC * NH * HD * DS];
__device__ float g_Sprev[(size_t)B_ * NC * NH * HD * DS];
__device__ float g_Y[(size_t)BL * DI];

// bf16 split buffers (hi/lo) for tensor-core GEMMs
__device__ __nv_bfloat16 g_xnh[(size_t)BL * DM];
__device__ __nv_bfloat16 g_xnl[(size_t)BL * DM];
__device__ __nv_bfloat16 g_wih[(size_t)DIN * DM];
__device__ __nv_bfloat16 g_wil[(size_t)DIN * DM];
__device__ __nv_bfloat16 g_ynh[(size_t)BL * DI];
__device__ __nv_bfloat16 g_ynl[(size_t)BL * DI];
__device__ __nv_bfloat16 g_woh[(size_t)DM * DI];
__device__ __nv_bfloat16 g_wol[(size_t)DM * DI];

// ---------------- helpers ----------------
__device__ __forceinline__ void bsplit(float v, __nv_bfloat16 &hi, __nv_bfloat16 &lo) {
    hi = __float2bfloat16_rn(v);
    lo = __float2bfloat16_rn(v - __bfloat162float(hi));
}

__device__ __forceinline__ void ldsm4(uint32_t &r0, uint32_t &r1, uint32_t &r2, uint32_t &r3,
                                      const __nv_bfloat16* p) {
    uint32_t addr = (uint32_t)__cvta_generic_to_shared(p);
    asm volatile("ldmatrix.sync.aligned.m8n8.x4.shared.b16 {%0,%1,%2,%3}, [%4];"
                 : "=r"(r0), "=r"(r1), "=r"(r2), "=r"(r3) : "r"(addr));
}

__device__ __forceinline__ void mma16816(float* c, const uint32_t* a, const uint32_t* b) {
    asm volatile("mma.sync.aligned.m16n8k16.row.col.f32.bf16.bf16.f32 "
                 "{%0,%1,%2,%3}, {%4,%5,%6,%7}, {%8,%9}, {%0,%1,%2,%3};"
                 : "+f"(c[0]), "+f"(c[1]), "+f"(c[2]), "+f"(c[3])
                 : "r"(a[0]), "r"(a[1]), "r"(a[2]), "r"(a[3]), "r"(b[0]), "r"(b[1]));
}

// ---------------- weight split: fp32 -> (hi,lo) bf16 ----------------
__global__ void split_kernel(const float* __restrict__ src,
                             __nv_bfloat16* __restrict__ hi,
                             __nv_bfloat16* __restrict__ lo, int n4) {
    int i = blockIdx.x * 256 + threadIdx.x;
    if (i >= n4) return;
    float4 v = ((const float4*)src)[i];
    __nv_bfloat16 h[4], l[4];
    bsplit(v.x, h[0], l[0]); bsplit(v.y, h[1], l[1]);
    bsplit(v.z, h[2], l[2]); bsplit(v.w, h[3], l[3]);
    ((ushort4*)hi)[i] = make_ushort4(__bfloat16_as_ushort(h[0]), __bfloat16_as_ushort(h[1]),
                                     __bfloat16_as_ushort(h[2]), __bfloat16_as_ushort(h[3]));
    ((ushort4*)lo)[i] = make_ushort4(__bfloat16_as_ushort(l[0]), __bfloat16_as_ushort(l[1]),
                                     __bfloat16_as_ushort(l[2]), __bfloat16_as_ushort(l[3]));
}

// ---------------- RMSNorm on input -> split bf16 ----------------
__global__ void rms_kernel(const float* __restrict__ x, const float* __restrict__ norm_w) {
    int r = blockIdx.x, tid = threadIdx.x;
    __shared__ float red[256];
    float v[4]; float sum = 0.f;
#pragma unroll
    for (int j = 0; j < 4; j++) {
        int i = tid + j * 256;
        v[j] = x[(size_t)r * DM + i];
        sum += v[j] * v[j];
    }
    red[tid] = sum; __syncthreads();
    for (int s = 128; s > 0; s >>= 1) { if (tid < s) red[tid] += red[tid + s]; __syncthreads(); }
    float rinv = rsqrtf(red[0] / DM + EPS);
#pragma unroll
    for (int j = 0; j < 4; j++) {
        int i = tid + j * 256;
        float xv = v[j] * rinv * norm_w[i];
        __nv_bfloat16 h, l; bsplit(xv, h, l);
        g_xnh[(size_t)r * DM + i] = h;
        g_xnl[(size_t)r * DM + i] = l;
    }
}

// ---------------- bf16-split tensor-core GEMM --------------------------------
// C[M,N] = (Ah+Al)[M,K] @ (Wh+Wl)[N,K]^T (+res), 3-term double-bf16.
// BM=BN=128, BK=32, 256 threads = 8 warps (4m x 2n), warp tile 32x64.
constexpr int ASTR = 40;  // smem half-stride (32 + 8 pad)

__global__ __launch_bounds__(256, 1) void mma_gemm_kernel(
    const __nv_bfloat16* __restrict__ Ah, const __nv_bfloat16* __restrict__ Al,
    const __nv_bfloat16* __restrict__ Wh, const __nv_bfloat16* __restrict__ Wl,
    float* __restrict__ C, int ldc,
    const float* __restrict__ res, int ldr,
    int M, int N, int K)
{
    __shared__ __nv_bfloat16 Ash[128 * ASTR];
    __shared__ __nv_bfloat16 Asl[128 * ASTR];
    __shared__ __nv_bfloat16 Wsh[128 * ASTR];
    __shared__ __nv_bfloat16 Wsl[128 * ASTR];

    int tid = threadIdx.x;
    int lane = tid & 31, warp = tid >> 5;
    int wm = warp >> 1, wn = warp & 1;
    int rowBase = blockIdx.y * 128;
    int colBase = blockIdx.x * 128;

    float acc[2][8][4];
#pragma unroll
    for (int mt = 0; mt < 2; mt++)
#pragma unroll
        for (int nt = 0; nt < 8; nt++)
#pragma unroll
            for (int q = 0; q < 4; q++) acc[mt][nt][q] = 0.f;

    // per-thread global->smem copy coordinates (2 chunks of 8 halfs per matrix)
    for (int k0 = 0; k0 < K; k0 += 32) {
#pragma unroll
        for (int i = 0; i < 2; i++) {
            int id = tid + i * 256;
            int row = id >> 2, seg = id & 3;
            // A
            size_t ga = (size_t)(rowBase + row) * K + k0 + seg * 8;
            *(uint4*)&Ash[row * ASTR + seg * 8] = *(const uint4*)&Ah[ga];
            *(uint4*)&Asl[row * ASTR + seg * 8] = *(const uint4*)&Al[ga];
            // W (guard N edge)
            int n = colBase + row;
            uint4 wh = make_uint4(0, 0, 0, 0), wl = make_uint4(0, 0, 0, 0);
            if (n < N) {
                size_t gw = (size_t)n * K + k0 + seg * 8;
                wh = *(const uint4*)&Wh[gw];
                wl = *(const uint4*)&Wl[gw];
            }
            *(uint4*)&Wsh[row * ASTR + seg * 8] = wh;
            *(uint4*)&Wsl[row * ASTR + seg * 8] = wl;
        }
        __syncthreads();

#pragma unroll
        for (int kk = 0; kk < 32; kk += 16) {
            uint32_t ah[2][4], al[2][4];
#pragma unroll
            for (int mt = 0; mt < 2; mt++) {
                int r = wm * 32 + mt * 16 + (lane & 15);
                int c = kk + (lane >> 4) * 8;
                ldsm4(ah[mt][0], ah[mt][1], ah[mt][2], ah[mt][3], &Ash[r * ASTR + c]);
                ldsm4(al[mt][0], al[mt][1], al[mt][2], al[mt][3], &Asl[r * ASTR + c]);
            }
            uint32_t bh[8][2], bl[8][2];
#pragma unroll
            for (int np = 0; np < 4; np++) {
                int n0 = wn * 64 + np * 16;
                int grp = lane >> 3;
                int r = n0 + (grp >> 1) * 8 + (lane & 7);
                int c = kk + (grp & 1) * 8;
                ldsm4(bh[np*2][0], bh[np*2][1], bh[np*2+1][0], bh[np*2+1][1], &Wsh[r * ASTR + c]);
                ldsm4(bl[np*2][0], bl[np*2][1], bl[np*2+1][0], bl[np*2+1][1], &Wsl[r * ASTR + c]);
            }
#pragma unroll
            for (int mt = 0; mt < 2; mt++)
#pragma unroll
                for (int nt = 0; nt < 8; nt++) {
                    mma16816(acc[mt][nt], ah[mt], bh[nt]);
                    mma16816(acc[mt][nt], ah[mt], bl[nt]);
                    mma16816(acc[mt][nt], al[mt], bh[nt]);
                }
        }
        __syncthreads();
    }

    // epilogue
#pragma unroll
    for (int mt = 0; mt < 2; mt++)
#pragma unroll
        for (int nt = 0; nt < 8; nt++) {
            int row = rowBase + wm * 32 + mt * 16 + (lane >> 2);
            int col = colBase + wn * 64 + nt * 8 + (lane & 3) * 2;
            if (col < N) {
                float2 v0 = make_float2(acc[mt][nt][0], acc[mt][nt][1]);
                float2 v1 = make_float2(acc[mt][nt][2], acc[mt][nt][3]);
                if (res) {
                    float2 e0 = *(const float2*)&res[(size_t)row * ldr + col];
                    float2 e1 = *(const float2*)&res[(size_t)(row + 8) * ldr + col];
                    v0.x += e0.x; v0.y += e0.y; v1.x += e1.x; v1.y += e1.y;
                }
                *(float2*)&C[(size_t)row * ldc + col] = v0;
                *(float2*)&C[(size_t)(row + 8) * ldc + col] = v1;
            }
        }
}

// ---------------- fp32 SGEMM (small G matmul only) ----------------
__global__ __launch_bounds__(256, 2) void sgemm2_kernel(
    const float* __restrict__ A, int lda, size_t batchA,
    const float* __restrict__ W, int ldw, size_t batchW,
    float* __restrict__ C, int ldc, size_t batchC,
    int M, int N, int K)
{
    __shared__ float As[16][132];
    __shared__ float Ws[16][132];
    int tid = threadIdx.x;
    int tx = tid & 15, ty = tid >> 4;
    const float* Ab = A + (size_t)blockIdx.z * batchA;
    const float* Wb = W + (size_t)blockIdx.z * batchW;
    float*       Cb = C + (size_t)blockIdx.z * batchC;
    int rowBase = blockIdx.y * 128;
    int colBase = blockIdx.x * 128;

    float acc[8][8];
#pragma unroll
    for (int i = 0; i < 8; i++)
#pragma unroll
        for (int j = 0; j < 8; j++) acc[i][j] = 0.f;

    for (int k0 = 0; k0 < K; k0 += 16) {
#pragma unroll
        for (int i = 0; i < 2; i++) {
            int t = tid + i * 256;
            int r = t >> 2, kq = t & 3;
            float4 v = *(const float4*)&Ab[(size_t)(rowBase + r) * lda + k0 + kq * 4];
            As[kq * 4 + 0][r] = v.x; As[kq * 4 + 1][r] = v.y;
            As[kq * 4 + 2][r] = v.z; As[kq * 4 + 3][r] = v.w;
        }
#pragma unroll
        for (int i = 0; i < 2; i++) {
            int t = tid + i * 256;
            int r = t >> 2, kq = t & 3;
            float4 v = *(const float4*)&Wb[(size_t)(colBase + r) * ldw + k0 + kq * 4];
            Ws[kq * 4 + 0][r] = v.x; Ws[kq * 4 + 1][r] = v.y;
            Ws[kq * 4 + 2][r] = v.z; Ws[kq * 4 + 3][r] = v.w;
        }
        __syncthreads();
#pragma unroll
        for (int kk = 0; kk < 16; kk++) {
            float a[8], b[8];
            *(float4*)&a[0] = *(const float4*)&As[kk][ty * 8];
            *(float4*)&a[4] = *(const float4*)&As[kk][ty * 8 + 4];
            *(float4*)&b[0] = *(const float4*)&Ws[kk][tx * 8];
            *(float4*)&b[4] = *(const float4*)&Ws[kk][tx * 8 + 4];
#pragma unroll
            for (int i = 0; i < 8; i++)
#pragma unroll
                for (int j = 0; j < 8; j++) acc[i][j] += a[i] * b[j];
        }
        __syncthreads();
    }
#pragma unroll
    for (int i = 0; i < 8; i++) {
        int r = rowBase + ty * 8 + i;
        *(float4*)&Cb[(size_t)r * ldc + colBase + tx * 8]     = *(float4*)&acc[i][0];
        *(float4*)&Cb[(size_t)r * ldc + colBase + tx * 8 + 4] = *(float4*)&acc[i][4];
    }
}

// ---------------- depthwise causal conv(4) + SiLU ----------------
__global__ void conv_kernel(const float* __restrict__ conv_w, const float* __restrict__ conv_b) {
    int r = blockIdx.x;
    int bi = r / L_, l = r % L_;
    for (int c = threadIdx.x; c < CONV; c += 256) {
        float s = conv_b[c];
#pragma unroll
        for (int k = 0; k < DC; k++) {
            int lt = l + k - (DC - 1);
            if (lt >= 0)
                s += g_zx[(size_t)(bi * L_ + lt) * DIN + DI + c] * conv_w[c * DC + k];
        }
        float sig = 1.f / (1.f + __expf(-s));
        g_xBC[(size_t)r * CONV + c] = s * sig;
    }
}

// ---------------- fused: dt=softplus(dt+bias), dA=dt*A, per-chunk cumsum ----
__global__ void acs_kernel(const float* __restrict__ dt_bias, const float* __restrict__ A_log) {
    int blk = blockIdx.x, tid = threadIdx.x;
    int bi = blk / (NC * NH);
    int rem = blk % (NC * NH);
    int c = rem / NH, h = rem % NH;
    __shared__ float s[CS];
    int t = bi * L_ + c * CS + tid;
    float v = g_zx[(size_t)t * DIN + (DIN - NH) + h] + dt_bias[h];
    float dtv = (v > 20.f) ? v : log1pf(__expf(v));
    g_dt[t * NH + h] = dtv;
    s[tid] = -__expf(A_log[h]) * dtv;
    __syncthreads();
    for (int off = 1; off < CS; off <<= 1) {
        float p = (tid >= off) ? s[tid - off] : 0.f;
        __syncthreads();
        s[tid] += p;
        __syncthreads();
    }
    g_Acs[blk * CS + tid] = s[tid];
}

// ---------------- Y_diag + D*xh : block per (b,chunk,head) ----------------
__global__ __launch_bounds__(256) void diag_kernel(const float* __restrict__ Dp) {
    int blk = blockIdx.x, tid = threadIdx.x;
    int bi = blk / (NC * NH);
    int rem = blk % (NC * NH);
    int c = rem / NH, h = rem % NH;
    __shared__ float Xs[128][64];
    __shared__ float Acss[CS];
    int rowBase = bi * L_ + c * CS;
    Acss[tid] = g_Acs[blk * CS + tid];
    __syncthreads();
    int l = tid;
    float acsl = Acss[l];
    const float* Grow = &g_G[((size_t)(bi * NC + c) * CS + l) * CS];
    float dH = Dp[h];

    for (int ph = 0; ph < 2; ph++) {
        float y[32];
#pragma unroll
        for (int p = 0; p < 32; p++) y[p] = 0.f;
        for (int s0 = 0; s0 < CS; s0 += 128) {
            __syncthreads();
#pragma unroll
            for (int i = 0; i < 32; i++) {
                int lin = tid + i * 256;
                int s = lin >> 6, p = lin & 63;
                int t = rowBase + s0 + s;
                Xs[s][p] = g_xBC[(size_t)t * CONV + h * HD + p] * g_dt[t * NH + h];
            }
            __syncthreads();
            int smax = l - s0; if (smax > 127) smax = 127;
            for (int s = 0; s <= smax; s++) {
                float coef = Grow[s0 + s] * __expf(acsl - Acss[s0 + s]);
#pragma unroll
                for (int p = 0; p < 32; p++) y[p] += coef * Xs[s][ph * 32 + p];
            }
        }
        int t = rowBase + l;
        size_t ob = (size_t)t * DI + h * HD + ph * 32;
#pragma unroll
        for (int p = 0; p < 32; p++) {
            float xh = g_xBC[(size_t)t * CONV + h * HD + ph * 32 + p];
            g_Y[ob + p] = y[p] + dH * xh;
        }
    }
}

// ---------------- per-chunk state: states[p,n] = sum_l B[l,n]*decay*X[l,p] ---
__global__ __launch_bounds__(256) void states_kernel() {
    int blk = blockIdx.x, tid = threadIdx.x;
    int bi = blk / (NC * NH);
    int rem = blk % (NC * NH);
    int c = rem / NH, h = rem % NH;
    __shared__ float Xs[32][64];
    __shared__ float Bs[32][128];
    int rowBase = bi * L_ + c * CS;
    float acsLast = g_Acs[blk * CS + (CS - 1)];
    int tn = tid & 31, tp = tid >> 5;
    float acc[8][4];
#pragma unroll
    for (int i = 0; i < 8; i++)
#pragma unroll
        for (int j = 0; j < 4; j++) acc[i][j] = 0.f;

    for (int l0 = 0; l0 < CS; l0 += 32) {
        __syncthreads();
#pragma unroll
        for (int i = 0; i < 8; i++) {
            int lin = tid + i * 256;
            int s = lin >> 6, p = lin & 63;
            int t = rowBase + l0 + s;
            float w = __expf(acsLast - g_Acs[blk * CS + l0 + s]);
            Xs[s][p] = g_xBC[(size_t)t * CONV + h * HD + p] * g_dt[t * NH + h] * w;
        }
#pragma unroll
        for (int i = 0; i < 16; i++) {
            int lin = tid + i * 256;
            int s = lin >> 7, n = lin & 127;
            Bs[s][n] = g_xBC[(size_t)(rowBase + l0 + s) * CONV + DI + n];
        }
        __syncthreads();
#pragma unroll 4
        for (int ll = 0; ll < 32; ll++) {
            float4 xa = *(const float4*)&Xs[ll][tp * 8];
            float4 xb = *(const float4*)&Xs[ll][tp * 8 + 4];
            float4 bv = *(const float4*)&Bs[ll][tn * 4];
            float xv[8] = {xa.x, xa.y, xa.z, xa.w, xb.x, xb.y, xb.z, xb.w};
            float bw[4] = {bv.x, bv.y, bv.z, bv.w};
#pragma unroll
            for (int i = 0; i < 8; i++)
#pragma unroll
                for (int j = 0; j < 4; j++) acc[i][j] += xv[i] * bw[j];
        }
    }
    size_t base = (size_t)blk * HD * DS;
#pragma unroll
    for (int i = 0; i < 8; i++) {
        int p = tp * 8 + i;
#pragma unroll
        for (int j = 0; j < 4; j++) {
            int n = tn * 4 + j;
            g_states[base + (size_t)p * DS + n] = acc[i][j];
        }
    }
}

// ---------------- inter-chunk scan ----------------
__global__ void cscan_kernel() {
    int bi = blockIdx.x / NH, h = blockIdx.x % NH;
    int tid = threadIdx.x;
    float P[32];
#pragma unroll
    for (int j = 0; j < 32; j++) P[j] = 0.f;
    for (int c = 0; c < NC; c++) {
        int cb = (bi * NC + c) * NH + h;
        size_t sb = (size_t)cb * HD * DS;
        float T = __expf(g_Acs[cb * CS + (CS - 1)]);
#pragma unroll
        for (int j = 0; j < 32; j++) {
            int e = tid + j * 256;
            g_Sprev[sb + e] = P[j];
            P[j] = P[j] * T + g_states[sb + e];
        }
    }
}

// ---------------- Y_off ----------------
__global__ __launch_bounds__(256) void yoff_kernel() {
    int blk = blockIdx.x, tid = threadIdx.x;
    int bi = blk / (NC * NH);
    int rem = blk % (NC * NH);
    int c = rem / NH, h = rem % NH;
    __shared__ float Ss[64][128];
    size_t sb = (size_t)blk * HD * DS;
#pragma unroll
    for (int i = 0; i < 32; i++) {
        int lin = tid + i * 256;
        Ss[lin >> 7][lin & 127] = g_Sprev[sb + lin];
    }
    int l = tid;
    int t = bi * L_ + c * CS + l;
    float scale = __expf(g_Acs[blk * CS + l]);
    const float* Crow = &g_xBC[(size_t)t * CONV + DI + DS];
    __syncthreads();

    for (int pg = 0; pg < 4; pg++) {
        float acc[16];
#pragma unroll
        for (int pi = 0; pi < 16; pi++) acc[pi] = 0.f;
        for (int n = 0; n < DS; n++) {
            float cv = Crow[n];
#pragma unroll
            for (int pi = 0; pi < 16; pi++) acc[pi] += cv * Ss[pg * 16 + pi][n];
        }
        size_t ob = (size_t)t * DI + h * HD + pg * 16;
#pragma unroll
        for (int pi = 0; pi < 16; pi++) g_Y[ob + pi] += scale * acc[pi];
    }
}

// ---------------- gate with silu(z), group-RMS, split to bf16 ---------------
__global__ void gate_kernel(const float* __restrict__ gnorm_w) {
    int r = blockIdx.x, tid = threadIdx.x;
    __shared__ float red[256];
    float g[8]; float sum = 0.f;
#pragma unroll
    for (int j = 0; j < 8; j++) {
        int i = tid + j * 256;
        float yv = g_Y[(size_t)r * DI + i];
        float z = g_zx[(size_t)r * DIN + i];
        float s = 1.f / (1.f + __expf(-z));
        float gv = yv * z * s;
        g[j] = gv; sum += gv * gv;
    }
    red[tid] = sum; __syncthreads();
    for (int s = 128; s > 0; s >>= 1) { if (tid < s) red[tid] += red[tid + s]; __syncthreads(); }
    float rinv = rsqrtf(red[0] / DI + EPS);
#pragma unroll
    for (int j = 0; j < 8; j++) {
        int i = tid + j * 256;
        float yn = g[j] * rinv * gnorm_w[i];
        __nv_bfloat16 h, l; bsplit(yn, h, l);
        g_ynh[(size_t)r * DI + i] = h;
        g_ynl[(size_t)r * DI + i] = l;
    }
}

// ---------------- launch ----------------
extern "C" void kernel_launch(void* const* d_in, const int* in_sizes, int n_in,
                              void* d_out, int out_size) {
    const float* x          = (const float*)d_in[0];
    const float* norm_w     = (const float*)d_in[1];
    const float* in_proj_w  = (const float*)d_in[2];
    const float* conv_w     = (const float*)d_in[3];
    const float* conv_b     = (const float*)d_in[4];
    const float* dt_bias    = (const float*)d_in[5];
    const float* A_log      = (const float*)d_in[6];
    const float* Dp         = (const float*)d_in[7];
    const float* gnorm_w    = (const float*)d_in[8];
    const float* out_proj_w = (const float*)d_in[9];
    float* out = (float*)d_out;

    float *zx, *xBC, *Gb;
    __nv_bfloat16 *xnh, *xnl, *wih, *wil, *ynh, *ynl, *woh, *wol;
    cudaGetSymbolAddress((void**)&zx,  g_zx);
    cudaGetSymbolAddress((void**)&xBC, g_xBC);
    cudaGetSymbolAddress((void**)&Gb,  g_G);
    cudaGetSymbolAddress((void**)&xnh, g_xnh);
    cudaGetSymbolAddress((void**)&xnl, g_xnl);
    cudaGetSymbolAddress((void**)&wih, g_wih);
    cudaGetSymbolAddress((void**)&wil, g_wil);
    cudaGetSymbolAddress((void**)&ynh, g_ynh);
    cudaGetSymbolAddress((void**)&ynl, g_ynl);
    cudaGetSymbolAddress((void**)&woh, g_woh);
    cudaGetSymbolAddress((void**)&wol, g_wol);

    rms_kernel<<<BL, 256>>>(x, norm_w);
    split_kernel<<<(DIN * DM / 4 + 255) / 256, 256>>>(in_proj_w, wih, wil, DIN * DM / 4);

    // zxbcdt = xn @ in_proj_w^T   (4096 x 4384 x 1024), bf16-split tensor core
    mma_gemm_kernel<<<dim3((DIN + 127) / 128, BL / 128), 256>>>(
        xnh, xnl, wih, wil, zx, DIN, nullptr, 0, BL, DIN, DM);

    conv_kernel<<<BL, 256>>>(conv_w, conv_b);
    acs_kernel<<<B_ * NC * NH, 256>>>(dt_bias, A_log);

    // G[b,c] = Cm @ Bm^T per chunk (256 x 256 x 128), batched
    sgemm2_kernel<<<dim3(CS / 128, CS / 128, B_ * NC), 256>>>(
        xBC + DI + DS, CONV, (size_t)CS * CONV,
        xBC + DI,      CONV, (size_t)CS * CONV,
        Gb, CS, (size_t)CS * CS,
        CS, CS, DS);

    diag_kernel<<<B_ * NC * NH, 256>>>(Dp);
    states_kernel<<<B_ * NC * NH, 256>>>();
    cscan_kernel<<<B_ * NH, 256>>>();
    yoff_kernel<<<B_ * NC * NH, 256>>>();
    gate_kernel<<<BL, 256>>>(gnorm_w);
    split_kernel<<<(DM * DI / 4 + 255) / 256, 256>>>(out_proj_w, woh, wol, DM * DI / 4);

    // out = x + yn @ out_proj_w^T   (4096 x 1024 x 2048)
    mma_gemm_kernel<<<dim3(DM / 128, BL / 128), 256>>>(
        ynh, ynl, woh, wol, out, DM, x, DM, BL, DM, DI);
}

// round 5
// speedup vs baseline: 1.7147x; 1.0526x over previous
#include <cuda_runtime.h>
#include <cuda_bf16.h>
#include <math.h>
#include <stdint.h>

// ---------------- problem constants ----------------
constexpr int B_  = 2;
constexpr int L_  = 2048;
constexpr int DM  = 1024;
constexpr int DS  = 128;
constexpr int DC  = 4;
constexpr int HD  = 64;
constexpr int DI  = 2048;      // EXP*DM
constexpr int NH  = 32;        // DI/HD
constexpr int CONV = DI + 2*DS;        // 2304
constexpr int DIN  = 2*DI + 2*DS + NH; // 4384
constexpr int CS  = 256;
constexpr int NC  = L_ / CS;   // 8
constexpr int BL  = B_ * L_;   // 4096
constexpr float EPS = 1e-5f;

// ---------------- scratch (static device globals; no cudaMalloc allowed) ----
__device__ float g_zx[(size_t)BL * DIN];
__device__ float g_xBC[(size_t)BL * CONV];
__device__ float g_dt[BL * NH];
__device__ float g_Acs[B_ * NC * NH * CS];
__device__ float g_G[(size_t)B_ * NC * CS * CS];
__device__ float g_states[(size_t)B_ * NC * NH * HD * DS];
__device__ float g_Sprev[(size_t)B_ * NC * NH * HD * DS];
__device__ float g_Y[(size_t)BL * DI];

// bf16 split buffers (hi/lo) for tensor-core GEMMs
__device__ __nv_bfloat16 g_xnh[(size_t)BL * DM];
__device__ __nv_bfloat16 g_xnl[(size_t)BL * DM];
__device__ __nv_bfloat16 g_wih[(size_t)DIN * DM];
__device__ __nv_bfloat16 g_wil[(size_t)DIN * DM];
__device__ __nv_bfloat16 g_ynh[(size_t)BL * DI];
__device__ __nv_bfloat16 g_ynl[(size_t)BL * DI];
__device__ __nv_bfloat16 g_woh[(size_t)DM * DI];
__device__ __nv_bfloat16 g_wol[(size_t)DM * DI];

// ---------------- helpers ----------------
__device__ __forceinline__ void bsplit(float v, __nv_bfloat16 &hi, __nv_bfloat16 &lo) {
    hi = __float2bfloat16_rn(v);
    lo = __float2bfloat16_rn(v - __bfloat162float(hi));
}

__device__ __forceinline__ void ldsm4(uint32_t &r0, uint32_t &r1, uint32_t &r2, uint32_t &r3,
                                      const __nv_bfloat16* p) {
    uint32_t addr = (uint32_t)__cvta_generic_to_shared(p);
    asm volatile("ldmatrix.sync.aligned.m8n8.x4.shared.b16 {%0,%1,%2,%3}, [%4];"
                 : "=r"(r0), "=r"(r1), "=r"(r2), "=r"(r3) : "r"(addr));
}

__device__ __forceinline__ void mma16816(float* c, const uint32_t* a, const uint32_t* b) {
    asm volatile("mma.sync.aligned.m16n8k16.row.col.f32.bf16.bf16.f32 "
                 "{%0,%1,%2,%3}, {%4,%5,%6,%7}, {%8,%9}, {%0,%1,%2,%3};"
                 : "+f"(c[0]), "+f"(c[1]), "+f"(c[2]), "+f"(c[3])
                 : "r"(a[0]), "r"(a[1]), "r"(a[2]), "r"(a[3]), "r"(b[0]), "r"(b[1]));
}

__device__ __forceinline__ void cpa16(uint32_t saddr, const void* g, int sz) {
    asm volatile("cp.async.cg.shared.global [%0], [%1], 16, %2;"
                 :: "r"(saddr), "l"(g), "r"(sz));
}
__device__ __forceinline__ void cpa_commit() {
    asm volatile("cp.async.commit_group;");
}
template <int N>
__device__ __forceinline__ void cpa_wait() {
    asm volatile("cp.async.wait_group %0;" :: "n"(N));
}

// ---------------- weight split: fp32 -> (hi,lo) bf16 ----------------
__global__ void split_kernel(const float* __restrict__ src,
                             __nv_bfloat16* __restrict__ hi,
                             __nv_bfloat16* __restrict__ lo, int n4) {
    int i = blockIdx.x * 256 + threadIdx.x;
    if (i >= n4) return;
    float4 v = ((const float4*)src)[i];
    __nv_bfloat16 h[4], l[4];
    bsplit(v.x, h[0], l[0]); bsplit(v.y, h[1], l[1]);
    bsplit(v.z, h[2], l[2]); bsplit(v.w, h[3], l[3]);
    ((ushort4*)hi)[i] = make_ushort4(__bfloat16_as_ushort(h[0]), __bfloat16_as_ushort(h[1]),
                                     __bfloat16_as_ushort(h[2]), __bfloat16_as_ushort(h[3]));
    ((ushort4*)lo)[i] = make_ushort4(__bfloat16_as_ushort(l[0]), __bfloat16_as_ushort(l[1]),
                                     __bfloat16_as_ushort(l[2]), __bfloat16_as_ushort(l[3]));
}

// ---------------- RMSNorm on input -> split bf16 ----------------
__global__ void rms_kernel(const float* __restrict__ x, const float* __restrict__ norm_w) {
    int r = blockIdx.x, tid = threadIdx.x;
    __shared__ float red[256];
    float v[4]; float sum = 0.f;
#pragma unroll
    for (int j = 0; j < 4; j++) {
        int i = tid + j * 256;
        v[j] = x[(size_t)r * DM + i];
        sum += v[j] * v[j];
    }
    red[tid] = sum; __syncthreads();
    for (int s = 128; s > 0; s >>= 1) { if (tid < s) red[tid] += red[tid + s]; __syncthreads(); }
    float rinv = rsqrtf(red[0] / DM + EPS);
#pragma unroll
    for (int j = 0; j < 4; j++) {
        int i = tid + j * 256;
        float xv = v[j] * rinv * norm_w[i];
        __nv_bfloat16 h, l; bsplit(xv, h, l);
        g_xnh[(size_t)r * DM + i] = h;
        g_xnl[(size_t)r * DM + i] = l;
    }
}

// ---------------- bf16-split tensor-core GEMM, 3-stage cp.async pipeline -----
// C[M,N] = (Ah+Al)[M,K] @ (Wh+Wl)[N,K]^T (+res), 3-term double-bf16.
// BM=BN=128, BK=32, 256 threads = 8 warps (4m x 2n), warp tile 32x64.
constexpr int ASTR = 40;             // smem half-stride (32 + 8 pad)
constexpr int STG_H = 128 * ASTR;    // halfs per array per stage (5120)
constexpr int NSTAGE = 3;
constexpr int GEMM_SMEM = NSTAGE * 4 * STG_H * 2;  // 122880 bytes

__global__ __launch_bounds__(256, 1) void mma_gemm_kernel(
    const __nv_bfloat16* __restrict__ Ah, const __nv_bfloat16* __restrict__ Al,
    const __nv_bfloat16* __restrict__ Wh, const __nv_bfloat16* __restrict__ Wl,
    float* __restrict__ C, int ldc,
    const float* __restrict__ res, int ldr,
    int M, int N, int K)
{
    extern __shared__ __nv_bfloat16 smem[];
    int tid = threadIdx.x;
    int lane = tid & 31, warp = tid >> 5;
    int wm = warp >> 1, wn = warp & 1;
    int rowBase = blockIdx.y * 128;
    int colBase = blockIdx.x * 128;

    uint32_t sbase = (uint32_t)__cvta_generic_to_shared(smem);

    // per-thread copy coords: 2 chunks, each 16B from each of 4 arrays
    int id0 = tid, id1 = tid + 256;
    int rowA0 = id0 >> 2, seg0 = id0 & 3;
    int rowA1 = id1 >> 2, seg1 = id1 & 3;
    int so0 = (rowA0 * ASTR + seg0 * 8) * 2;   // byte offset within array
    int so1 = (rowA1 * ASTR + seg1 * 8) * 2;
    int n0 = colBase + rowA0, n1 = colBase + rowA1;
    int wsz0 = (n0 < N) ? 16 : 0;
    int wsz1 = (n1 < N) ? 16 : 0;
    if (n0 >= N) n0 = 0;
    if (n1 >= N) n1 = 0;

    int nt = K / 32;
    auto issue = [&](int t) {
        int st = t % NSTAGE;
        int k0 = t * 32;
        uint32_t sb = sbase + st * 4 * STG_H * 2;
        size_t ga0 = (size_t)(rowBase + rowA0) * K + k0 + seg0 * 8;
        size_t ga1 = (size_t)(rowBase + rowA1) * K + k0 + seg1 * 8;
        size_t gw0 = (size_t)n0 * K + k0 + seg0 * 8;
        size_t gw1 = (size_t)n1 * K + k0 + seg1 * 8;
        cpa16(sb + so0,                 Ah + ga0, 16);
        cpa16(sb + so1,                 Ah + ga1, 16);
        cpa16(sb + STG_H*2 + so0,       Al + ga0, 16);
        cpa16(sb + STG_H*2 + so1,       Al + ga1, 16);
        cpa16(sb + 2*STG_H*2 + so0,     Wh + gw0, wsz0);
        cpa16(sb + 2*STG_H*2 + so1,     Wh + gw1, wsz1);
        cpa16(sb + 3*STG_H*2 + so0,     Wl + gw0, wsz0);
        cpa16(sb + 3*STG_H*2 + so1,     Wl + gw1, wsz1);
        cpa_commit();
    };

    float acc[2][8][4];
#pragma unroll
    for (int mt = 0; mt < 2; mt++)
#pragma unroll
        for (int ntt = 0; ntt < 8; ntt++)
#pragma unroll
            for (int q = 0; q < 4; q++) acc[mt][ntt][q] = 0.f;

    issue(0);
    if (nt > 1) issue(1);

    for (int t = 0; t < nt; t++) {
        if (t + 2 < nt) { issue(t + 2); cpa_wait<2>(); }
        else if (t + 1 < nt) cpa_wait<1>();
        else cpa_wait<0>();
        __syncthreads();

        int st = t % NSTAGE;
        __nv_bfloat16* Ash = smem + st * 4 * STG_H;
        __nv_bfloat16* Asl = Ash + STG_H;
        __nv_bfloat16* Wsh = Ash + 2 * STG_H;
        __nv_bfloat16* Wsl = Ash + 3 * STG_H;

#pragma unroll
        for (int kk = 0; kk < 32; kk += 16) {
            uint32_t ah[2][4], al[2][4];
#pragma unroll
            for (int mt = 0; mt < 2; mt++) {
                int r = wm * 32 + mt * 16 + (lane & 15);
                int c = kk + (lane >> 4) * 8;
                ldsm4(ah[mt][0], ah[mt][1], ah[mt][2], ah[mt][3], &Ash[r * ASTR + c]);
                ldsm4(al[mt][0], al[mt][1], al[mt][2], al[mt][3], &Asl[r * ASTR + c]);
            }
            uint32_t bh[8][2], bl[8][2];
#pragma unroll
            for (int np = 0; np < 4; np++) {
                int nb = wn * 64 + np * 16;
                int grp = lane >> 3;
                int r = nb + (grp >> 1) * 8 + (lane & 7);
                int c = kk + (grp & 1) * 8;
                ldsm4(bh[np*2][0], bh[np*2][1], bh[np*2+1][0], bh[np*2+1][1], &Wsh[r * ASTR + c]);
                ldsm4(bl[np*2][0], bl[np*2][1], bl[np*2+1][0], bl[np*2+1][1], &Wsl[r * ASTR + c]);
            }
#pragma unroll
            for (int mt = 0; mt < 2; mt++)
#pragma unroll
                for (int ntt = 0; ntt < 8; ntt++) {
                    mma16816(acc[mt][ntt], ah[mt], bh[ntt]);
                    mma16816(acc[mt][ntt], ah[mt], bl[ntt]);
                    mma16816(acc[mt][ntt], al[mt], bh[ntt]);
                }
        }
        __syncthreads();
    }

    // epilogue
#pragma unroll
    for (int mt = 0; mt < 2; mt++)
#pragma unroll
        for (int ntt = 0; ntt < 8; ntt++) {
            int row = rowBase + wm * 32 + mt * 16 + (lane >> 2);
            int col = colBase + wn * 64 + ntt * 8 + (lane & 3) * 2;
            if (col < N) {
                float2 v0 = make_float2(acc[mt][ntt][0], acc[mt][ntt][1]);
                float2 v1 = make_float2(acc[mt][ntt][2], acc[mt][ntt][3]);
                if (res) {
                    float2 e0 = *(const float2*)&res[(size_t)row * ldr + col];
                    float2 e1 = *(const float2*)&res[(size_t)(row + 8) * ldr + col];
                    v0.x += e0.x; v0.y += e0.y; v1.x += e1.x; v1.y += e1.y;
                }
                *(float2*)&C[(size_t)row * ldc + col] = v0;
                *(float2*)&C[(size_t)(row + 8) * ldc + col] = v1;
            }
        }
}

// ---------------- fp32 SGEMM (small G matmul only) ----------------
__global__ __launch_bounds__(256, 2) void sgemm2_kernel(
    const float* __restrict__ A, int lda, size_t batchA,
    const float* __restrict__ W, int ldw, size_t batchW,
    float* __restrict__ C, int ldc, size_t batchC,
    int M, int N, int K)
{
    __shared__ float As[16][132];
    __shared__ float Ws[16][132];
    int tid = threadIdx.x;
    int tx = tid & 15, ty = tid >> 4;
    const float* Ab = A + (size_t)blockIdx.z * batchA;
    const float* Wb = W + (size_t)blockIdx.z * batchW;
    float*       Cb = C + (size_t)blockIdx.z * batchC;
    int rowBase = blockIdx.y * 128;
    int colBase = blockIdx.x * 128;

    float acc[8][8];
#pragma unroll
    for (int i = 0; i < 8; i++)
#pragma unroll
        for (int j = 0; j < 8; j++) acc[i][j] = 0.f;

    for (int k0 = 0; k0 < K; k0 += 16) {
#pragma unroll
        for (int i = 0; i < 2; i++) {
            int t = tid + i * 256;
            int r = t >> 2, kq = t & 3;
            float4 v = *(const float4*)&Ab[(size_t)(rowBase + r) * lda + k0 + kq * 4];
            As[kq * 4 + 0][r] = v.x; As[kq * 4 + 1][r] = v.y;
            As[kq * 4 + 2][r] = v.z; As[kq * 4 + 3][r] = v.w;
        }
#pragma unroll
        for (int i = 0; i < 2; i++) {
            int t = tid + i * 256;
            int r = t >> 2, kq = t & 3;
            float4 v = *(const float4*)&Wb[(size_t)(colBase + r) * ldw + k0 + kq * 4];
            Ws[kq * 4 + 0][r] = v.x; Ws[kq * 4 + 1][r] = v.y;
            Ws[kq * 4 + 2][r] = v.z; Ws[kq * 4 + 3][r] = v.w;
        }
        __syncthreads();
#pragma unroll
        for (int kk = 0; kk < 16; kk++) {
            float a[8], b[8];
            *(float4*)&a[0] = *(const float4*)&As[kk][ty * 8];
            *(float4*)&a[4] = *(const float4*)&As[kk][ty * 8 + 4];
            *(float4*)&b[0] = *(const float4*)&Ws[kk][tx * 8];
            *(float4*)&b[4] = *(const float4*)&Ws[kk][tx * 8 + 4];
#pragma unroll
            for (int i = 0; i < 8; i++)
#pragma unroll
                for (int j = 0; j < 8; j++) acc[i][j] += a[i] * b[j];
        }
        __syncthreads();
    }
#pragma unroll
    for (int i = 0; i < 8; i++) {
        int r = rowBase + ty * 8 + i;
        *(float4*)&Cb[(size_t)r * ldc + colBase + tx * 8]     = *(float4*)&acc[i][0];
        *(float4*)&Cb[(size_t)r * ldc + colBase + tx * 8 + 4] = *(float4*)&acc[i][4];
    }
}

// ---------------- depthwise causal conv(4) + SiLU (vectorized) ---------------
__global__ void conv_kernel(const float* __restrict__ conv_w, const float* __restrict__ conv_b) {
    int r = blockIdx.x;
    int bi = r / L_, l = r % L_;
    for (int c4 = threadIdx.x; c4 < CONV / 4; c4 += 256) {
        float4 bsv = ((const float4*)conv_b)[c4];
        float acc[4] = {bsv.x, bsv.y, bsv.z, bsv.w};
        float4 w0 = ((const float4*)conv_w)[c4 * 4 + 0];
        float4 w1 = ((const float4*)conv_w)[c4 * 4 + 1];
        float4 w2 = ((const float4*)conv_w)[c4 * 4 + 2];
        float4 w3 = ((const float4*)conv_w)[c4 * 4 + 3];
#pragma unroll
        for (int k = 0; k < DC; k++) {
            int lt = l + k - (DC - 1);
            if (lt >= 0) {
                float4 v = *(const float4*)&g_zx[(size_t)(bi * L_ + lt) * DIN + DI + c4 * 4];
                float wk0 = (k==0)?w0.x:(k==1)?w0.y:(k==2)?w0.z:w0.w;
                float wk1 = (k==0)?w1.x:(k==1)?w1.y:(k==2)?w1.z:w1.w;
                float wk2 = (k==0)?w2.x:(k==1)?w2.y:(k==2)?w2.z:w2.w;
                float wk3 = (k==0)?w3.x:(k==1)?w3.y:(k==2)?w3.z:w3.w;
                acc[0] += v.x * wk0; acc[1] += v.y * wk1;
                acc[2] += v.z * wk2; acc[3] += v.w * wk3;
            }
        }
        float4 outv;
        outv.x = acc[0] / (1.f + __expf(-acc[0]));
        outv.y = acc[1] / (1.f + __expf(-acc[1]));
        outv.z = acc[2] / (1.f + __expf(-acc[2]));
        outv.w = acc[3] / (1.f + __expf(-acc[3]));
        *(float4*)&g_xBC[(size_t)r * CONV + c4 * 4] = outv;
    }
}

// ---------------- fused: dt=softplus(dt+bias), dA=dt*A, per-chunk cumsum ----
__global__ void acs_kernel(const float* __restrict__ dt_bias, const float* __restrict__ A_log) {
    int blk = blockIdx.x, tid = threadIdx.x;
    int bi = blk / (NC * NH);
    int rem = blk % (NC * NH);
    int c = rem / NH, h = rem % NH;
    __shared__ float s[CS];
    int t = bi * L_ + c * CS + tid;
    float v = g_zx[(size_t)t * DIN + (DIN - NH) + h] + dt_bias[h];
    float dtv = (v > 20.f) ? v : log1pf(__expf(v));
    g_dt[t * NH + h] = dtv;
    s[tid] = -__expf(A_log[h]) * dtv;
    __syncthreads();
    for (int off = 1; off < CS; off <<= 1) {
        float p = (tid >= off) ? s[tid - off] : 0.f;
        __syncthreads();
        s[tid] += p;
        __syncthreads();
    }
    g_Acs[blk * CS + tid] = s[tid];
}

// ---------------- Y_diag + D*xh : block per (b,chunk,head) ----------------
__global__ __launch_bounds__(256) void diag_kernel(const float* __restrict__ Dp) {
    int blk = blockIdx.x, tid = threadIdx.x;
    int bi = blk / (NC * NH);
    int rem = blk % (NC * NH);
    int c = rem / NH, h = rem % NH;
    __shared__ float Xs[128][64];
    __shared__ float Acss[CS];
    int rowBase = bi * L_ + c * CS;
    Acss[tid] = g_Acs[blk * CS + tid];
    __syncthreads();
    int l = tid;
    float acsl = Acss[l];
    const float* Grow = &g_G[((size_t)(bi * NC + c) * CS + l) * CS];
    float dH = Dp[h];

    for (int ph = 0; ph < 2; ph++) {
        float y[32];
#pragma unroll
        for (int p = 0; p < 32; p++) y[p] = 0.f;
        for (int s0 = 0; s0 < CS; s0 += 128) {
            __syncthreads();
#pragma unroll
            for (int i = 0; i < 32; i++) {
                int lin = tid + i * 256;
                int s = lin >> 6, p = lin & 63;
                int t = rowBase + s0 + s;
                Xs[s][p] = g_xBC[(size_t)t * CONV + h * HD + p] * g_dt[t * NH + h];
            }
            __syncthreads();
            int smax = l - s0; if (smax > 127) smax = 127;
            for (int s = 0; s <= smax; s++) {
                float coef = Grow[s0 + s] * __expf(acsl - Acss[s0 + s]);
#pragma unroll
                for (int p = 0; p < 32; p++) y[p] += coef * Xs[s][ph * 32 + p];
            }
        }
        int t = rowBase + l;
        size_t ob = (size_t)t * DI + h * HD + ph * 32;
#pragma unroll
        for (int p = 0; p < 32; p++) {
            float xh = g_xBC[(size_t)t * CONV + h * HD + ph * 32 + p];
            g_Y[ob + p] = y[p] + dH * xh;
        }
    }
}

// ---------------- per-chunk state: states[p,n] = sum_l B[l,n]*decay*X[l,p] ---
__global__ __launch_bounds__(256) void states_kernel() {
    int blk = blockIdx.x, tid = threadIdx.x;
    int bi = blk / (NC * NH);
    int rem = blk % (NC * NH);
    int c = rem / NH, h = rem % NH;
    __shared__ float Xs[32][64];
    __shared__ float Bs[32][128];
    int rowBase = bi * L_ + c * CS;
    float acsLast = g_Acs[blk * CS + (CS - 1)];
    int tn = tid & 31, tp = tid >> 5;
    float acc[8][4];
#pragma unroll
    for (int i = 0; i < 8; i++)
#pragma unroll
        for (int j = 0; j < 4; j++) acc[i][j] = 0.f;

    for (int l0 = 0; l0 < CS; l0 += 32) {
        __syncthreads();
#pragma unroll
        for (int i = 0; i < 8; i++) {
            int lin = tid + i * 256;
            int s = lin >> 6, p = lin & 63;
            int t = rowBase + l0 + s;
            float w = __expf(acsLast - g_Acs[blk * CS + l0 + s]);
            Xs[s][p] = g_xBC[(size_t)t * CONV + h * HD + p] * g_dt[t * NH + h] * w;
        }
#pragma unroll
        for (int i = 0; i < 16; i++) {
            int lin = tid + i * 256;
            int s = lin >> 7, n = lin & 127;
            Bs[s][n] = g_xBC[(size_t)(rowBase + l0 + s) * CONV + DI + n];
        }
        __syncthreads();
#pragma unroll 4
        for (int ll = 0; ll < 32; ll++) {
            float4 xa = *(const float4*)&Xs[ll][tp * 8];
            float4 xb = *(const float4*)&Xs[ll][tp * 8 + 4];
            float4 bv = *(const float4*)&Bs[ll][tn * 4];
            float xv[8] = {xa.x, xa.y, xa.z, xa.w, xb.x, xb.y, xb.z, xb.w};
            float bw[4] = {bv.x, bv.y, bv.z, bv.w};
#pragma unroll
            for (int i = 0; i < 8; i++)
#pragma unroll
                for (int j = 0; j < 4; j++) acc[i][j] += xv[i] * bw[j];
        }
    }
    size_t base = (size_t)blk * HD * DS;
#pragma unroll
    for (int i = 0; i < 8; i++) {
        int p = tp * 8 + i;
#pragma unroll
        for (int j = 0; j < 4; j++) {
            int n = tn * 4 + j;
            g_states[base + (size_t)p * DS + n] = acc[i][j];
        }
    }
}

// ---------------- inter-chunk scan ----------------
__global__ void cscan_kernel() {
    int bi = blockIdx.x / NH, h = blockIdx.x % NH;
    int tid = threadIdx.x;
    float P[32];
#pragma unroll
    for (int j = 0; j < 32; j++) P[j] = 0.f;
    for (int c = 0; c < NC; c++) {
        int cb = (bi * NC + c) * NH + h;
        size_t sb = (size_t)cb * HD * DS;
        float T = __expf(g_Acs[cb * CS + (CS - 1)]);
#pragma unroll
        for (int j = 0; j < 32; j++) {
            int e = tid + j * 256;
            g_Sprev[sb + e] = P[j];
            P[j] = P[j] * T + g_states[sb + e];
        }
    }
}

// ---------------- Y_off ----------------
__global__ __launch_bounds__(256) void yoff_kernel() {
    int blk = blockIdx.x, tid = threadIdx.x;
    int bi = blk / (NC * NH);
    int rem = blk % (NC * NH);
    int c = rem / NH, h = rem % NH;
    __shared__ float Ss[64][128];
    size_t sb = (size_t)blk * HD * DS;
#pragma unroll
    for (int i = 0; i < 32; i++) {
        int lin = tid + i * 256;
        Ss[lin >> 7][lin & 127] = g_Sprev[sb + lin];
    }
    int l = tid;
    int t = bi * L_ + c * CS + l;
    float scale = __expf(g_Acs[blk * CS + l]);
    const float* Crow = &g_xBC[(size_t)t * CONV + DI + DS];
    __syncthreads();

    for (int pg = 0; pg < 4; pg++) {
        float acc[16];
#pragma unroll
        for (int pi = 0; pi < 16; pi++) acc[pi] = 0.f;
        for (int n = 0; n < DS; n++) {
            float cv = Crow[n];
#pragma unroll
            for (int pi = 0; pi < 16; pi++) acc[pi] += cv * Ss[pg * 16 + pi][n];
        }
        size_t ob = (size_t)t * DI + h * HD + pg * 16;
#pragma unroll
        for (int pi = 0; pi < 16; pi++) g_Y[ob + pi] += scale * acc[pi];
    }
}

// ---------------- gate with silu(z), group-RMS, split to bf16 ---------------
__global__ void gate_kernel(const float* __restrict__ gnorm_w) {
    int r = blockIdx.x, tid = threadIdx.x;
    __shared__ float red[256];
    float g[8]; float sum = 0.f;
#pragma unroll
    for (int j = 0; j < 8; j++) {
        int i = tid + j * 256;
        float yv = g_Y[(size_t)r * DI + i];
        float z = g_zx[(size_t)r * DIN + i];
        float s = 1.f / (1.f + __expf(-z));
        float gv = yv * z * s;
        g[j] = gv; sum += gv * gv;
    }
    red[tid] = sum; __syncthreads();
    for (int s = 128; s > 0; s >>= 1) { if (tid < s) red[tid] += red[tid + s]; __syncthreads(); }
    float rinv = rsqrtf(red[0] / DI + EPS);
#pragma unroll
    for (int j = 0; j < 8; j++) {
        int i = tid + j * 256;
        float yn = g[j] * rinv * gnorm_w[i];
        __nv_bfloat16 h, l; bsplit(yn, h, l);
        g_ynh[(size_t)r * DI + i] = h;
        g_ynl[(size_t)r * DI + i] = l;
    }
}

// ---------------- launch ----------------
extern "C" void kernel_launch(void* const* d_in, const int* in_sizes, int n_in,
                              void* d_out, int out_size) {
    const float* x          = (const float*)d_in[0];
    const float* norm_w     = (const float*)d_in[1];
    const float* in_proj_w  = (const float*)d_in[2];
    const float* conv_w     = (const float*)d_in[3];
    const float* conv_b     = (const float*)d_in[4];
    const float* dt_bias    = (const float*)d_in[5];
    const float* A_log      = (const float*)d_in[6];
    const float* Dp         = (const float*)d_in[7];
    const float* gnorm_w    = (const float*)d_in[8];
    const float* out_proj_w = (const float*)d_in[9];
    float* out = (float*)d_out;

    float *zx, *xBC, *Gb;
    __nv_bfloat16 *xnh, *xnl, *wih, *wil, *ynh, *ynl, *woh, *wol;
    cudaGetSymbolAddress((void**)&zx,  g_zx);
    cudaGetSymbolAddress((void**)&xBC, g_xBC);
    cudaGetSymbolAddress((void**)&Gb,  g_G);
    cudaGetSymbolAddress((void**)&xnh, g_xnh);
    cudaGetSymbolAddress((void**)&xnl, g_xnl);
    cudaGetSymbolAddress((void**)&wih, g_wih);
    cudaGetSymbolAddress((void**)&wil, g_wil);
    cudaGetSymbolAddress((void**)&ynh, g_ynh);
    cudaGetSymbolAddress((void**)&ynl, g_ynl);
    cudaGetSymbolAddress((void**)&woh, g_woh);
    cudaGetSymbolAddress((void**)&wol, g_wol);

    cudaFuncSetAttribute(mma_gemm_kernel,
                         cudaFuncAttributeMaxDynamicSharedMemorySize, GEMM_SMEM);

    rms_kernel<<<BL, 256>>>(x, norm_w);
    split_kernel<<<(DIN * DM / 4 + 255) / 256, 256>>>(in_proj_w, wih, wil, DIN * DM / 4);

    // zxbcdt = xn @ in_proj_w^T   (4096 x 4384 x 1024), bf16-split tensor core
    mma_gemm_kernel<<<dim3((DIN + 127) / 128, BL / 128), 256, GEMM_SMEM>>>(
        xnh, xnl, wih, wil, zx, DIN, nullptr, 0, BL, DIN, DM);

    conv_kernel<<<BL, 256>>>(conv_w, conv_b);
    acs_kernel<<<B_ * NC * NH, 256>>>(dt_bias, A_log);

    // G[b,c] = Cm @ Bm^T per chunk (256 x 256 x 128), batched
    sgemm2_kernel<<<dim3(CS / 128, CS / 128, B_ * NC), 256>>>(
        xBC + DI + DS, CONV, (size_t)CS * CONV,
        xBC + DI,      CONV, (size_t)CS * CONV,
        Gb, CS, (size_t)CS * CS,
        CS, CS, DS);

    diag_kernel<<<B_ * NC * NH, 256>>>(Dp);
    states_kernel<<<B_ * NC * NH, 256>>>();
    cscan_kernel<<<B_ * NH, 256>>>();
    yoff_kernel<<<B_ * NC * NH, 256>>>();
    gate_kernel<<<BL, 256>>>(gnorm_w);
    split_kernel<<<(DM * DI / 4 + 255) / 256, 256>>>(out_proj_w, woh, wol, DM * DI / 4);

    // out = x + yn @ out_proj_w^T   (4096 x 1024 x 2048)
    mma_gemm_kernel<<<dim3(DM / 128, BL / 128), 256, GEMM_SMEM>>>(
        ynh, ynl, woh, wol, out, DM, x, DM, BL, DM, DI);
}

// round 7
// speedup vs baseline: 2.0825x; 1.2145x over previous
#include <cuda_runtime.h>
#include <cuda_fp16.h>
#include <cuda_bf16.h>
#include <math.h>
#include <stdint.h>

// ---------------- problem constants ----------------
constexpr int B_  = 2;
constexpr int L_  = 2048;
constexpr int DM  = 1024;
constexpr int DS  = 128;
constexpr int DC  = 4;
constexpr int HD  = 64;
constexpr int DI  = 2048;      // EXP*DM
constexpr int NH  = 32;        // DI/HD
constexpr int CONV = DI + 2*DS;        // 2304
constexpr int DIN  = 2*DI + 2*DS + NH; // 4384
constexpr int CS  = 256;
constexpr int NC  = L_ / CS;   // 8
constexpr int BL  = B_ * L_;   // 4096
constexpr float EPS = 1e-5f;

// ---------------- scratch (static device globals; no cudaMalloc allowed) ----
__device__ float g_zx[(size_t)BL * DIN];
__device__ float g_xBC[(size_t)BL * CONV];
__device__ float g_dt[BL * NH];
__device__ float g_Acs[B_ * NC * NH * CS];
__device__ float g_G[(size_t)B_ * NC * CS * CS];
__device__ float g_states[(size_t)B_ * NC * NH * HD * DS];
__device__ float g_Sprev[(size_t)B_ * NC * NH * HD * DS];
__device__ float g_Y[(size_t)BL * DI];

// fp16 split buffers: A operands get (hi,lo); W operands single fp16
__device__ __half g_xnh[(size_t)BL * DM];
__device__ __half g_xnl[(size_t)BL * DM];
__device__ __half g_wi[(size_t)DIN * DM];
__device__ __half g_ynh[(size_t)BL * DI];
__device__ __half g_ynl[(size_t)BL * DI];
__device__ __half g_wo[(size_t)DM * DI];

// ---------------- helpers ----------------
__device__ __forceinline__ void hsplit(float v, __half &hi, __half &lo) {
    hi = __float2half_rn(v);
    lo = __float2half_rn(v - __half2float(hi));
}

__device__ __forceinline__ void ldsm4(uint32_t &r0, uint32_t &r1, uint32_t &r2, uint32_t &r3,
                                      const __half* p) {
    uint32_t addr = (uint32_t)__cvta_generic_to_shared(p);
    asm volatile("ldmatrix.sync.aligned.m8n8.x4.shared.b16 {%0,%1,%2,%3}, [%4];"
                 : "=r"(r0), "=r"(r1), "=r"(r2), "=r"(r3) : "r"(addr));
}

__device__ __forceinline__ void mma16816(float* c, const uint32_t* a, const uint32_t* b) {
    asm volatile("mma.sync.aligned.m16n8k16.row.col.f32.f16.f16.f32 "
                 "{%0,%1,%2,%3}, {%4,%5,%6,%7}, {%8,%9}, {%0,%1,%2,%3};"
                 : "+f"(c[0]), "+f"(c[1]), "+f"(c[2]), "+f"(c[3])
                 : "r"(a[0]), "r"(a[1]), "r"(a[2]), "r"(a[3]), "r"(b[0]), "r"(b[1]));
}

__device__ __forceinline__ void cpa16(uint32_t saddr, const void* g, int sz) {
    asm volatile("cp.async.cg.shared.global [%0], [%1], 16, %2;"
                 :: "r"(saddr), "l"(g), "r"(sz));
}
__device__ __forceinline__ void cpa_commit() { asm volatile("cp.async.commit_group;"); }
template <int N>
__device__ __forceinline__ void cpa_wait() { asm volatile("cp.async.wait_group %0;" :: "n"(N)); }

// ---------------- weight convert: fp32 -> fp16 ----------------
__global__ void wconv_kernel(const float* __restrict__ src,
                             __half* __restrict__ dst, int n4) {
    int i = blockIdx.x * 256 + threadIdx.x;
    if (i >= n4) return;
    float4 v = ((const float4*)src)[i];
    __half2 a = make_half2(__float2half_rn(v.x), __float2half_rn(v.y));
    __half2 b = make_half2(__float2half_rn(v.z), __float2half_rn(v.w));
    ((__half2*)dst)[i * 2]     = a;
    ((__half2*)dst)[i * 2 + 1] = b;
}

// ---------------- RMSNorm on input -> split fp16 ----------------
__global__ void rms_kernel(const float* __restrict__ x, const float* __restrict__ norm_w) {
    int r = blockIdx.x, tid = threadIdx.x;
    __shared__ float red[256];
    float v[4]; float sum = 0.f;
#pragma unroll
    for (int j = 0; j < 4; j++) {
        int i = tid + j * 256;
        v[j] = x[(size_t)r * DM + i];
        sum += v[j] * v[j];
    }
    red[tid] = sum; __syncthreads();
    for (int s = 128; s > 0; s >>= 1) { if (tid < s) red[tid] += red[tid + s]; __syncthreads(); }
    float rinv = rsqrtf(red[0] / DM + EPS);
#pragma unroll
    for (int j = 0; j < 4; j++) {
        int i = tid + j * 256;
        float xv = v[j] * rinv * norm_w[i];
        __half h, l; hsplit(xv, h, l);
        g_xnh[(size_t)r * DM + i] = h;
        g_xnl[(size_t)r * DM + i] = l;
    }
}

// ---------------- fp16 2-term split tensor-core GEMM ------------------------
// C[M,N] = (Ah+Al)[M,K] @ Wh[N,K]^T (+res).
// BM=BN=128, BK=32, 256 threads = 8 warps (4m x 2n), warp tile 32x64.
// 3-stage cp.async pipeline, 2 CTAs/SM.
constexpr int ASTR = 40;             // smem half-stride (32 + 8 pad)
constexpr int ARR_H = 128 * ASTR;    // halfs per array (5120)
constexpr int NSTAGE = 3;
constexpr int STG_B = 3 * ARR_H * 2;               // bytes per stage (30720)
constexpr int GEMM_SMEM = NSTAGE * STG_B;          // 92160

__global__ __launch_bounds__(256, 2) void mma_gemm_kernel(
    const __half* __restrict__ Ah, const __half* __restrict__ Al,
    const __half* __restrict__ Wh,
    float* __restrict__ C, int ldc,
    const float* __restrict__ res, int ldr,
    int M, int N, int K)
{
    extern __shared__ __half smem[];
    int tid = threadIdx.x;
    int lane = tid & 31, warp = tid >> 5;
    int wm = warp >> 1, wn = warp & 1;
    int rowBase = blockIdx.y * 128;
    int colBase = blockIdx.x * 128;

    uint32_t sbase = (uint32_t)__cvta_generic_to_shared(smem);

    // per-thread copy coords: 2 chunks of 16B per array
    int id0 = tid, id1 = tid + 256;
    int rowA0 = id0 >> 2, seg0 = id0 & 3;
    int rowA1 = id1 >> 2, seg1 = id1 & 3;
    int so0 = (rowA0 * ASTR + seg0 * 8) * 2;
    int so1 = (rowA1 * ASTR + seg1 * 8) * 2;
    int n0 = colBase + rowA0, n1 = colBase + rowA1;
    int wsz0 = (n0 < N) ? 16 : 0;
    int wsz1 = (n1 < N) ? 16 : 0;
    if (n0 >= N) n0 = 0;
    if (n1 >= N) n1 = 0;

    int nt = K / 32;
    auto issue = [&](int t) {
        int st = t % NSTAGE;
        int k0 = t * 32;
        uint32_t sb = sbase + st * STG_B;
        size_t ga0 = (size_t)(rowBase + rowA0) * K + k0 + seg0 * 8;
        size_t ga1 = (size_t)(rowBase + rowA1) * K + k0 + seg1 * 8;
        size_t gw0 = (size_t)n0 * K + k0 + seg0 * 8;
        size_t gw1 = (size_t)n1 * K + k0 + seg1 * 8;
        cpa16(sb + so0,               Ah + ga0, 16);
        cpa16(sb + so1,               Ah + ga1, 16);
        cpa16(sb + ARR_H*2 + so0,     Al + ga0, 16);
        cpa16(sb + ARR_H*2 + so1,     Al + ga1, 16);
        cpa16(sb + 2*ARR_H*2 + so0,   Wh + gw0, wsz0);
        cpa16(sb + 2*ARR_H*2 + so1,   Wh + gw1, wsz1);
        cpa_commit();
    };

    float acc[2][8][4];
#pragma unroll
    for (int mt = 0; mt < 2; mt++)
#pragma unroll
        for (int ntt = 0; ntt < 8; ntt++)
#pragma unroll
            for (int q = 0; q < 4; q++) acc[mt][ntt][q] = 0.f;

    issue(0);
    if (nt > 1) issue(1);

    for (int t = 0; t < nt; t++) {
        if (t + 2 < nt) { issue(t + 2); cpa_wait<2>(); }
        else if (t + 1 < nt) cpa_wait<1>();
        else cpa_wait<0>();
        __syncthreads();

        int st = t % NSTAGE;
        __half* Ash = smem + st * 3 * ARR_H;
        __half* Asl = Ash + ARR_H;
        __half* Wsh = Ash + 2 * ARR_H;

#pragma unroll
        for (int kk = 0; kk < 32; kk += 16) {
            uint32_t ah[2][4], al[2][4];
#pragma unroll
            for (int mt = 0; mt < 2; mt++) {
                int r = wm * 32 + mt * 16 + (lane & 15);
                int c = kk + (lane >> 4) * 8;
                ldsm4(ah[mt][0], ah[mt][1], ah[mt][2], ah[mt][3], &Ash[r * ASTR + c]);
                ldsm4(al[mt][0], al[mt][1], al[mt][2], al[mt][3], &Asl[r * ASTR + c]);
            }
            uint32_t bh[8][2];
#pragma unroll
            for (int np = 0; np < 4; np++) {
                int nb = wn * 64 + np * 16;
                int grp = lane >> 3;
                int r = nb + (grp >> 1) * 8 + (lane & 7);
                int c = kk + (grp & 1) * 8;
                ldsm4(bh[np*2][0], bh[np*2][1], bh[np*2+1][0], bh[np*2+1][1], &Wsh[r * ASTR + c]);
            }
#pragma unroll
            for (int mt = 0; mt < 2; mt++)
#pragma unroll
                for (int ntt = 0; ntt < 8; ntt++) {
                    mma16816(acc[mt][ntt], ah[mt], bh[ntt]);
                    mma16816(acc[mt][ntt], al[mt], bh[ntt]);
                }
        }
        __syncthreads();
    }

    // epilogue
#pragma unroll
    for (int mt = 0; mt < 2; mt++)
#pragma unroll
        for (int ntt = 0; ntt < 8; ntt++) {
            int row = rowBase + wm * 32 + mt * 16 + (lane >> 2);
            int col = colBase + wn * 64 + ntt * 8 + (lane & 3) * 2;
            if (col < N) {
                float2 v0 = make_float2(acc[mt][ntt][0], acc[mt][ntt][1]);
                float2 v1 = make_float2(acc[mt][ntt][2], acc[mt][ntt][3]);
                if (res) {
                    float2 e0 = *(const float2*)&res[(size_t)row * ldr + col];
                    float2 e1 = *(const float2*)&res[(size_t)(row + 8) * ldr + col];
                    v0.x += e0.x; v0.y += e0.y; v1.x += e1.x; v1.y += e1.y;
                }
                *(float2*)&C[(size_t)row * ldc + col] = v0;
                *(float2*)&C[(size_t)(row + 8) * ldc + col] = v1;
            }
        }
}

// ---------------- fp32 SGEMM (small G matmul only) ----------------
__global__ __launch_bounds__(256, 2) void sgemm2_kernel(
    const float* __restrict__ A, int lda, size_t batchA,
    const float* __restrict__ W, int ldw, size_t batchW,
    float* __restrict__ C, int ldc, size_t batchC,
    int M, int N, int K)
{
    __shared__ float As[16][132];
    __shared__ float Ws[16][132];
    int tid = threadIdx.x;
    int tx = tid & 15, ty = tid >> 4;
    const float* Ab = A + (size_t)blockIdx.z * batchA;
    const float* Wb = W + (size_t)blockIdx.z * batchW;
    float*       Cb = C + (size_t)blockIdx.z * batchC;
    int rowBase = blockIdx.y * 128;
    int colBase = blockIdx.x * 128;

    float acc[8][8];
#pragma unroll
    for (int i = 0; i < 8; i++)
#pragma unroll
        for (int j = 0; j < 8; j++) acc[i][j] = 0.f;

    for (int k0 = 0; k0 < K; k0 += 16) {
#pragma unroll
        for (int i = 0; i < 2; i++) {
            int t = tid + i * 256;
            int r = t >> 2, kq = t & 3;
            float4 v = *(const float4*)&Ab[(size_t)(rowBase + r) * lda + k0 + kq * 4];
            As[kq * 4 + 0][r] = v.x; As[kq * 4 + 1][r] = v.y;
            As[kq * 4 + 2][r] = v.z; As[kq * 4 + 3][r] = v.w;
        }
#pragma unroll
        for (int i = 0; i < 2; i++) {
            int t = tid + i * 256;
            int r = t >> 2, kq = t & 3;
            float4 v = *(const float4*)&Wb[(size_t)(colBase + r) * ldw + k0 + kq * 4];
            Ws[kq * 4 + 0][r] = v.x; Ws[kq * 4 + 1][r] = v.y;
            Ws[kq * 4 + 2][r] = v.z; Ws[kq * 4 + 3][r] = v.w;
        }
        __syncthreads();
#pragma unroll
        for (int kk = 0; kk < 16; kk++) {
            float a[8], b[8];
            *(float4*)&a[0] = *(const float4*)&As[kk][ty * 8];
            *(float4*)&a[4] = *(const float4*)&As[kk][ty * 8 + 4];
            *(float4*)&b[0] = *(const float4*)&Ws[kk][tx * 8];
            *(float4*)&b[4] = *(const float4*)&Ws[kk][tx * 8 + 4];
#pragma unroll
            for (int i = 0; i < 8; i++)
#pragma unroll
                for (int j = 0; j < 8; j++) acc[i][j] += a[i] * b[j];
        }
        __syncthreads();
    }
#pragma unroll
    for (int i = 0; i < 8; i++) {
        int r = rowBase + ty * 8 + i;
        *(float4*)&Cb[(size_t)r * ldc + colBase + tx * 8]     = *(float4*)&acc[i][0];
        *(float4*)&Cb[(size_t)r * ldc + colBase + tx * 8 + 4] = *(float4*)&acc[i][4];
    }
}

// ---------------- depthwise causal conv(4) + SiLU ----------------
__global__ void conv_kernel(const float* __restrict__ conv_w, const float* __restrict__ conv_b) {
    int r = blockIdx.x;
    int bi = r / L_, l = r % L_;
    for (int c = threadIdx.x; c < CONV; c += 256) {
        float s = conv_b[c];
#pragma unroll
        for (int k = 0; k < DC; k++) {
            int lt = l + k - (DC - 1);
            if (lt >= 0)
                s += g_zx[(size_t)(bi * L_ + lt) * DIN + DI + c] * conv_w[c * DC + k];
        }
        float sig = 1.f / (1.f + __expf(-s));
        g_xBC[(size_t)r * CONV + c] = s * sig;
    }
}

// ---------------- fused: dt=softplus(dt+bias), dA=dt*A, per-chunk cumsum ----
__global__ void acs_kernel(const float* __restrict__ dt_bias, const float* __restrict__ A_log) {
    int blk = blockIdx.x, tid = threadIdx.x;
    int bi = blk / (NC * NH);
    int rem = blk % (NC * NH);
    int c = rem / NH, h = rem % NH;
    __shared__ float s[CS];
    int t = bi * L_ + c * CS + tid;
    float v = g_zx[(size_t)t * DIN + (DIN - NH) + h] + dt_bias[h];
    float dtv = (v > 20.f) ? v : log1pf(__expf(v));
    g_dt[t * NH + h] = dtv;
    s[tid] = -__expf(A_log[h]) * dtv;
    __syncthreads();
    for (int off = 1; off < CS; off <<= 1) {
        float p = (tid >= off) ? s[tid - off] : 0.f;
        __syncthreads();
        s[tid] += p;
        __syncthreads();
    }
    g_Acs[blk * CS + tid] = s[tid];
}

// ---------------- Y_diag + D*xh : block per (b,chunk,head) ----------------
__global__ __launch_bounds__(256) void diag_kernel(const float* __restrict__ Dp) {
    int blk = blockIdx.x, tid = threadIdx.x;
    int bi = blk / (NC * NH);
    int rem = blk % (NC * NH);
    int c = rem / NH, h = rem % NH;
    __shared__ float Xs[128][64];
    __shared__ float Acss[CS];
    int rowBase = bi * L_ + c * CS;
    Acss[tid] = g_Acs[blk * CS + tid];
    __syncthreads();
    int l = tid;
    float acsl = Acss[l];
    const float* Grow = &g_G[((size_t)(bi * NC + c) * CS + l) * CS];
    float dH = Dp[h];

    for (int ph = 0; ph < 2; ph++) {
        float y[32];
#pragma unroll
        for (int p = 0; p < 32; p++) y[p] = 0.f;
        for (int s0 = 0; s0 < CS; s0 += 128) {
            __syncthreads();
#pragma unroll
            for (int i = 0; i < 32; i++) {
                int lin = tid + i * 256;
                int s = lin >> 6, p = lin & 63;
                int t = rowBase + s0 + s;
                Xs[s][p] = g_xBC[(size_t)t * CONV + h * HD + p] * g_dt[t * NH + h];
            }
            __syncthreads();
            int smax = l - s0; if (smax > 127) smax = 127;
            for (int s = 0; s <= smax; s++) {
                float coef = Grow[s0 + s] * __expf(acsl - Acss[s0 + s]);
#pragma unroll
                for (int p = 0; p < 32; p++) y[p] += coef * Xs[s][ph * 32 + p];
            }
        }
        int t = rowBase + l;
        size_t ob = (size_t)t * DI + h * HD + ph * 32;
#pragma unroll
        for (int p = 0; p < 32; p++) {
            float xh = g_xBC[(size_t)t * CONV + h * HD + ph * 32 + p];
            g_Y[ob + p] = y[p] + dH * xh;
        }
    }
}

// ---------------- per-chunk state: states[p,n] = sum_l B[l,n]*decay*X[l,p] ---
__global__ __launch_bounds__(256) void states_kernel() {
    int blk = blockIdx.x, tid = threadIdx.x;
    int bi = blk / (NC * NH);
    int rem = blk % (NC * NH);
    int c = rem / NH, h = rem % NH;
    __shared__ float Xs[32][64];
    __shared__ float Bs[32][128];
    int rowBase = bi * L_ + c * CS;
    float acsLast = g_Acs[blk * CS + (CS - 1)];
    int tn = tid & 31, tp = tid >> 5;
    float acc[8][4];
#pragma unroll
    for (int i = 0; i < 8; i++)
#pragma unroll
        for (int j = 0; j < 4; j++) acc[i][j] = 0.f;

    for (int l0 = 0; l0 < CS; l0 += 32) {
        __syncthreads();
#pragma unroll
        for (int i = 0; i < 8; i++) {
            int lin = tid + i * 256;
            int s = lin >> 6, p = lin & 63;
            int t = rowBase + l0 + s;
            float w = __expf(acsLast - g_Acs[blk * CS + l0 + s]);
            Xs[s][p] = g_xBC[(size_t)t * CONV + h * HD + p] * g_dt[t * NH + h] * w;
        }
#pragma unroll
        for (int i = 0; i < 16; i++) {
            int lin = tid + i * 256;
            int s = lin >> 7, n = lin & 127;
            Bs[s][n] = g_xBC[(size_t)(rowBase + l0 + s) * CONV + DI + n];
        }
        __syncthreads();
#pragma unroll 4
        for (int ll = 0; ll < 32; ll++) {
            float4 xa = *(const float4*)&Xs[ll][tp * 8];
            float4 xb = *(const float4*)&Xs[ll][tp * 8 + 4];
            float4 bv = *(const float4*)&Bs[ll][tn * 4];
            float xv[8] = {xa.x, xa.y, xa.z, xa.w, xb.x, xb.y, xb.z, xb.w};
            float bw[4] = {bv.x, bv.y, bv.z, bv.w};
#pragma unroll
            for (int i = 0; i < 8; i++)
#pragma unroll
                for (int j = 0; j < 4; j++) acc[i][j] += xv[i] * bw[j];
        }
    }
    size_t base = (size_t)blk * HD * DS;
#pragma unroll
    for (int i = 0; i < 8; i++) {
        int p = tp * 8 + i;
#pragma unroll
        for (int j = 0; j < 4; j++) {
            int n = tn * 4 + j;
            g_states[base + (size_t)p * DS + n] = acc[i][j];
        }
    }
}

// ---------------- inter-chunk scan ----------------
__global__ void cscan_kernel() {
    int bi = blockIdx.x / NH, h = blockIdx.x % NH;
    int tid = threadIdx.x;
    float P[32];
#pragma unroll
    for (int j = 0; j < 32; j++) P[j] = 0.f;
    for (int c = 0; c < NC; c++) {
        int cb = (bi * NC + c) * NH + h;
        size_t sb = (size_t)cb * HD * DS;
        float T = __expf(g_Acs[cb * CS + (CS - 1)]);
#pragma unroll
        for (int j = 0; j < 32; j++) {
            int e = tid + j * 256;
            g_Sprev[sb + e] = P[j];
            P[j] = P[j] * T + g_states[sb + e];
        }
    }
}

// ---------------- Y_off ----------------
__global__ __launch_bounds__(256) void yoff_kernel() {
    int blk = blockIdx.x, tid = threadIdx.x;
    int bi = blk / (NC * NH);
    int rem = blk % (NC * NH);
    int c = rem / NH, h = rem % NH;
    __shared__ float Ss[64][128];
    size_t sb = (size_t)blk * HD * DS;
#pragma unroll
    for (int i = 0; i < 32; i++) {
        int lin = tid + i * 256;
        Ss[lin >> 7][lin & 127] = g_Sprev[sb + lin];
    }
    int l = tid;
    int t = bi * L_ + c * CS + l;
    float scale = __expf(g_Acs[blk * CS + l]);
    const float* Crow = &g_xBC[(size_t)t * CONV + DI + DS];
    __syncthreads();

    for (int pg = 0; pg < 4; pg++) {
        float acc[16];
#pragma unroll
        for (int pi = 0; pi < 16; pi++) acc[pi] = 0.f;
        for (int n = 0; n < DS; n++) {
            float cv = Crow[n];
#pragma unroll
            for (int pi = 0; pi < 16; pi++) acc[pi] += cv * Ss[pg * 16 + pi][n];
        }
        size_t ob = (size_t)t * DI + h * HD + pg * 16;
#pragma unroll
        for (int pi = 0; pi < 16; pi++) g_Y[ob + pi] += scale * acc[pi];
    }
}

// ---------------- gate with silu(z), group-RMS, split to fp16 ---------------
__global__ void gate_kernel(const float* __restrict__ gnorm_w) {
    int r = blockIdx.x, tid = threadIdx.x;
    __shared__ float red[256];
    float g[8]; float sum = 0.f;
#pragma unroll
    for (int j = 0; j < 8; j++) {
        int i = tid + j * 256;
        float yv = g_Y[(size_t)r * DI + i];
        float z = g_zx[(size_t)r * DIN + i];
        float s = 1.f / (1.f + __expf(-z));
        float gv = yv * z * s;
        g[j] = gv; sum += gv * gv;
    }
    red[tid] = sum; __syncthreads();
    for (int s = 128; s > 0; s >>= 1) { if (tid < s) red[tid] += red[tid + s]; __syncthreads(); }
    float rinv = rsqrtf(red[0] / DI + EPS);
#pragma unroll
    for (int j = 0; j < 8; j++) {
        int i = tid + j * 256;
        float yn = g[j] * rinv * gnorm_w[i];
        __half h, l; hsplit(yn, h, l);
        g_ynh[(size_t)r * DI + i] = h;
        g_ynl[(size_t)r * DI + i] = l;
    }
}

// ---------------- launch ----------------
extern "C" void kernel_launch(void* const* d_in, const int* in_sizes, int n_in,
                              void* d_out, int out_size) {
    const float* x          = (const float*)d_in[0];
    const float* norm_w     = (const float*)d_in[1];
    const float* in_proj_w  = (const float*)d_in[2];
    const float* conv_w     = (const float*)d_in[3];
    const float* conv_b     = (const float*)d_in[4];
    const float* dt_bias    = (const float*)d_in[5];
    const float* A_log      = (const float*)d_in[6];
    const float* Dp         = (const float*)d_in[7];
    const float* gnorm_w    = (const float*)d_in[8];
    const float* out_proj_w = (const float*)d_in[9];
    float* out = (float*)d_out;

    float *zx, *xBC, *Gb;
    __half *xnh, *xnl, *wi, *ynh, *ynl, *wo;
    cudaGetSymbolAddress((void**)&zx,  g_zx);
    cudaGetSymbolAddress((void**)&xBC, g_xBC);
    cudaGetSymbolAddress((void**)&Gb,  g_G);
    cudaGetSymbolAddress((void**)&xnh, g_xnh);
    cudaGetSymbolAddress((void**)&xnl, g_xnl);
    cudaGetSymbolAddress((void**)&wi,  g_wi);
    cudaGetSymbolAddress((void**)&ynh, g_ynh);
    cudaGetSymbolAddress((void**)&ynl, g_ynl);
    cudaGetSymbolAddress((void**)&wo,  g_wo);

    cudaFuncSetAttribute(mma_gemm_kernel,
                         cudaFuncAttributeMaxDynamicSharedMemorySize, GEMM_SMEM);

    rms_kernel<<<BL, 256>>>(x, norm_w);
    wconv_kernel<<<(DIN * DM / 4 + 255) / 256, 256>>>(in_proj_w, wi, DIN * DM / 4);

    // zxbcdt = xn @ in_proj_w^T   (4096 x 4384 x 1024)
    mma_gemm_kernel<<<dim3((DIN + 127) / 128, BL / 128), 256, GEMM_SMEM>>>(
        xnh, xnl, wi, zx, DIN, nullptr, 0, BL, DIN, DM);

    conv_kernel<<<BL, 256>>>(conv_w, conv_b);
    acs_kernel<<<B_ * NC * NH, 256>>>(dt_bias, A_log);

    // G[b,c] = Cm @ Bm^T per chunk (256 x 256 x 128), batched
    sgemm2_kernel<<<dim3(CS / 128, CS / 128, B_ * NC), 256>>>(
        xBC + DI + DS, CONV, (size_t)CS * CONV,
        xBC + DI,      CONV, (size_t)CS * CONV,
        Gb, CS, (size_t)CS * CS,
        CS, CS, DS);

    diag_kernel<<<B_ * NC * NH, 256>>>(Dp);
    states_kernel<<<B_ * NC * NH, 256>>>();
    cscan_kernel<<<B_ * NH, 256>>>();
    yoff_kernel<<<B_ * NC * NH, 256>>>();
    gate_kernel<<<BL, 256>>>(gnorm_w);
    wconv_kernel<<<(DM * DI / 4 + 255) / 256, 256>>>(out_proj_w, wo, DM * DI / 4);

    // out = x + yn @ out_proj_w^T   (4096 x 1024 x 2048)
    mma_gemm_kernel<<<dim3(DM / 128, BL / 128), 256, GEMM_SMEM>>>(
        ynh, ynl, wo, out, DM, x, DM, BL, DM, DI);
}

// round 8
// speedup vs baseline: 2.1079x; 1.0122x over previous
#include <cuda_runtime.h>
#include <cuda_fp16.h>
#include <math.h>
#include <stdint.h>

// ---------------- problem constants ----------------
constexpr int B_  = 2;
constexpr int L_  = 2048;
constexpr int DM  = 1024;
constexpr int DS  = 128;
constexpr int DC  = 4;
constexpr int HD  = 64;
constexpr int DI  = 2048;      // EXP*DM
constexpr int NH  = 32;        // DI/HD
constexpr int CONV = DI + 2*DS;        // 2304
constexpr int DIN  = 2*DI + 2*DS + NH; // 4384
constexpr int CS  = 256;
constexpr int NC  = L_ / CS;   // 8
constexpr int BL  = B_ * L_;   // 4096
constexpr float EPS = 1e-5f;

// ---------------- scratch (static device globals; no cudaMalloc allowed) ----
__device__ float g_zx[(size_t)BL * DIN];
__device__ float g_xBC[(size_t)BL * CONV];
__device__ float g_dt[BL * NH];
__device__ float g_Acs[B_ * NC * NH * CS];
__device__ float g_G[(size_t)B_ * NC * CS * CS];
__device__ float g_states[(size_t)B_ * NC * NH * HD * DS];
__device__ float g_Sprev[(size_t)B_ * NC * NH * HD * DS];
__device__ float g_Y[(size_t)BL * DI];

// fp16 split buffers: A operands get (hi,lo); W operands single fp16
__device__ __half g_xnh[(size_t)BL * DM];
__device__ __half g_xnl[(size_t)BL * DM];
__device__ __half g_wi[(size_t)DIN * DM];
__device__ __half g_ynh[(size_t)BL * DI];
__device__ __half g_ynl[(size_t)BL * DI];
__device__ __half g_wo[(size_t)DM * DI];

// ---------------- helpers ----------------
__device__ __forceinline__ void hsplit(float v, __half &hi, __half &lo) {
    hi = __float2half_rn(v);
    lo = __float2half_rn(v - __half2float(hi));
}

__device__ __forceinline__ void ldsm4(uint32_t &r0, uint32_t &r1, uint32_t &r2, uint32_t &r3,
                                      const __half* p) {
    uint32_t addr = (uint32_t)__cvta_generic_to_shared(p);
    asm volatile("ldmatrix.sync.aligned.m8n8.x4.shared.b16 {%0,%1,%2,%3}, [%4];"
                 : "=r"(r0), "=r"(r1), "=r"(r2), "=r"(r3) : "r"(addr));
}

__device__ __forceinline__ void mma16816(float* c, const uint32_t* a, const uint32_t* b) {
    asm volatile("mma.sync.aligned.m16n8k16.row.col.f32.f16.f16.f32 "
                 "{%0,%1,%2,%3}, {%4,%5,%6,%7}, {%8,%9}, {%0,%1,%2,%3};"
                 : "+f"(c[0]), "+f"(c[1]), "+f"(c[2]), "+f"(c[3])
                 : "r"(a[0]), "r"(a[1]), "r"(a[2]), "r"(a[3]), "r"(b[0]), "r"(b[1]));
}

__device__ __forceinline__ void cpa16(uint32_t saddr, const void* g, int sz) {
    asm volatile("cp.async.cg.shared.global [%0], [%1], 16, %2;"
                 :: "r"(saddr), "l"(g), "r"(sz));
}
__device__ __forceinline__ void cpa_commit() { asm volatile("cp.async.commit_group;"); }
template <int N>
__device__ __forceinline__ void cpa_wait() { asm volatile("cp.async.wait_group %0;" :: "n"(N)); }

// ---------------- weight convert: fp32 -> fp16 ----------------
__global__ void wconv_kernel(const float* __restrict__ src,
                             __half* __restrict__ dst, int n4) {
    int i = blockIdx.x * 256 + threadIdx.x;
    if (i >= n4) return;
    float4 v = ((const float4*)src)[i];
    __half2 a = make_half2(__float2half_rn(v.x), __float2half_rn(v.y));
    __half2 b = make_half2(__float2half_rn(v.z), __float2half_rn(v.w));
    ((__half2*)dst)[i * 2]     = a;
    ((__half2*)dst)[i * 2 + 1] = b;
}

// ---------------- RMSNorm on input -> split fp16 ----------------
__global__ void rms_kernel(const float* __restrict__ x, const float* __restrict__ norm_w) {
    int r = blockIdx.x, tid = threadIdx.x;
    __shared__ float red[256];
    float v[4]; float sum = 0.f;
#pragma unroll
    for (int j = 0; j < 4; j++) {
        int i = tid + j * 256;
        v[j] = x[(size_t)r * DM + i];
        sum += v[j] * v[j];
    }
    red[tid] = sum; __syncthreads();
    for (int s = 128; s > 0; s >>= 1) { if (tid < s) red[tid] += red[tid + s]; __syncthreads(); }
    float rinv = rsqrtf(red[0] / DM + EPS);
#pragma unroll
    for (int j = 0; j < 4; j++) {
        int i = tid + j * 256;
        float xv = v[j] * rinv * norm_w[i];
        __half h, l; hsplit(xv, h, l);
        g_xnh[(size_t)r * DM + i] = h;
        g_xnl[(size_t)r * DM + i] = l;
    }
}

// ---------------- fp16 2-term split tensor-core GEMM ------------------------
// C[M,N] = (Ah+Al)[M,K] @ Wh[N,K]^T (+res).
// BM=BN=128, BK=64, 256 threads = 8 warps (4m x 2n), warp tile 32x64.
// 2-stage cp.async pipeline, 2 CTAs/SM.
constexpr int ASTR = 72;             // smem half-stride (64 + 8 pad)
constexpr int ARR_H = 128 * ASTR;    // halfs per array (9216)
constexpr int STG_B = 3 * ARR_H * 2;               // bytes per stage (55296)
constexpr int GEMM_SMEM = 2 * STG_B;               // 110592

__global__ __launch_bounds__(256, 2) void mma_gemm_kernel(
    const __half* __restrict__ Ah, const __half* __restrict__ Al,
    const __half* __restrict__ Wh,
    float* __restrict__ C, int ldc,
    const float* __restrict__ res, int ldr,
    int M, int N, int K)
{
    extern __shared__ __half smem[];
    int tid = threadIdx.x;
    int lane = tid & 31, warp = tid >> 5;
    int wm = warp >> 1, wn = warp & 1;
    int rowBase = blockIdx.y * 128;
    int colBase = blockIdx.x * 128;

    uint32_t sbase = (uint32_t)__cvta_generic_to_shared(smem);

    // per-thread copy coords: 4 chunks of 16B per array (8 chunks per 64-half row)
    int rowA[4], seg[4], so[4], nW[4], wsz[4];
#pragma unroll
    for (int i = 0; i < 4; i++) {
        int id = tid + i * 256;
        rowA[i] = id >> 3; seg[i] = id & 7;
        so[i] = (rowA[i] * ASTR + seg[i] * 8) * 2;
        int n = colBase + rowA[i];
        wsz[i] = (n < N) ? 16 : 0;
        nW[i] = (n < N) ? n : 0;
    }

    int nt = K / 64;
    auto issue = [&](int t) {
        int st = t & 1;
        int k0 = t * 64;
        uint32_t sb = sbase + st * STG_B;
#pragma unroll
        for (int i = 0; i < 4; i++) {
            size_t ga = (size_t)(rowBase + rowA[i]) * K + k0 + seg[i] * 8;
            size_t gw = (size_t)nW[i] * K + k0 + seg[i] * 8;
            cpa16(sb + so[i],               Ah + ga, 16);
            cpa16(sb + ARR_H*2 + so[i],     Al + ga, 16);
            cpa16(sb + 2*ARR_H*2 + so[i],   Wh + gw, wsz[i]);
        }
        cpa_commit();
    };

    float acc[2][8][4];
#pragma unroll
    for (int mt = 0; mt < 2; mt++)
#pragma unroll
        for (int ntt = 0; ntt < 8; ntt++)
#pragma unroll
            for (int q = 0; q < 4; q++) acc[mt][ntt][q] = 0.f;

    issue(0);
    if (nt > 1) issue(1);

    for (int t = 0; t < nt; t++) {
        if (t + 1 < nt) cpa_wait<1>(); else cpa_wait<0>();
        __syncthreads();

        int st = t & 1;
        __half* Ash = smem + st * 3 * ARR_H;
        __half* Asl = Ash + ARR_H;
        __half* Wsh = Ash + 2 * ARR_H;

#pragma unroll
        for (int kk = 0; kk < 64; kk += 16) {
            uint32_t ah[2][4], al[2][4];
#pragma unroll
            for (int mt = 0; mt < 2; mt++) {
                int r = wm * 32 + mt * 16 + (lane & 15);
                int c = kk + (lane >> 4) * 8;
                ldsm4(ah[mt][0], ah[mt][1], ah[mt][2], ah[mt][3], &Ash[r * ASTR + c]);
                ldsm4(al[mt][0], al[mt][1], al[mt][2], al[mt][3], &Asl[r * ASTR + c]);
            }
            uint32_t bh[8][2];
#pragma unroll
            for (int np = 0; np < 4; np++) {
                int nb = wn * 64 + np * 16;
                int grp = lane >> 3;
                int r = nb + (grp >> 1) * 8 + (lane & 7);
                int c = kk + (grp & 1) * 8;
                ldsm4(bh[np*2][0], bh[np*2][1], bh[np*2+1][0], bh[np*2+1][1], &Wsh[r * ASTR + c]);
            }
#pragma unroll
            for (int mt = 0; mt < 2; mt++)
#pragma unroll
                for (int ntt = 0; ntt < 8; ntt++) {
                    mma16816(acc[mt][ntt], ah[mt], bh[ntt]);
                    mma16816(acc[mt][ntt], al[mt], bh[ntt]);
                }
        }
        __syncthreads();
        if (t + 2 < nt) issue(t + 2);
    }

    // epilogue
#pragma unroll
    for (int mt = 0; mt < 2; mt++)
#pragma unroll
        for (int ntt = 0; ntt < 8; ntt++) {
            int row = rowBase + wm * 32 + mt * 16 + (lane >> 2);
            int col = colBase + wn * 64 + ntt * 8 + (lane & 3) * 2;
            if (col < N) {
                float2 v0 = make_float2(acc[mt][ntt][0], acc[mt][ntt][1]);
                float2 v1 = make_float2(acc[mt][ntt][2], acc[mt][ntt][3]);
                if (res) {
                    float2 e0 = *(const float2*)&res[(size_t)row * ldr + col];
                    float2 e1 = *(const float2*)&res[(size_t)(row + 8) * ldr + col];
                    v0.x += e0.x; v0.y += e0.y; v1.x += e1.x; v1.y += e1.y;
                }
                *(float2*)&C[(size_t)row * ldc + col] = v0;
                *(float2*)&C[(size_t)(row + 8) * ldc + col] = v1;
            }
        }
}

// ---------------- fp32 SGEMM (small G matmul only) ----------------
__global__ __launch_bounds__(256, 2) void sgemm2_kernel(
    const float* __restrict__ A, int lda, size_t batchA,
    const float* __restrict__ W, int ldw, size_t batchW,
    float* __restrict__ C, int ldc, size_t batchC,
    int M, int N, int K)
{
    __shared__ float As[16][132];
    __shared__ float Ws[16][132];
    int tid = threadIdx.x;
    int tx = tid & 15, ty = tid >> 4;
    const float* Ab = A + (size_t)blockIdx.z * batchA;
    const float* Wb = W + (size_t)blockIdx.z * batchW;
    float*       Cb = C + (size_t)blockIdx.z * batchC;
    int rowBase = blockIdx.y * 128;
    int colBase = blockIdx.x * 128;

    float acc[8][8];
#pragma unroll
    for (int i = 0; i < 8; i++)
#pragma unroll
        for (int j = 0; j < 8; j++) acc[i][j] = 0.f;

    for (int k0 = 0; k0 < K; k0 += 16) {
#pragma unroll
        for (int i = 0; i < 2; i++) {
            int t = tid + i * 256;
            int r = t >> 2, kq = t & 3;
            float4 v = *(const float4*)&Ab[(size_t)(rowBase + r) * lda + k0 + kq * 4];
            As[kq * 4 + 0][r] = v.x; As[kq * 4 + 1][r] = v.y;
            As[kq * 4 + 2][r] = v.z; As[kq * 4 + 3][r] = v.w;
        }
#pragma unroll
        for (int i = 0; i < 2; i++) {
            int t = tid + i * 256;
            int r = t >> 2, kq = t & 3;
            float4 v = *(const float4*)&Wb[(size_t)(colBase + r) * ldw + k0 + kq * 4];
            Ws[kq * 4 + 0][r] = v.x; Ws[kq * 4 + 1][r] = v.y;
            Ws[kq * 4 + 2][r] = v.z; Ws[kq * 4 + 3][r] = v.w;
        }
        __syncthreads();
#pragma unroll
        for (int kk = 0; kk < 16; kk++) {
            float a[8], b[8];
            *(float4*)&a[0] = *(const float4*)&As[kk][ty * 8];
            *(float4*)&a[4] = *(const float4*)&As[kk][ty * 8 + 4];
            *(float4*)&b[0] = *(const float4*)&Ws[kk][tx * 8];
            *(float4*)&b[4] = *(const float4*)&Ws[kk][tx * 8 + 4];
#pragma unroll
            for (int i = 0; i < 8; i++)
#pragma unroll
                for (int j = 0; j < 8; j++) acc[i][j] += a[i] * b[j];
        }
        __syncthreads();
    }
#pragma unroll
    for (int i = 0; i < 8; i++) {
        int r = rowBase + ty * 8 + i;
        *(float4*)&Cb[(size_t)r * ldc + colBase + tx * 8]     = *(float4*)&acc[i][0];
        *(float4*)&Cb[(size_t)r * ldc + colBase + tx * 8 + 4] = *(float4*)&acc[i][4];
    }
}

// ---------------- depthwise causal conv(4) + SiLU ----------------
__global__ void conv_kernel(const float* __restrict__ conv_w, const float* __restrict__ conv_b) {
    int r = blockIdx.x;
    int bi = r / L_, l = r % L_;
    for (int c = threadIdx.x; c < CONV; c += 256) {
        float s = conv_b[c];
#pragma unroll
        for (int k = 0; k < DC; k++) {
            int lt = l + k - (DC - 1);
            if (lt >= 0)
                s += g_zx[(size_t)(bi * L_ + lt) * DIN + DI + c] * conv_w[c * DC + k];
        }
        float sig = 1.f / (1.f + __expf(-s));
        g_xBC[(size_t)r * CONV + c] = s * sig;
    }
}

// ---------------- fused: dt=softplus(dt+bias), dA=dt*A, per-chunk cumsum ----
__global__ void acs_kernel(const float* __restrict__ dt_bias, const float* __restrict__ A_log) {
    int blk = blockIdx.x, tid = threadIdx.x;
    int bi = blk / (NC * NH);
    int rem = blk % (NC * NH);
    int c = rem / NH, h = rem % NH;
    __shared__ float s[CS];
    int t = bi * L_ + c * CS + tid;
    float v = g_zx[(size_t)t * DIN + (DIN - NH) + h] + dt_bias[h];
    float dtv = (v > 20.f) ? v : log1pf(__expf(v));
    g_dt[t * NH + h] = dtv;
    s[tid] = -__expf(A_log[h]) * dtv;
    __syncthreads();
    for (int off = 1; off < CS; off <<= 1) {
        float p = (tid >= off) ? s[tid - off] : 0.f;
        __syncthreads();
        s[tid] += p;
        __syncthreads();
    }
    g_Acs[blk * CS + tid] = s[tid];
}

// ---------------- Y_diag + D*xh : block per (b,chunk,head) ----------------
__global__ __launch_bounds__(256) void diag_kernel(const float* __restrict__ Dp) {
    int blk = blockIdx.x, tid = threadIdx.x;
    int bi = blk / (NC * NH);
    int rem = blk % (NC * NH);
    int c = rem / NH, h = rem % NH;
    __shared__ float Xs[128][64];
    __shared__ float Acss[CS];
    int rowBase = bi * L_ + c * CS;
    Acss[tid] = g_Acs[blk * CS + tid];
    __syncthreads();
    int l = tid;
    float acsl = Acss[l];
    const float* Grow = &g_G[((size_t)(bi * NC + c) * CS + l) * CS];
    float dH = Dp[h];

    for (int ph = 0; ph < 2; ph++) {
        float y[32];
#pragma unroll
        for (int p = 0; p < 32; p++) y[p] = 0.f;
        for (int s0 = 0; s0 < CS; s0 += 128) {
            __syncthreads();
#pragma unroll
            for (int i = 0; i < 32; i++) {
                int lin = tid + i * 256;
                int s = lin >> 6, p = lin & 63;
                int t = rowBase + s0 + s;
                Xs[s][p] = g_xBC[(size_t)t * CONV + h * HD + p] * g_dt[t * NH + h];
            }
            __syncthreads();
            int smax = l - s0; if (smax > 127) smax = 127;
            for (int s = 0; s <= smax; s++) {
                float coef = Grow[s0 + s] * __expf(acsl - Acss[s0 + s]);
#pragma unroll
                for (int p = 0; p < 32; p++) y[p] += coef * Xs[s][ph * 32 + p];
            }
        }
        int t = rowBase + l;
        size_t ob = (size_t)t * DI + h * HD + ph * 32;
#pragma unroll
        for (int p = 0; p < 32; p++) {
            float xh = g_xBC[(size_t)t * CONV + h * HD + ph * 32 + p];
            g_Y[ob + p] = y[p] + dH * xh;
        }
    }
}

// ---------------- per-chunk state: states[p,n] = sum_l B[l,n]*decay*X[l,p] ---
__global__ __launch_bounds__(256) void states_kernel() {
    int blk = blockIdx.x, tid = threadIdx.x;
    int bi = blk / (NC * NH);
    int rem = blk % (NC * NH);
    int c = rem / NH, h = rem % NH;
    __shared__ float Xs[32][64];
    __shared__ float Bs[32][128];
    int rowBase = bi * L_ + c * CS;
    float acsLast = g_Acs[blk * CS + (CS - 1)];
    int tn = tid & 31, tp = tid >> 5;
    float acc[8][4];
#pragma unroll
    for (int i = 0; i < 8; i++)
#pragma unroll
        for (int j = 0; j < 4; j++) acc[i][j] = 0.f;

    for (int l0 = 0; l0 < CS; l0 += 32) {
        __syncthreads();
#pragma unroll
        for (int i = 0; i < 8; i++) {
            int lin = tid + i * 256;
            int s = lin >> 6, p = lin & 63;
            int t = rowBase + l0 + s;
            float w = __expf(acsLast - g_Acs[blk * CS + l0 + s]);
            Xs[s][p] = g_xBC[(size_t)t * CONV + h * HD + p] * g_dt[t * NH + h] * w;
        }
#pragma unroll
        for (int i = 0; i < 16; i++) {
            int lin = tid + i * 256;
            int s = lin >> 7, n = lin & 127;
            Bs[s][n] = g_xBC[(size_t)(rowBase + l0 + s) * CONV + DI + n];
        }
        __syncthreads();
#pragma unroll 4
        for (int ll = 0; ll < 32; ll++) {
            float4 xa = *(const float4*)&Xs[ll][tp * 8];
            float4 xb = *(const float4*)&Xs[ll][tp * 8 + 4];
            float4 bv = *(const float4*)&Bs[ll][tn * 4];
            float xv[8] = {xa.x, xa.y, xa.z, xa.w, xb.x, xb.y, xb.z, xb.w};
            float bw[4] = {bv.x, bv.y, bv.z, bv.w};
#pragma unroll
            for (int i = 0; i < 8; i++)
#pragma unroll
                for (int j = 0; j < 4; j++) acc[i][j] += xv[i] * bw[j];
        }
    }
    size_t base = (size_t)blk * HD * DS;
#pragma unroll
    for (int i = 0; i < 8; i++) {
        int p = tp * 8 + i;
#pragma unroll
        for (int j = 0; j < 4; j++) {
            int n = tn * 4 + j;
            g_states[base + (size_t)p * DS + n] = acc[i][j];
        }
    }
}

// ---------------- inter-chunk scan ----------------
__global__ void cscan_kernel() {
    int bi = blockIdx.x / NH, h = blockIdx.x % NH;
    int tid = threadIdx.x;
    float P[32];
#pragma unroll
    for (int j = 0; j < 32; j++) P[j] = 0.f;
    for (int c = 0; c < NC; c++) {
        int cb = (bi * NC + c) * NH + h;
        size_t sb = (size_t)cb * HD * DS;
        float T = __expf(g_Acs[cb * CS + (CS - 1)]);
#pragma unroll
        for (int j = 0; j < 32; j++) {
            int e = tid + j * 256;
            g_Sprev[sb + e] = P[j];
            P[j] = P[j] * T + g_states[sb + e];
        }
    }
}

// ---------------- Y_off ----------------
__global__ __launch_bounds__(256) void yoff_kernel() {
    int blk = blockIdx.x, tid = threadIdx.x;
    int bi = blk / (NC * NH);
    int rem = blk % (NC * NH);
    int c = rem / NH, h = rem % NH;
    __shared__ float Ss[64][128];
    size_t sb = (size_t)blk * HD * DS;
#pragma unroll
    for (int i = 0; i < 32; i++) {
        int lin = tid + i * 256;
        Ss[lin >> 7][lin & 127] = g_Sprev[sb + lin];
    }
    int l = tid;
    int t = bi * L_ + c * CS + l;
    float scale = __expf(g_Acs[blk * CS + l]);
    const float* Crow = &g_xBC[(size_t)t * CONV + DI + DS];
    __syncthreads();

    for (int pg = 0; pg < 4; pg++) {
        float acc[16];
#pragma unroll
        for (int pi = 0; pi < 16; pi++) acc[pi] = 0.f;
        for (int n = 0; n < DS; n++) {
            float cv = Crow[n];
#pragma unroll
            for (int pi = 0; pi < 16; pi++) acc[pi] += cv * Ss[pg * 16 + pi][n];
        }
        size_t ob = (size_t)t * DI + h * HD + pg * 16;
#pragma unroll
        for (int pi = 0; pi < 16; pi++) g_Y[ob + pi] += scale * acc[pi];
    }
}

// ---------------- gate with silu(z), group-RMS, split to fp16 ---------------
__global__ void gate_kernel(const float* __restrict__ gnorm_w) {
    int r = blockIdx.x, tid = threadIdx.x;
    __shared__ float red[256];
    float g[8]; float sum = 0.f;
#pragma unroll
    for (int j = 0; j < 8; j++) {
        int i = tid + j * 256;
        float yv = g_Y[(size_t)r * DI + i];
        float z = g_zx[(size_t)r * DIN + i];
        float s = 1.f / (1.f + __expf(-z));
        float gv = yv * z * s;
        g[j] = gv; sum += gv * gv;
    }
    red[tid] = sum; __syncthreads();
    for (int s = 128; s > 0; s >>= 1) { if (tid < s) red[tid] += red[tid + s]; __syncthreads(); }
    float rinv = rsqrtf(red[0] / DI + EPS);
#pragma unroll
    for (int j = 0; j < 8; j++) {
        int i = tid + j * 256;
        float yn = g[j] * rinv * gnorm_w[i];
        __half h, l; hsplit(yn, h, l);
        g_ynh[(size_t)r * DI + i] = h;
        g_ynl[(size_t)r * DI + i] = l;
    }
}

// ---------------- launch ----------------
extern "C" void kernel_launch(void* const* d_in, const int* in_sizes, int n_in,
                              void* d_out, int out_size) {
    const float* x          = (const float*)d_in[0];
    const float* norm_w     = (const float*)d_in[1];
    const float* in_proj_w  = (const float*)d_in[2];
    const float* conv_w     = (const float*)d_in[3];
    const float* conv_b     = (const float*)d_in[4];
    const float* dt_bias    = (const float*)d_in[5];
    const float* A_log      = (const float*)d_in[6];
    const float* Dp         = (const float*)d_in[7];
    const float* gnorm_w    = (const float*)d_in[8];
    const float* out_proj_w = (const float*)d_in[9];
    float* out = (float*)d_out;

    float *zx, *xBC, *Gb;
    __half *xnh, *xnl, *wi, *ynh, *ynl, *wo;
    cudaGetSymbolAddress((void**)&zx,  g_zx);
    cudaGetSymbolAddress((void**)&xBC, g_xBC);
    cudaGetSymbolAddress((void**)&Gb,  g_G);
    cudaGetSymbolAddress((void**)&xnh, g_xnh);
    cudaGetSymbolAddress((void**)&xnl, g_xnl);
    cudaGetSymbolAddress((void**)&wi,  g_wi);
    cudaGetSymbolAddress((void**)&ynh, g_ynh);
    cudaGetSymbolAddress((void**)&ynl, g_ynl);
    cudaGetSymbolAddress((void**)&wo,  g_wo);

    cudaFuncSetAttribute(mma_gemm_kernel,
                         cudaFuncAttributeMaxDynamicSharedMemorySize, GEMM_SMEM);

    // launches 1-3 (so the ncu capture window lands on the in_proj GEMM, #4)
    rms_kernel<<<BL, 256>>>(x, norm_w);
    wconv_kernel<<<(DIN * DM / 4 + 255) / 256, 256>>>(in_proj_w, wi, DIN * DM / 4);
    wconv_kernel<<<(DM * DI / 4 + 255) / 256, 256>>>(out_proj_w, wo, DM * DI / 4);

    // #4: zxbcdt = xn @ in_proj_w^T   (4096 x 4384 x 1024)
    mma_gemm_kernel<<<dim3((DIN + 127) / 128, BL / 128), 256, GEMM_SMEM>>>(
        xnh, xnl, wi, zx, DIN, nullptr, 0, BL, DIN, DM);

    conv_kernel<<<BL, 256>>>(conv_w, conv_b);
    acs_kernel<<<B_ * NC * NH, 256>>>(dt_bias, A_log);

    // G[b,c] = Cm @ Bm^T per chunk (256 x 256 x 128), batched
    sgemm2_kernel<<<dim3(CS / 128, CS / 128, B_ * NC), 256>>>(
        xBC + DI + DS, CONV, (size_t)CS * CONV,
        xBC + DI,      CONV, (size_t)CS * CONV,
        Gb, CS, (size_t)CS * CS,
        CS, CS, DS);

    diag_kernel<<<B_ * NC * NH, 256>>>(Dp);
    states_kernel<<<B_ * NC * NH, 256>>>();
    cscan_kernel<<<B_ * NH, 256>>>();
    yoff_kernel<<<B_ * NC * NH, 256>>>();
    gate_kernel<<<BL, 256>>>(gnorm_w);

    // out = x + yn @ out_proj_w^T   (4096 x 1024 x 2048)
    mma_gemm_kernel<<<dim3(DM / 128, BL / 128), 256, GEMM_SMEM>>>(
        ynh, ynl, wo, out, DM, x, DM, BL, DM, DI);
}

// round 9
// speedup vs baseline: 2.3013x; 1.0918x over previous
#include <cuda_runtime.h>
#include <cuda_fp16.h>
#include <math.h>
#include <stdint.h>

// ---------------- problem constants ----------------
constexpr int B_  = 2;
constexpr int L_  = 2048;
constexpr int DM  = 1024;
constexpr int DS  = 128;
constexpr int DC  = 4;
constexpr int HD  = 64;
constexpr int DI  = 2048;      // EXP*DM
constexpr int NH  = 32;        // DI/HD
constexpr int CONV = DI + 2*DS;        // 2304
constexpr int DIN  = 2*DI + 2*DS + NH; // 4384
constexpr int CS  = 256;
constexpr int NC  = L_ / CS;   // 8
constexpr int BL  = B_ * L_;   // 4096
constexpr float EPS = 1e-5f;

// ---------------- scratch (static device globals; no cudaMalloc allowed) ----
__device__ float g_zx[(size_t)BL * DIN];
__device__ float g_xBC[(size_t)BL * CONV];
__device__ float g_dt[BL * NH];
__device__ float g_Acs[B_ * NC * NH * CS];
__device__ float g_G[(size_t)B_ * NC * CS * CS];   // TRANSPOSED: GT[s][l]
__device__ float g_states[(size_t)B_ * NC * NH * HD * DS];
__device__ float g_Sprev[(size_t)B_ * NC * NH * HD * DS];
__device__ float g_Y[(size_t)BL * DI];

// fp16 split buffers: A operands get (hi,lo); W operands single fp16
__device__ __half g_xnh[(size_t)BL * DM];
__device__ __half g_xnl[(size_t)BL * DM];
__device__ __half g_wi[(size_t)DIN * DM];
__device__ __half g_ynh[(size_t)BL * DI];
__device__ __half g_ynl[(size_t)BL * DI];
__device__ __half g_wo[(size_t)DM * DI];

// ---------------- helpers ----------------
__device__ __forceinline__ void hsplit(float v, __half &hi, __half &lo) {
    hi = __float2half_rn(v);
    lo = __float2half_rn(v - __half2float(hi));
}

__device__ __forceinline__ void ldsm4(uint32_t &r0, uint32_t &r1, uint32_t &r2, uint32_t &r3,
                                      const __half* p) {
    uint32_t addr = (uint32_t)__cvta_generic_to_shared(p);
    asm volatile("ldmatrix.sync.aligned.m8n8.x4.shared.b16 {%0,%1,%2,%3}, [%4];"
                 : "=r"(r0), "=r"(r1), "=r"(r2), "=r"(r3) : "r"(addr));
}

__device__ __forceinline__ void mma16816(float* c, const uint32_t* a, const uint32_t* b) {
    asm volatile("mma.sync.aligned.m16n8k16.row.col.f32.f16.f16.f32 "
                 "{%0,%1,%2,%3}, {%4,%5,%6,%7}, {%8,%9}, {%0,%1,%2,%3};"
                 : "+f"(c[0]), "+f"(c[1]), "+f"(c[2]), "+f"(c[3])
                 : "r"(a[0]), "r"(a[1]), "r"(a[2]), "r"(a[3]), "r"(b[0]), "r"(b[1]));
}

__device__ __forceinline__ void cpa16(uint32_t saddr, const void* g, int sz) {
    asm volatile("cp.async.cg.shared.global [%0], [%1], 16, %2;"
                 :: "r"(saddr), "l"(g), "r"(sz));
}
__device__ __forceinline__ void cpa_commit() { asm volatile("cp.async.commit_group;"); }
template <int N>
__device__ __forceinline__ void cpa_wait() { asm volatile("cp.async.wait_group %0;" :: "n"(N)); }

// ---------------- weight convert: fp32 -> fp16 ----------------
__global__ void wconv_kernel(const float* __restrict__ src,
                             __half* __restrict__ dst, int n4) {
    int i = blockIdx.x * 256 + threadIdx.x;
    if (i >= n4) return;
    float4 v = ((const float4*)src)[i];
    __half2 a = make_half2(__float2half_rn(v.x), __float2half_rn(v.y));
    __half2 b = make_half2(__float2half_rn(v.z), __float2half_rn(v.w));
    ((__half2*)dst)[i * 2]     = a;
    ((__half2*)dst)[i * 2 + 1] = b;
}

// ---------------- RMSNorm on input -> split fp16 ----------------
__global__ void rms_kernel(const float* __restrict__ x, const float* __restrict__ norm_w) {
    int r = blockIdx.x, tid = threadIdx.x;
    __shared__ float red[256];
    float v[4]; float sum = 0.f;
#pragma unroll
    for (int j = 0; j < 4; j++) {
        int i = tid + j * 256;
        v[j] = x[(size_t)r * DM + i];
        sum += v[j] * v[j];
    }
    red[tid] = sum; __syncthreads();
    for (int s = 128; s > 0; s >>= 1) { if (tid < s) red[tid] += red[tid + s]; __syncthreads(); }
    float rinv = rsqrtf(red[0] / DM + EPS);
#pragma unroll
    for (int j = 0; j < 4; j++) {
        int i = tid + j * 256;
        float xv = v[j] * rinv * norm_w[i];
        __half h, l; hsplit(xv, h, l);
        g_xnh[(size_t)r * DM + i] = h;
        g_xnl[(size_t)r * DM + i] = l;
    }
}

// ---------------- fp16 2-term split tensor-core GEMM ------------------------
constexpr int ASTR = 72;             // smem half-stride (64 + 8 pad)
constexpr int ARR_H = 128 * ASTR;    // halfs per array (9216)
constexpr int STG_B = 3 * ARR_H * 2;               // bytes per stage (55296)
constexpr int GEMM_SMEM = 2 * STG_B;               // 110592

__global__ __launch_bounds__(256, 2) void mma_gemm_kernel(
    const __half* __restrict__ Ah, const __half* __restrict__ Al,
    const __half* __restrict__ Wh,
    float* __restrict__ C, int ldc,
    const float* __restrict__ res, int ldr,
    int M, int N, int K)
{
    extern __shared__ __half smem[];
    int tid = threadIdx.x;
    int lane = tid & 31, warp = tid >> 5;
    int wm = warp >> 1, wn = warp & 1;
    int rowBase = blockIdx.y * 128;
    int colBase = blockIdx.x * 128;

    uint32_t sbase = (uint32_t)__cvta_generic_to_shared(smem);

    int rowA[4], seg[4], so[4], nW[4], wsz[4];
#pragma unroll
    for (int i = 0; i < 4; i++) {
        int id = tid + i * 256;
        rowA[i] = id >> 3; seg[i] = id & 7;
        so[i] = (rowA[i] * ASTR + seg[i] * 8) * 2;
        int n = colBase + rowA[i];
        wsz[i] = (n < N) ? 16 : 0;
        nW[i] = (n < N) ? n : 0;
    }

    int nt = K / 64;
    auto issue = [&](int t) {
        int st = t & 1;
        int k0 = t * 64;
        uint32_t sb = sbase + st * STG_B;
#pragma unroll
        for (int i = 0; i < 4; i++) {
            size_t ga = (size_t)(rowBase + rowA[i]) * K + k0 + seg[i] * 8;
            size_t gw = (size_t)nW[i] * K + k0 + seg[i] * 8;
            cpa16(sb + so[i],               Ah + ga, 16);
            cpa16(sb + ARR_H*2 + so[i],     Al + ga, 16);
            cpa16(sb + 2*ARR_H*2 + so[i],   Wh + gw, wsz[i]);
        }
        cpa_commit();
    };

    float acc[2][8][4];
#pragma unroll
    for (int mt = 0; mt < 2; mt++)
#pragma unroll
        for (int ntt = 0; ntt < 8; ntt++)
#pragma unroll
            for (int q = 0; q < 4; q++) acc[mt][ntt][q] = 0.f;

    issue(0);
    if (nt > 1) issue(1);

    for (int t = 0; t < nt; t++) {
        if (t + 1 < nt) cpa_wait<1>(); else cpa_wait<0>();
        __syncthreads();

        int st = t & 1;
        __half* Ash = smem + st * 3 * ARR_H;
        __half* Asl = Ash + ARR_H;
        __half* Wsh = Ash + 2 * ARR_H;

#pragma unroll
        for (int kk = 0; kk < 64; kk += 16) {
            uint32_t ah[2][4], al[2][4];
#pragma unroll
            for (int mt = 0; mt < 2; mt++) {
                int r = wm * 32 + mt * 16 + (lane & 15);
                int c = kk + (lane >> 4) * 8;
                ldsm4(ah[mt][0], ah[mt][1], ah[mt][2], ah[mt][3], &Ash[r * ASTR + c]);
                ldsm4(al[mt][0], al[mt][1], al[mt][2], al[mt][3], &Asl[r * ASTR + c]);
            }
            uint32_t bh[8][2];
#pragma unroll
            for (int np = 0; np < 4; np++) {
                int nb = wn * 64 + np * 16;
                int grp = lane >> 3;
                int r = nb + (grp >> 1) * 8 + (lane & 7);
                int c = kk + (grp & 1) * 8;
                ldsm4(bh[np*2][0], bh[np*2][1], bh[np*2+1][0], bh[np*2+1][1], &Wsh[r * ASTR + c]);
            }
#pragma unroll
            for (int mt = 0; mt < 2; mt++)
#pragma unroll
                for (int ntt = 0; ntt < 8; ntt++) {
                    mma16816(acc[mt][ntt], ah[mt], bh[ntt]);
                    mma16816(acc[mt][ntt], al[mt], bh[ntt]);
                }
        }
        __syncthreads();
        if (t + 2 < nt) issue(t + 2);
    }

#pragma unroll
    for (int mt = 0; mt < 2; mt++)
#pragma unroll
        for (int ntt = 0; ntt < 8; ntt++) {
            int row = rowBase + wm * 32 + mt * 16 + (lane >> 2);
            int col = colBase + wn * 64 + ntt * 8 + (lane & 3) * 2;
            if (col < N) {
                float2 v0 = make_float2(acc[mt][ntt][0], acc[mt][ntt][1]);
                float2 v1 = make_float2(acc[mt][ntt][2], acc[mt][ntt][3]);
                if (res) {
                    float2 e0 = *(const float2*)&res[(size_t)row * ldr + col];
                    float2 e1 = *(const float2*)&res[(size_t)(row + 8) * ldr + col];
                    v0.x += e0.x; v0.y += e0.y; v1.x += e1.x; v1.y += e1.y;
                }
                *(float2*)&C[(size_t)row * ldc + col] = v0;
                *(float2*)&C[(size_t)(row + 8) * ldc + col] = v1;
            }
        }
}

// ---------------- fp32 SGEMM (small G matmul only) ----------------
__global__ __launch_bounds__(256, 2) void sgemm2_kernel(
    const float* __restrict__ A, int lda, size_t batchA,
    const float* __restrict__ W, int ldw, size_t batchW,
    float* __restrict__ C, int ldc, size_t batchC,
    int M, int N, int K)
{
    __shared__ float As[16][132];
    __shared__ float Ws[16][132];
    int tid = threadIdx.x;
    int tx = tid & 15, ty = tid >> 4;
    const float* Ab = A + (size_t)blockIdx.z * batchA;
    const float* Wb = W + (size_t)blockIdx.z * batchW;
    float*       Cb = C + (size_t)blockIdx.z * batchC;
    int rowBase = blockIdx.y * 128;
    int colBase = blockIdx.x * 128;

    float acc[8][8];
#pragma unroll
    for (int i = 0; i < 8; i++)
#pragma unroll
        for (int j = 0; j < 8; j++) acc[i][j] = 0.f;

    for (int k0 = 0; k0 < K; k0 += 16) {
#pragma unroll
        for (int i = 0; i < 2; i++) {
            int t = tid + i * 256;
            int r = t >> 2, kq = t & 3;
            float4 v = *(const float4*)&Ab[(size_t)(rowBase + r) * lda + k0 + kq * 4];
            As[kq * 4 + 0][r] = v.x; As[kq * 4 + 1][r] = v.y;
            As[kq * 4 + 2][r] = v.z; As[kq * 4 + 3][r] = v.w;
        }
#pragma unroll
        for (int i = 0; i < 2; i++) {
            int t = tid + i * 256;
            int r = t >> 2, kq = t & 3;
            float4 v = *(const float4*)&Wb[(size_t)(colBase + r) * ldw + k0 + kq * 4];
            Ws[kq * 4 + 0][r] = v.x; Ws[kq * 4 + 1][r] = v.y;
            Ws[kq * 4 + 2][r] = v.z; Ws[kq * 4 + 3][r] = v.w;
        }
        __syncthreads();
#pragma unroll
        for (int kk = 0; kk < 16; kk++) {
            float a[8], b[8];
            *(float4*)&a[0] = *(const float4*)&As[kk][ty * 8];
            *(float4*)&a[4] = *(const float4*)&As[kk][ty * 8 + 4];
            *(float4*)&b[0] = *(const float4*)&Ws[kk][tx * 8];
            *(float4*)&b[4] = *(const float4*)&Ws[kk][tx * 8 + 4];
#pragma unroll
            for (int i = 0; i < 8; i++)
#pragma unroll
                for (int j = 0; j < 8; j++) acc[i][j] += a[i] * b[j];
        }
        __syncthreads();
    }
#pragma unroll
    for (int i = 0; i < 8; i++) {
        int r = rowBase + ty * 8 + i;
        *(float4*)&Cb[(size_t)r * ldc + colBase + tx * 8]     = *(float4*)&acc[i][0];
        *(float4*)&Cb[(size_t)r * ldc + colBase + tx * 8 + 4] = *(float4*)&acc[i][4];
    }
}

// ---------------- depthwise causal conv(4) + SiLU ----------------
__global__ void conv_kernel(const float* __restrict__ conv_w, const float* __restrict__ conv_b) {
    int r = blockIdx.x;
    int bi = r / L_, l = r % L_;
    for (int c = threadIdx.x; c < CONV; c += 256) {
        float s = conv_b[c];
#pragma unroll
        for (int k = 0; k < DC; k++) {
            int lt = l + k - (DC - 1);
            if (lt >= 0)
                s += g_zx[(size_t)(bi * L_ + lt) * DIN + DI + c] * conv_w[c * DC + k];
        }
        float sig = 1.f / (1.f + __expf(-s));
        g_xBC[(size_t)r * CONV + c] = s * sig;
    }
}

// ---------------- fused: dt=softplus(dt+bias), dA=dt*A, per-chunk cumsum ----
__global__ void acs_kernel(const float* __restrict__ dt_bias, const float* __restrict__ A_log) {
    int blk = blockIdx.x, tid = threadIdx.x;
    int bi = blk / (NC * NH);
    int rem = blk % (NC * NH);
    int c = rem / NH, h = rem % NH;
    __shared__ float s[CS];
    int t = bi * L_ + c * CS + tid;
    float v = g_zx[(size_t)t * DIN + (DIN - NH) + h] + dt_bias[h];
    float dtv = (v > 20.f) ? v : log1pf(__expf(v));
    g_dt[t * NH + h] = dtv;
    s[tid] = -__expf(A_log[h]) * dtv;
    __syncthreads();
    for (int off = 1; off < CS; off <<= 1) {
        float p = (tid >= off) ? s[tid - off] : 0.f;
        __syncthreads();
        s[tid] += p;
        __syncthreads();
    }
    g_Acs[blk * CS + tid] = s[tid];
}

// ---------------- Y_diag + D*xh : running-product L, single pass ------------
// Uses transposed G (GT[s][l]) for coalesced loads; Es[s]=exp(dA_s) table
// replaces per-(l,s) exp (kills the MUFU wall).
constexpr int DIAG_SMEM = CS * 64 * 4;   // 64KB dynamic (X chunk)

__global__ __launch_bounds__(256) void diag_kernel(const float* __restrict__ Dp) {
    int blk = blockIdx.x, tid = threadIdx.x;
    int bi = blk / (NC * NH);
    int rem = blk % (NC * NH);
    int c = rem / NH, h = rem % NH;
    extern __shared__ float Xs[];        // [CS][64]
    __shared__ float Acss[CS];
    __shared__ float Es[CS];
    int rowBase = bi * L_ + c * CS;
    Acss[tid] = g_Acs[blk * CS + tid];
    __syncthreads();
    Es[tid] = __expf(tid ? Acss[tid] - Acss[tid - 1] : Acss[0]);

    // fill X chunk: thread owns column p = tid&63, rows s = (tid>>6) + 4i
    {
        int p = tid & 63, s0 = tid >> 6;
        for (int i = 0; i < 64; i++) {
            int s = s0 + i * 4;
            int t = rowBase + s;
            Xs[s * 64 + p] = g_xBC[(size_t)t * CONV + h * HD + p] * g_dt[t * NH + h];
        }
    }
    __syncthreads();

    int l = tid;
    const float* GT = &g_G[(size_t)(bi * NC + c) * CS * CS];
    float y[64];
#pragma unroll
    for (int p = 0; p < 64; p++) y[p] = 0.f;

    float L = 0.f;
    for (int s = (l | 31); s >= 0; s--) {
        if (s == l) L = 1.f;
        if (s <= l) {
            float coef = GT[(size_t)s * CS + l] * L;
            const float* xr = &Xs[s * 64];
#pragma unroll
            for (int p = 0; p < 64; p++) y[p] += coef * xr[p];
        }
        L *= Es[s];
    }

    float dH = Dp[h];
    int t = rowBase + l;
    size_t ob = (size_t)t * DI + h * HD;
#pragma unroll
    for (int p = 0; p < 64; p++) {
        float xh = g_xBC[(size_t)t * CONV + h * HD + p];
        g_Y[ob + p] = y[p] + dH * xh;
    }
}

// ---------------- per-chunk state: states[p,n] = sum_l B[l,n]*decay*X[l,p] ---
__global__ __launch_bounds__(256) void states_kernel() {
    int blk = blockIdx.x, tid = threadIdx.x;
    int bi = blk / (NC * NH);
    int rem = blk % (NC * NH);
    int c = rem / NH, h = rem % NH;
    __shared__ float Xs[32][64];
    __shared__ float Bs[32][128];
    __shared__ float wdec[CS];
    int rowBase = bi * L_ + c * CS;
    float acsLast = g_Acs[blk * CS + (CS - 1)];
    wdec[tid] = __expf(acsLast - g_Acs[blk * CS + tid]);
    int tn = tid & 31, tp = tid >> 5;
    float acc[8][4];
#pragma unroll
    for (int i = 0; i < 8; i++)
#pragma unroll
        for (int j = 0; j < 4; j++) acc[i][j] = 0.f;

    for (int l0 = 0; l0 < CS; l0 += 32) {
        __syncthreads();
#pragma unroll
        for (int i = 0; i < 8; i++) {
            int lin = tid + i * 256;
            int s = lin >> 6, p = lin & 63;
            int t = rowBase + l0 + s;
            Xs[s][p] = g_xBC[(size_t)t * CONV + h * HD + p] * g_dt[t * NH + h] * wdec[l0 + s];
        }
#pragma unroll
        for (int i = 0; i < 16; i++) {
            int lin = tid + i * 256;
            int s = lin >> 7, n = lin & 127;
            Bs[s][n] = g_xBC[(size_t)(rowBase + l0 + s) * CONV + DI + n];
        }
        __syncthreads();
#pragma unroll 4
        for (int ll = 0; ll < 32; ll++) {
            float4 xa = *(const float4*)&Xs[ll][tp * 8];
            float4 xb = *(const float4*)&Xs[ll][tp * 8 + 4];
            float4 bv = *(const float4*)&Bs[ll][tn * 4];
            float xv[8] = {xa.x, xa.y, xa.z, xa.w, xb.x, xb.y, xb.z, xb.w};
            float bw[4] = {bv.x, bv.y, bv.z, bv.w};
#pragma unroll
            for (int i = 0; i < 8; i++)
#pragma unroll
                for (int j = 0; j < 4; j++) acc[i][j] += xv[i] * bw[j];
        }
    }
    size_t base = (size_t)blk * HD * DS;
#pragma unroll
    for (int i = 0; i < 8; i++) {
        int p = tp * 8 + i;
#pragma unroll
        for (int j = 0; j < 4; j++) {
            int n = tn * 4 + j;
            g_states[base + (size_t)p * DS + n] = acc[i][j];
        }
    }
}

// ---------------- inter-chunk scan ----------------
__global__ void cscan_kernel() {
    int bi = blockIdx.x / NH, h = blockIdx.x % NH;
    int tid = threadIdx.x;
    float P[32];
#pragma unroll
    for (int j = 0; j < 32; j++) P[j] = 0.f;
    for (int c = 0; c < NC; c++) {
        int cb = (bi * NC + c) * NH + h;
        size_t sb = (size_t)cb * HD * DS;
        float T = __expf(g_Acs[cb * CS + (CS - 1)]);
#pragma unroll
        for (int j = 0; j < 32; j++) {
            int e = tid + j * 256;
            g_Sprev[sb + e] = P[j];
            P[j] = P[j] * T + g_states[sb + e];
        }
    }
}

// ---------------- Y_off ----------------
__global__ __launch_bounds__(256) void yoff_kernel() {
    int blk = blockIdx.x, tid = threadIdx.x;
    int bi = blk / (NC * NH);
    int rem = blk % (NC * NH);
    int c = rem / NH, h = rem % NH;
    __shared__ float Ss[64][128];
    size_t sb = (size_t)blk * HD * DS;
#pragma unroll
    for (int i = 0; i < 32; i++) {
        int lin = tid + i * 256;
        Ss[lin >> 7][lin & 127] = g_Sprev[sb + lin];
    }
    int l = tid;
    int t = bi * L_ + c * CS + l;
    float scale = __expf(g_Acs[blk * CS + l]);
    const float* Crow = &g_xBC[(size_t)t * CONV + DI + DS];
    __syncthreads();

    for (int pg = 0; pg < 4; pg++) {
        float acc[16];
#pragma unroll
        for (int pi = 0; pi < 16; pi++) acc[pi] = 0.f;
        for (int n = 0; n < DS; n++) {
            float cv = Crow[n];
#pragma unroll
            for (int pi = 0; pi < 16; pi++) acc[pi] += cv * Ss[pg * 16 + pi][n];
        }
        size_t ob = (size_t)t * DI + h * HD + pg * 16;
#pragma unroll
        for (int pi = 0; pi < 16; pi++) g_Y[ob + pi] += scale * acc[pi];
    }
}

// ---------------- gate with silu(z), group-RMS, split to fp16 ---------------
__global__ void gate_kernel(const float* __restrict__ gnorm_w) {
    int r = blockIdx.x, tid = threadIdx.x;
    __shared__ float red[256];
    float g[8]; float sum = 0.f;
#pragma unroll
    for (int j = 0; j < 8; j++) {
        int i = tid + j * 256;
        float yv = g_Y[(size_t)r * DI + i];
        float z = g_zx[(size_t)r * DIN + i];
        float s = 1.f / (1.f + __expf(-z));
        float gv = yv * z * s;
        g[j] = gv; sum += gv * gv;
    }
    red[tid] = sum; __syncthreads();
    for (int s = 128; s > 0; s >>= 1) { if (tid < s) red[tid] += red[tid + s]; __syncthreads(); }
    float rinv = rsqrtf(red[0] / DI + EPS);
#pragma unroll
    for (int j = 0; j < 8; j++) {
        int i = tid + j * 256;
        float yn = g[j] * rinv * gnorm_w[i];
        __half h, l; hsplit(yn, h, l);
        g_ynh[(size_t)r * DI + i] = h;
        g_ynl[(size_t)r * DI + i] = l;
    }
}

// ---------------- launch ----------------
extern "C" void kernel_launch(void* const* d_in, const int* in_sizes, int n_in,
                              void* d_out, int out_size) {
    const float* x          = (const float*)d_in[0];
    const float* norm_w     = (const float*)d_in[1];
    const float* in_proj_w  = (const float*)d_in[2];
    const float* conv_w     = (const float*)d_in[3];
    const float* conv_b     = (const float*)d_in[4];
    const float* dt_bias    = (const float*)d_in[5];
    const float* A_log      = (const float*)d_in[6];
    const float* Dp         = (const float*)d_in[7];
    const float* gnorm_w    = (const float*)d_in[8];
    const float* out_proj_w = (const float*)d_in[9];
    float* out = (float*)d_out;

    float *zx, *xBC, *Gb;
    __half *xnh, *xnl, *wi, *ynh, *ynl, *wo;
    cudaGetSymbolAddress((void**)&zx,  g_zx);
    cudaGetSymbolAddress((void**)&xBC, g_xBC);
    cudaGetSymbolAddress((void**)&Gb,  g_G);
    cudaGetSymbolAddress((void**)&xnh, g_xnh);
    cudaGetSymbolAddress((void**)&xnl, g_xnl);
    cudaGetSymbolAddress((void**)&wi,  g_wi);
    cudaGetSymbolAddress((void**)&ynh, g_ynh);
    cudaGetSymbolAddress((void**)&ynl, g_ynl);
    cudaGetSymbolAddress((void**)&wo,  g_wo);

    cudaFuncSetAttribute(mma_gemm_kernel,
                         cudaFuncAttributeMaxDynamicSharedMemorySize, GEMM_SMEM);
    cudaFuncSetAttribute(diag_kernel,
                         cudaFuncAttributeMaxDynamicSharedMemorySize, DIAG_SMEM);

    // launches 1-3 (ncu capture window lands on the in_proj GEMM, #4)
    rms_kernel<<<BL, 256>>>(x, norm_w);
    wconv_kernel<<<(DIN * DM / 4 + 255) / 256, 256>>>(in_proj_w, wi, DIN * DM / 4);
    wconv_kernel<<<(DM * DI / 4 + 255) / 256, 256>>>(out_proj_w, wo, DM * DI / 4);

    // #4: zxbcdt = xn @ in_proj_w^T   (4096 x 4384 x 1024)
    mma_gemm_kernel<<<dim3((DIN + 127) / 128, BL / 128), 256, GEMM_SMEM>>>(
        xnh, xnl, wi, zx, DIN, nullptr, 0, BL, DIN, DM);

    conv_kernel<<<BL, 256>>>(conv_w, conv_b);
    acs_kernel<<<B_ * NC * NH, 256>>>(dt_bias, A_log);

    // GT[b,c] = Bm @ Cm^T per chunk (transposed G for coalesced diag reads)
    sgemm2_kernel<<<dim3(CS / 128, CS / 128, B_ * NC), 256>>>(
        xBC + DI,      CONV, (size_t)CS * CONV,
        xBC + DI + DS, CONV, (size_t)CS * CONV,
        Gb, CS, (size_t)CS * CS,
        CS, CS, DS);

    diag_kernel<<<B_ * NC * NH, 256, DIAG_SMEM>>>(Dp);
    states_kernel<<<B_ * NC * NH, 256>>>();
    cscan_kernel<<<B_ * NH, 256>>>();
    yoff_kernel<<<B_ * NC * NH, 256>>>();
    gate_kernel<<<BL, 256>>>(gnorm_w);

    // out = x + yn @ out_proj_w^T   (4096 x 1024 x 2048)
    mma_gemm_kernel<<<dim3(DM / 128, BL / 128), 256, GEMM_SMEM>>>(
        ynh, ynl, wo, out, DM, x, DM, BL, DM, DI);
}

// round 11
// speedup vs baseline: 3.1110x; 1.3518x over previous
#include <cuda_runtime.h>
#include <cuda_fp16.h>
#include <math.h>
#include <stdint.h>

// ---------------- problem constants ----------------
constexpr int B_  = 2;
constexpr int L_  = 2048;
constexpr int DM  = 1024;
constexpr int DS  = 128;
constexpr int DC  = 4;
constexpr int HD  = 64;
constexpr int DI  = 2048;      // EXP*DM
constexpr int NH  = 32;        // DI/HD
constexpr int CONV = DI + 2*DS;        // 2304
constexpr int DIN  = 2*DI + 2*DS + NH; // 4384
constexpr int CS  = 256;
constexpr int NC  = L_ / CS;   // 8
constexpr int BL  = B_ * L_;   // 4096
constexpr float EPS = 1e-5f;

// ---------------- scratch (static device globals; no cudaMalloc allowed) ----
__device__ float g_zx[(size_t)BL * DIN];
__device__ float g_xBC[(size_t)BL * CONV];
__device__ float g_dt[BL * NH];
__device__ float g_Acs[B_ * NC * NH * CS];
__device__ float g_G[(size_t)B_ * NC * CS * CS];   // TRANSPOSED: GT[s][l]
__device__ float g_states[(size_t)B_ * NC * NH * HD * DS];
__device__ float g_Sprev[(size_t)B_ * NC * NH * HD * DS];
__device__ float g_Y[(size_t)BL * DI];

// fp16 split buffers: A operands get (hi,lo); W operands single fp16
__device__ __half g_xnh[(size_t)BL * DM];
__device__ __half g_xnl[(size_t)BL * DM];
__device__ __half g_wi[(size_t)DIN * DM];
__device__ __half g_ynh[(size_t)BL * DI];
__device__ __half g_ynl[(size_t)BL * DI];
__device__ __half g_wo[(size_t)DM * DI];

// ---------------- helpers ----------------
__device__ __forceinline__ void hsplit(float v, __half &hi, __half &lo) {
    hi = __float2half_rn(v);
    lo = __float2half_rn(v - __half2float(hi));
}

__device__ __forceinline__ void ldsm4(uint32_t &r0, uint32_t &r1, uint32_t &r2, uint32_t &r3,
                                      const __half* p) {
    uint32_t addr = (uint32_t)__cvta_generic_to_shared(p);
    asm volatile("ldmatrix.sync.aligned.m8n8.x4.shared.b16 {%0,%1,%2,%3}, [%4];"
                 : "=r"(r0), "=r"(r1), "=r"(r2), "=r"(r3) : "r"(addr));
}

__device__ __forceinline__ void mma16816(float* c, const uint32_t* a, const uint32_t* b) {
    asm volatile("mma.sync.aligned.m16n8k16.row.col.f32.f16.f16.f32 "
                 "{%0,%1,%2,%3}, {%4,%5,%6,%7}, {%8,%9}, {%0,%1,%2,%3};"
                 : "+f"(c[0]), "+f"(c[1]), "+f"(c[2]), "+f"(c[3])
                 : "r"(a[0]), "r"(a[1]), "r"(a[2]), "r"(a[3]), "r"(b[0]), "r"(b[1]));
}

__device__ __forceinline__ void cpa16(uint32_t saddr, const void* g, int sz) {
    asm volatile("cp.async.cg.shared.global [%0], [%1], 16, %2;"
                 :: "r"(saddr), "l"(g), "r"(sz));
}
__device__ __forceinline__ void cpa_commit() { asm volatile("cp.async.commit_group;"); }
template <int N>
__device__ __forceinline__ void cpa_wait() { asm volatile("cp.async.wait_group %0;" :: "n"(N)); }

// ---------------- weight convert: fp32 -> fp16 ----------------
__global__ void wconv_kernel(const float* __restrict__ src,
                             __half* __restrict__ dst, int n4) {
    int i = blockIdx.x * 256 + threadIdx.x;
    if (i >= n4) return;
    float4 v = ((const float4*)src)[i];
    __half2 a = make_half2(__float2half_rn(v.x), __float2half_rn(v.y));
    __half2 b = make_half2(__float2half_rn(v.z), __float2half_rn(v.w));
    ((__half2*)dst)[i * 2]     = a;
    ((__half2*)dst)[i * 2 + 1] = b;
}

// ---------------- RMSNorm on input -> split fp16 ----------------
__global__ void rms_kernel(const float* __restrict__ x, const float* __restrict__ norm_w) {
    int r = blockIdx.x, tid = threadIdx.x;
    __shared__ float red[256];
    float v[4]; float sum = 0.f;
#pragma unroll
    for (int j = 0; j < 4; j++) {
        int i = tid + j * 256;
        v[j] = x[(size_t)r * DM + i];
        sum += v[j] * v[j];
    }
    red[tid] = sum; __syncthreads();
    for (int s = 128; s > 0; s >>= 1) { if (tid < s) red[tid] += red[tid + s]; __syncthreads(); }
    float rinv = rsqrtf(red[0] / DM + EPS);
#pragma unroll
    for (int j = 0; j < 4; j++) {
        int i = tid + j * 256;
        float xv = v[j] * rinv * norm_w[i];
        __half h, l; hsplit(xv, h, l);
        g_xnh[(size_t)r * DM + i] = h;
        g_xnl[(size_t)r * DM + i] = l;
    }
}

// ---------------- fp16 2-term split tensor-core GEMM ------------------------
constexpr int ASTR = 72;             // smem half-stride (64 + 8 pad)
constexpr int ARR_H = 128 * ASTR;    // halfs per array (9216)
constexpr int STG_B = 3 * ARR_H * 2;               // bytes per stage (55296)
constexpr int GEMM_SMEM = 2 * STG_B;               // 110592

__global__ __launch_bounds__(256, 2) void mma_gemm_kernel(
    const __half* __restrict__ Ah, const __half* __restrict__ Al,
    const __half* __restrict__ Wh,
    float* __restrict__ C, int ldc,
    const float* __restrict__ res, int ldr,
    int M, int N, int K)
{
    extern __shared__ __half smem[];
    int tid = threadIdx.x;
    int lane = tid & 31, warp = tid >> 5;
    int wm = warp >> 1, wn = warp & 1;
    int rowBase = blockIdx.y * 128;
    int colBase = blockIdx.x * 128;

    uint32_t sbase = (uint32_t)__cvta_generic_to_shared(smem);

    int rowA[4], seg[4], so[4], nW[4], wsz[4];
#pragma unroll
    for (int i = 0; i < 4; i++) {
        int id = tid + i * 256;
        rowA[i] = id >> 3; seg[i] = id & 7;
        so[i] = (rowA[i] * ASTR + seg[i] * 8) * 2;
        int n = colBase + rowA[i];
        wsz[i] = (n < N) ? 16 : 0;
        nW[i] = (n < N) ? n : 0;
    }

    int nt = K / 64;
    auto issue = [&](int t) {
        int st = t & 1;
        int k0 = t * 64;
        uint32_t sb = sbase + st * STG_B;
#pragma unroll
        for (int i = 0; i < 4; i++) {
            size_t ga = (size_t)(rowBase + rowA[i]) * K + k0 + seg[i] * 8;
            size_t gw = (size_t)nW[i] * K + k0 + seg[i] * 8;
            cpa16(sb + so[i],               Ah + ga, 16);
            cpa16(sb + ARR_H*2 + so[i],     Al + ga, 16);
            cpa16(sb + 2*ARR_H*2 + so[i],   Wh + gw, wsz[i]);
        }
        cpa_commit();
    };

    float acc[2][8][4];
#pragma unroll
    for (int mt = 0; mt < 2; mt++)
#pragma unroll
        for (int ntt = 0; ntt < 8; ntt++)
#pragma unroll
            for (int q = 0; q < 4; q++) acc[mt][ntt][q] = 0.f;

    issue(0);
    if (nt > 1) issue(1);

    for (int t = 0; t < nt; t++) {
        if (t + 1 < nt) cpa_wait<1>(); else cpa_wait<0>();
        __syncthreads();

        int st = t & 1;
        __half* Ash = smem + st * 3 * ARR_H;
        __half* Asl = Ash + ARR_H;
        __half* Wsh = Ash + 2 * ARR_H;

#pragma unroll
        for (int kk = 0; kk < 64; kk += 16) {
            uint32_t ah[2][4], al[2][4];
#pragma unroll
            for (int mt = 0; mt < 2; mt++) {
                int r = wm * 32 + mt * 16 + (lane & 15);
                int c = kk + (lane >> 4) * 8;
                ldsm4(ah[mt][0], ah[mt][1], ah[mt][2], ah[mt][3], &Ash[r * ASTR + c]);
                ldsm4(al[mt][0], al[mt][1], al[mt][2], al[mt][3], &Asl[r * ASTR + c]);
            }
            uint32_t bh[8][2];
#pragma unroll
            for (int np = 0; np < 4; np++) {
                int nb = wn * 64 + np * 16;
                int grp = lane >> 3;
                int r = nb + (grp >> 1) * 8 + (lane & 7);
                int c = kk + (grp & 1) * 8;
                ldsm4(bh[np*2][0], bh[np*2][1], bh[np*2+1][0], bh[np*2+1][1], &Wsh[r * ASTR + c]);
            }
#pragma unroll
            for (int mt = 0; mt < 2; mt++)
#pragma unroll
                for (int ntt = 0; ntt < 8; ntt++) {
                    mma16816(acc[mt][ntt], ah[mt], bh[ntt]);
                    mma16816(acc[mt][ntt], al[mt], bh[ntt]);
                }
        }
        __syncthreads();
        if (t + 2 < nt) issue(t + 2);
    }

#pragma unroll
    for (int mt = 0; mt < 2; mt++)
#pragma unroll
        for (int ntt = 0; ntt < 8; ntt++) {
            int row = rowBase + wm * 32 + mt * 16 + (lane >> 2);
            int col = colBase + wn * 64 + ntt * 8 + (lane & 3) * 2;
            if (col < N) {
                float2 v0 = make_float2(acc[mt][ntt][0], acc[mt][ntt][1]);
                float2 v1 = make_float2(acc[mt][ntt][2], acc[mt][ntt][3]);
                if (res) {
                    float2 e0 = *(const float2*)&res[(size_t)row * ldr + col];
                    float2 e1 = *(const float2*)&res[(size_t)(row + 8) * ldr + col];
                    v0.x += e0.x; v0.y += e0.y; v1.x += e1.x; v1.y += e1.y;
                }
                *(float2*)&C[(size_t)row * ldc + col] = v0;
                *(float2*)&C[(size_t)(row + 8) * ldc + col] = v1;
            }
        }
}

// ---------------- fp32 SGEMM (small G matmul only) ----------------
__global__ __launch_bounds__(256, 2) void sgemm2_kernel(
    const float* __restrict__ A, int lda, size_t batchA,
    const float* __restrict__ W, int ldw, size_t batchW,
    float* __restrict__ C, int ldc, size_t batchC,
    int M, int N, int K)
{
    __shared__ float As[16][132];
    __shared__ float Ws[16][132];
    int tid = threadIdx.x;
    int tx = tid & 15, ty = tid >> 4;
    const float* Ab = A + (size_t)blockIdx.z * batchA;
    const float* Wb = W + (size_t)blockIdx.z * batchW;
    float*       Cb = C + (size_t)blockIdx.z * batchC;
    int rowBase = blockIdx.y * 128;
    int colBase = blockIdx.x * 128;

    float acc[8][8];
#pragma unroll
    for (int i = 0; i < 8; i++)
#pragma unroll
        for (int j = 0; j < 8; j++) acc[i][j] = 0.f;

    for (int k0 = 0; k0 < K; k0 += 16) {
#pragma unroll
        for (int i = 0; i < 2; i++) {
            int t = tid + i * 256;
            int r = t >> 2, kq = t & 3;
            float4 v = *(const float4*)&Ab[(size_t)(rowBase + r) * lda + k0 + kq * 4];
            As[kq * 4 + 0][r] = v.x; As[kq * 4 + 1][r] = v.y;
            As[kq * 4 + 2][r] = v.z; As[kq * 4 + 3][r] = v.w;
        }
#pragma unroll
        for (int i = 0; i < 2; i++) {
            int t = tid + i * 256;
            int r = t >> 2, kq = t & 3;
            float4 v = *(const float4*)&Wb[(size_t)(colBase + r) * ldw + k0 + kq * 4];
            Ws[kq * 4 + 0][r] = v.x; Ws[kq * 4 + 1][r] = v.y;
            Ws[kq * 4 + 2][r] = v.z; Ws[kq * 4 + 3][r] = v.w;
        }
        __syncthreads();
#pragma unroll
        for (int kk = 0; kk < 16; kk++) {
            float a[8], b[8];
            *(float4*)&a[0] = *(const float4*)&As[kk][ty * 8];
            *(float4*)&a[4] = *(const float4*)&As[kk][ty * 8 + 4];
            *(float4*)&b[0] = *(const float4*)&Ws[kk][tx * 8];
            *(float4*)&b[4] = *(const float4*)&Ws[kk][tx * 8 + 4];
#pragma unroll
            for (int i = 0; i < 8; i++)
#pragma unroll
                for (int j = 0; j < 8; j++) acc[i][j] += a[i] * b[j];
        }
        __syncthreads();
    }
#pragma unroll
    for (int i = 0; i < 8; i++) {
        int r = rowBase + ty * 8 + i;
        *(float4*)&Cb[(size_t)r * ldc + colBase + tx * 8]     = *(float4*)&acc[i][0];
        *(float4*)&Cb[(size_t)r * ldc + colBase + tx * 8 + 4] = *(float4*)&acc[i][4];
    }
}

// ---------------- depthwise causal conv(4) + SiLU ----------------
__global__ void conv_kernel(const float* __restrict__ conv_w, const float* __restrict__ conv_b) {
    int r = blockIdx.x;
    int bi = r / L_, l = r % L_;
    for (int c = threadIdx.x; c < CONV; c += 256) {
        float s = conv_b[c];
#pragma unroll
        for (int k = 0; k < DC; k++) {
            int lt = l + k - (DC - 1);
            if (lt >= 0)
                s += g_zx[(size_t)(bi * L_ + lt) * DIN + DI + c] * conv_w[c * DC + k];
        }
        float sig = 1.f / (1.f + __expf(-s));
        g_xBC[(size_t)r * CONV + c] = s * sig;
    }
}

// ---------------- fused: dt=softplus(dt+bias), dA=dt*A, per-chunk cumsum ----
__global__ void acs_kernel(const float* __restrict__ dt_bias, const float* __restrict__ A_log) {
    int blk = blockIdx.x, tid = threadIdx.x;
    int bi = blk / (NC * NH);
    int rem = blk % (NC * NH);
    int c = rem / NH, h = rem % NH;
    __shared__ float s[CS];
    int t = bi * L_ + c * CS + tid;
    float v = g_zx[(size_t)t * DIN + (DIN - NH) + h] + dt_bias[h];
    float dtv = (v > 20.f) ? v : log1pf(__expf(v));
    g_dt[t * NH + h] = dtv;
    s[tid] = -__expf(A_log[h]) * dtv;
    __syncthreads();
    for (int off = 1; off < CS; off <<= 1) {
        float p = (tid >= off) ? s[tid - off] : 0.f;
        __syncthreads();
        s[tid] += p;
        __syncthreads();
    }
    g_Acs[blk * CS + tid] = s[tid];
}

// ---------------- Y_diag + D*xh : running-product L, single pass ------------
constexpr int DIAG_SMEM = CS * 64 * 4;   // 64KB dynamic (X chunk)

__global__ __launch_bounds__(256) void diag_kernel(const float* __restrict__ Dp) {
    int blk = blockIdx.x, tid = threadIdx.x;
    int bi = blk / (NC * NH);
    int rem = blk % (NC * NH);
    int c = rem / NH, h = rem % NH;
    extern __shared__ float Xs[];        // [CS][64]
    __shared__ float Acss[CS];
    __shared__ float Es[CS];
    int rowBase = bi * L_ + c * CS;
    Acss[tid] = g_Acs[blk * CS + tid];
    __syncthreads();
    Es[tid] = __expf(tid ? Acss[tid] - Acss[tid - 1] : Acss[0]);

    {
        int p = tid & 63, s0 = tid >> 6;
        for (int i = 0; i < 64; i++) {
            int s = s0 + i * 4;
            int t = rowBase + s;
            Xs[s * 64 + p] = g_xBC[(size_t)t * CONV + h * HD + p] * g_dt[t * NH + h];
        }
    }
    __syncthreads();

    int l = tid;
    const float* GT = &g_G[(size_t)(bi * NC + c) * CS * CS];
    float y[64];
#pragma unroll
    for (int p = 0; p < 64; p++) y[p] = 0.f;

    float L = 0.f;
    for (int s = (l | 31); s >= 0; s--) {
        if (s == l) L = 1.f;
        if (s <= l) {
            float coef = GT[(size_t)s * CS + l] * L;
            const float* xr = &Xs[s * 64];
#pragma unroll
            for (int p = 0; p < 64; p++) y[p] += coef * xr[p];
        }
        L *= Es[s];
    }

    float dH = Dp[h];
    int t = rowBase + l;
    size_t ob = (size_t)t * DI + h * HD;
#pragma unroll
    for (int p = 0; p < 64; p++) {
        float xh = g_xBC[(size_t)t * CONV + h * HD + p];
        g_Y[ob + p] = y[p] + dH * xh;
    }
}

// ---------------- per-chunk state: states[p,n] = sum_l B[l,n]*decay*X[l,p] ---
__global__ __launch_bounds__(256) void states_kernel() {
    int blk = blockIdx.x, tid = threadIdx.x;
    int bi = blk / (NC * NH);
    int rem = blk % (NC * NH);
    int c = rem / NH, h = rem % NH;
    __shared__ float Xs[32][64];
    __shared__ float Bs[32][128];
    __shared__ float wdec[CS];
    int rowBase = bi * L_ + c * CS;
    float acsLast = g_Acs[blk * CS + (CS - 1)];
    wdec[tid] = __expf(acsLast - g_Acs[blk * CS + tid]);
    int tn = tid & 31, tp = tid >> 5;
    float acc[8][4];
#pragma unroll
    for (int i = 0; i < 8; i++)
#pragma unroll
        for (int j = 0; j < 4; j++) acc[i][j] = 0.f;

    for (int l0 = 0; l0 < CS; l0 += 32) {
        __syncthreads();
#pragma unroll
        for (int i = 0; i < 8; i++) {
            int lin = tid + i * 256;
            int s = lin >> 6, p = lin & 63;
            int t = rowBase + l0 + s;
            Xs[s][p] = g_xBC[(size_t)t * CONV + h * HD + p] * g_dt[t * NH + h] * wdec[l0 + s];
        }
#pragma unroll
        for (int i = 0; i < 16; i++) {
            int lin = tid + i * 256;
            int s = lin >> 7, n = lin & 127;
            Bs[s][n] = g_xBC[(size_t)(rowBase + l0 + s) * CONV + DI + n];
        }
        __syncthreads();
#pragma unroll 4
        for (int ll = 0; ll < 32; ll++) {
            float4 xa = *(const float4*)&Xs[ll][tp * 8];
            float4 xb = *(const float4*)&Xs[ll][tp * 8 + 4];
            float4 bv = *(const float4*)&Bs[ll][tn * 4];
            float xv[8] = {xa.x, xa.y, xa.z, xa.w, xb.x, xb.y, xb.z, xb.w};
            float bw[4] = {bv.x, bv.y, bv.z, bv.w};
#pragma unroll
            for (int i = 0; i < 8; i++)
#pragma unroll
                for (int j = 0; j < 4; j++) acc[i][j] += xv[i] * bw[j];
        }
    }
    size_t base = (size_t)blk * HD * DS;
#pragma unroll
    for (int i = 0; i < 8; i++) {
        int p = tp * 8 + i;
#pragma unroll
        for (int j = 0; j < 4; j++) {
            int n = tn * 4 + j;
            g_states[base + (size_t)p * DS + n] = acc[i][j];
        }
    }
}

// ---------------- inter-chunk scan (8-way element-parallel) ----------------
__global__ void cscan_kernel() {
    int part = blockIdx.x & 7;
    int hh = blockIdx.x >> 3;
    int bi = hh / NH, h = hh % NH;
    int tid = threadIdx.x;
    int ebase = part * 1024;
    float P[4];
#pragma unroll
    for (int j = 0; j < 4; j++) P[j] = 0.f;
    for (int c = 0; c < NC; c++) {
        int cb = (bi * NC + c) * NH + h;
        size_t sb = (size_t)cb * HD * DS;
        float T = __expf(g_Acs[cb * CS + (CS - 1)]);
#pragma unroll
        for (int j = 0; j < 4; j++) {
            int e = ebase + tid + j * 256;
            g_Sprev[sb + e] = P[j];
            P[j] = P[j] * T + g_states[sb + e];
        }
    }
}

// ---------------- Y_off : staged C + Sprev in smem (coalesced) --------------
constexpr int YOFF_SMEM = 2 * 64 * 129 * 4;   // 66048 bytes

__global__ __launch_bounds__(256) void yoff_kernel() {
    int blk = blockIdx.x, tid = threadIdx.x;
    int bi = blk / (NC * NH);
    int rem = blk % (NC * NH);
    int c = rem / NH, h = rem % NH;
    extern __shared__ float ysm[];
    float* Ss = ysm;                 // [64][129] : Sprev[p][n]  (stride 129 = conflict-free reads)
    float* Cs = ysm + 64 * 129;      // [64][129] : C chunk [l_local][n]
    int rowBase = bi * L_ + c * CS;
    size_t sb = (size_t)blk * HD * DS;

    // load Sprev (64x128): float4 global load, 4 scalar smem stores (129-stride
    // rows are not 16B-aligned; scalar stores keep writes conflict-free)
#pragma unroll
    for (int i = 0; i < 8; i++) {
        int idx = (tid + i * 256) * 4;
        int p = idx >> 7, n = idx & 127;
        float4 v = *(const float4*)&g_Sprev[sb + idx];
        float* d = &Ss[p * 129 + n];
        d[0] = v.x; d[1] = v.y; d[2] = v.z; d[3] = v.w;
    }

    int l_local = tid & 63;
    int pg = tid >> 6;               // 0..3 -> p range pg*16..+15

    for (int lc = 0; lc < 4; lc++) {
        __syncthreads();
        // load C chunk rows [lc*64, lc*64+64) coalesced
#pragma unroll
        for (int i = 0; i < 8; i++) {
            int idx = (tid + i * 256) * 4;
            int r = idx >> 7, n = idx & 127;
            int t = rowBase + lc * 64 + r;
            float4 v = *(const float4*)&g_xBC[(size_t)t * CONV + DI + DS + n];
            float* d = &Cs[r * 129 + n];
            d[0] = v.x; d[1] = v.y; d[2] = v.z; d[3] = v.w;
        }
        __syncthreads();

        float acc[16];
#pragma unroll
        for (int pi = 0; pi < 16; pi++) acc[pi] = 0.f;
        const float* Crow = &Cs[l_local * 129];
        for (int n = 0; n < DS; n++) {
            float cv = Crow[n];
#pragma unroll
            for (int pi = 0; pi < 16; pi++) acc[pi] += cv * Ss[(pg * 16 + pi) * 129 + n];
        }

        int l = lc * 64 + l_local;
        float scale = __expf(g_Acs[blk * CS + l]);
        int t = rowBase + l;
        size_t ob = (size_t)t * DI + h * HD + pg * 16;
#pragma unroll
        for (int q = 0; q < 4; q++) {
            float4 y = *(float4*)&g_Y[ob + q * 4];
            y.x += scale * acc[q * 4 + 0];
            y.y += scale * acc[q * 4 + 1];
            y.z += scale * acc[q * 4 + 2];
            y.w += scale * acc[q * 4 + 3];
            *(float4*)&g_Y[ob + q * 4] = y;
        }
    }
}

// ---------------- gate with silu(z), group-RMS, split to fp16 ---------------
__global__ void gate_kernel(const float* __restrict__ gnorm_w) {
    int r = blockIdx.x, tid = threadIdx.x;
    __shared__ float red[256];
    float g[8]; float sum = 0.f;
#pragma unroll
    for (int j = 0; j < 8; j++) {
        int i = tid + j * 256;
        float yv = g_Y[(size_t)r * DI + i];
        float z = g_zx[(size_t)r * DIN + i];
        float s = 1.f / (1.f + __expf(-z));
        float gv = yv * z * s;
        g[j] = gv; sum += gv * gv;
    }
    red[tid] = sum; __syncthreads();
    for (int s = 128; s > 0; s >>= 1) { if (tid < s) red[tid] += red[tid + s]; __syncthreads(); }
    float rinv = rsqrtf(red[0] / DI + EPS);
#pragma unroll
    for (int j = 0; j < 8; j++) {
        int i = tid + j * 256;
        float yn = g[j] * rinv * gnorm_w[i];
        __half h, l; hsplit(yn, h, l);
        g_ynh[(size_t)r * DI + i] = h;
        g_ynl[(size_t)r * DI + i] = l;
    }
}

// ---------------- launch ----------------
extern "C" void kernel_launch(void* const* d_in, const int* in_sizes, int n_in,
                              void* d_out, int out_size) {
    const float* x          = (const float*)d_in[0];
    const float* norm_w     = (const float*)d_in[1];
    const float* in_proj_w  = (const float*)d_in[2];
    const float* conv_w     = (const float*)d_in[3];
    const float* conv_b     = (const float*)d_in[4];
    const float* dt_bias    = (const float*)d_in[5];
    const float* A_log      = (const float*)d_in[6];
    const float* Dp         = (const float*)d_in[7];
    const float* gnorm_w    = (const float*)d_in[8];
    const float* out_proj_w = (const float*)d_in[9];
    float* out = (float*)d_out;

    float *zx, *xBC, *Gb;
    __half *xnh, *xnl, *wi, *ynh, *ynl, *wo;
    cudaGetSymbolAddress((void**)&zx,  g_zx);
    cudaGetSymbolAddress((void**)&xBC, g_xBC);
    cudaGetSymbolAddress((void**)&Gb,  g_G);
    cudaGetSymbolAddress((void**)&xnh, g_xnh);
    cudaGetSymbolAddress((void**)&xnl, g_xnl);
    cudaGetSymbolAddress((void**)&wi,  g_wi);
    cudaGetSymbolAddress((void**)&ynh, g_ynh);
    cudaGetSymbolAddress((void**)&ynl, g_ynl);
    cudaGetSymbolAddress((void**)&wo,  g_wo);

    cudaFuncSetAttribute(mma_gemm_kernel,
                         cudaFuncAttributeMaxDynamicSharedMemorySize, GEMM_SMEM);
    cudaFuncSetAttribute(diag_kernel,
                         cudaFuncAttributeMaxDynamicSharedMemorySize, DIAG_SMEM);
    cudaFuncSetAttribute(yoff_kernel,
                         cudaFuncAttributeMaxDynamicSharedMemorySize, YOFF_SMEM);

    // launches 1-3 (ncu capture window lands on the in_proj GEMM, #4)
    rms_kernel<<<BL, 256>>>(x, norm_w);
    wconv_kernel<<<(DIN * DM / 4 + 255) / 256, 256>>>(in_proj_w, wi, DIN * DM / 4);
    wconv_kernel<<<(DM * DI / 4 + 255) / 256, 256>>>(out_proj_w, wo, DM * DI / 4);

    // #4: zxbcdt = xn @ in_proj_w^T   (4096 x 4384 x 1024)
    mma_gemm_kernel<<<dim3((DIN + 127) / 128, BL / 128), 256, GEMM_SMEM>>>(
        xnh, xnl, wi, zx, DIN, nullptr, 0, BL, DIN, DM);

    conv_kernel<<<BL, 256>>>(conv_w, conv_b);
    acs_kernel<<<B_ * NC * NH, 256>>>(dt_bias, A_log);

    // GT[b,c] = Bm @ Cm^T per chunk (transposed G for coalesced diag reads)
    sgemm2_kernel<<<dim3(CS / 128, CS / 128, B_ * NC), 256>>>(
        xBC + DI,      CONV, (size_t)CS * CONV,
        xBC + DI + DS, CONV, (size_t)CS * CONV,
        Gb, CS, (size_t)CS * CS,
        CS, CS, DS);

    diag_kernel<<<B_ * NC * NH, 256, DIAG_SMEM>>>(Dp);
    states_kernel<<<B_ * NC * NH, 256>>>();
    cscan_kernel<<<B_ * NH * 8, 256>>>();
    yoff_kernel<<<B_ * NC * NH, 256, YOFF_SMEM>>>();
    gate_kernel<<<BL, 256>>>(gnorm_w);

    // out = x + yn @ out_proj_w^T   (4096 x 1024 x 2048)
    mma_gemm_kernel<<<dim3(DM / 128, BL / 128), 256, GEMM_SMEM>>>(
        ynh, ynl, wo, out, DM, x, DM, BL, DM, DI);
}

// round 12
// speedup vs baseline: 3.7321x; 1.1996x over previous
#include <cuda_runtime.h>
#include <cuda_fp16.h>
#include <math.h>
#include <stdint.h>

// ---------------- problem constants ----------------
constexpr int B_  = 2;
constexpr int L_  = 2048;
constexpr int DM  = 1024;
constexpr int DS  = 128;
constexpr int DC  = 4;
constexpr int HD  = 64;
constexpr int DI  = 2048;      // EXP*DM
constexpr int NH  = 32;        // DI/HD
constexpr int CONV = DI + 2*DS;        // 2304
constexpr int DIN  = 2*DI + 2*DS + NH; // 4384
constexpr int CS  = 256;
constexpr int NC  = L_ / CS;   // 8
constexpr int BL  = B_ * L_;   // 4096
constexpr float EPS = 1e-5f;

// ---------------- scratch (static device globals; no cudaMalloc allowed) ----
__device__ float g_zx[(size_t)BL * DIN];
__device__ float g_xBC[(size_t)BL * CONV];
__device__ float g_dt[BL * NH];
__device__ float g_Acs[B_ * NC * NH * CS];
__device__ float g_G[(size_t)B_ * NC * CS * CS];   // TRANSPOSED: GT[s][l]
__device__ float g_states[(size_t)B_ * NC * NH * HD * DS];
__device__ float g_Sprev[(size_t)B_ * NC * NH * HD * DS];
__device__ float g_Y[(size_t)BL * DI];

// fp16 buffers for tensor-core GEMMs
__device__ __half g_xn[(size_t)BL * DM];
__device__ __half g_wi[(size_t)DIN * DM];
__device__ __half g_yn[(size_t)BL * DI];
__device__ __half g_wo[(size_t)DM * DI];

// ---------------- helpers ----------------
__device__ __forceinline__ void ldsm4(uint32_t &r0, uint32_t &r1, uint32_t &r2, uint32_t &r3,
                                      const __half* p) {
    uint32_t addr = (uint32_t)__cvta_generic_to_shared(p);
    asm volatile("ldmatrix.sync.aligned.m8n8.x4.shared.b16 {%0,%1,%2,%3}, [%4];"
                 : "=r"(r0), "=r"(r1), "=r"(r2), "=r"(r3) : "r"(addr));
}

__device__ __forceinline__ void mma16816(float* c, const uint32_t* a, const uint32_t* b) {
    asm volatile("mma.sync.aligned.m16n8k16.row.col.f32.f16.f16.f32 "
                 "{%0,%1,%2,%3}, {%4,%5,%6,%7}, {%8,%9}, {%0,%1,%2,%3};"
                 : "+f"(c[0]), "+f"(c[1]), "+f"(c[2]), "+f"(c[3])
                 : "r"(a[0]), "r"(a[1]), "r"(a[2]), "r"(a[3]), "r"(b[0]), "r"(b[1]));
}

__device__ __forceinline__ void cpa16(uint32_t saddr, const void* g, int sz) {
    asm volatile("cp.async.cg.shared.global [%0], [%1], 16, %2;"
                 :: "r"(saddr), "l"(g), "r"(sz));
}
__device__ __forceinline__ void cpa_commit() { asm volatile("cp.async.commit_group;"); }
template <int N>
__device__ __forceinline__ void cpa_wait() { asm volatile("cp.async.wait_group %0;" :: "n"(N)); }

// ---------------- weight convert: fp32 -> fp16 ----------------
__global__ void wconv_kernel(const float* __restrict__ src,
                             __half* __restrict__ dst, int n4) {
    int i = blockIdx.x * 256 + threadIdx.x;
    if (i >= n4) return;
    float4 v = ((const float4*)src)[i];
    __half2 a = make_half2(__float2half_rn(v.x), __float2half_rn(v.y));
    __half2 b = make_half2(__float2half_rn(v.z), __float2half_rn(v.w));
    ((__half2*)dst)[i * 2]     = a;
    ((__half2*)dst)[i * 2 + 1] = b;
}

// ---------------- RMSNorm on input -> fp16 ----------------
__global__ void rms_kernel(const float* __restrict__ x, const float* __restrict__ norm_w) {
    int r = blockIdx.x, tid = threadIdx.x;
    __shared__ float red[256];
    float v[4]; float sum = 0.f;
#pragma unroll
    for (int j = 0; j < 4; j++) {
        int i = tid + j * 256;
        v[j] = x[(size_t)r * DM + i];
        sum += v[j] * v[j];
    }
    red[tid] = sum; __syncthreads();
    for (int s = 128; s > 0; s >>= 1) { if (tid < s) red[tid] += red[tid + s]; __syncthreads(); }
    float rinv = rsqrtf(red[0] / DM + EPS);
#pragma unroll
    for (int j = 0; j < 4; j++) {
        int i = tid + j * 256;
        g_xn[(size_t)r * DM + i] = __float2half_rn(v[j] * rinv * norm_w[i]);
    }
}

// ---------------- fp16 tensor-core GEMM: C[M,N] = A[M,K] @ W[N,K]^T (+res) --
// BM=BN=128, BK=64, 256 threads = 8 warps (4m x 2n), warp tile 32x64.
// 2-stage cp.async pipeline, 2 CTAs/SM.
constexpr int ASTR = 72;             // smem half-stride (64 + 8 pad)
constexpr int ARR_H = 128 * ASTR;    // halfs per array (9216)
constexpr int STG_B = 2 * ARR_H * 2;               // bytes per stage (36864)
constexpr int GEMM_SMEM = 2 * STG_B;               // 73728

__global__ __launch_bounds__(256, 2) void mma_gemm_kernel(
    const __half* __restrict__ Ah,
    const __half* __restrict__ Wh,
    float* __restrict__ C, int ldc,
    const float* __restrict__ res, int ldr,
    int M, int N, int K)
{
    extern __shared__ __half smem[];
    int tid = threadIdx.x;
    int lane = tid & 31, warp = tid >> 5;
    int wm = warp >> 1, wn = warp & 1;
    int rowBase = blockIdx.y * 128;
    int colBase = blockIdx.x * 128;

    uint32_t sbase = (uint32_t)__cvta_generic_to_shared(smem);

    int rowA[4], seg[4], so[4], nW[4], wsz[4];
#pragma unroll
    for (int i = 0; i < 4; i++) {
        int id = tid + i * 256;
        rowA[i] = id >> 3; seg[i] = id & 7;
        so[i] = (rowA[i] * ASTR + seg[i] * 8) * 2;
        int n = colBase + rowA[i];
        wsz[i] = (n < N) ? 16 : 0;
        nW[i] = (n < N) ? n : 0;
    }

    int nt = K / 64;
    auto issue = [&](int t) {
        int st = t & 1;
        int k0 = t * 64;
        uint32_t sb = sbase + st * STG_B;
#pragma unroll
        for (int i = 0; i < 4; i++) {
            size_t ga = (size_t)(rowBase + rowA[i]) * K + k0 + seg[i] * 8;
            size_t gw = (size_t)nW[i] * K + k0 + seg[i] * 8;
            cpa16(sb + so[i],             Ah + ga, 16);
            cpa16(sb + ARR_H*2 + so[i],   Wh + gw, wsz[i]);
        }
        cpa_commit();
    };

    float acc[2][8][4];
#pragma unroll
    for (int mt = 0; mt < 2; mt++)
#pragma unroll
        for (int ntt = 0; ntt < 8; ntt++)
#pragma unroll
            for (int q = 0; q < 4; q++) acc[mt][ntt][q] = 0.f;

    issue(0);
    if (nt > 1) issue(1);

    for (int t = 0; t < nt; t++) {
        if (t + 1 < nt) cpa_wait<1>(); else cpa_wait<0>();
        __syncthreads();

        int st = t & 1;
        __half* Ash = smem + st * 2 * ARR_H;
        __half* Wsh = Ash + ARR_H;

#pragma unroll
        for (int kk = 0; kk < 64; kk += 16) {
            uint32_t ah[2][4];
#pragma unroll
            for (int mt = 0; mt < 2; mt++) {
                int r = wm * 32 + mt * 16 + (lane & 15);
                int c = kk + (lane >> 4) * 8;
                ldsm4(ah[mt][0], ah[mt][1], ah[mt][2], ah[mt][3], &Ash[r * ASTR + c]);
            }
            uint32_t bh[8][2];
#pragma unroll
            for (int np = 0; np < 4; np++) {
                int nb = wn * 64 + np * 16;
                int grp = lane >> 3;
                int r = nb + (grp >> 1) * 8 + (lane & 7);
                int c = kk + (grp & 1) * 8;
                ldsm4(bh[np*2][0], bh[np*2][1], bh[np*2+1][0], bh[np*2+1][1], &Wsh[r * ASTR + c]);
            }
#pragma unroll
            for (int mt = 0; mt < 2; mt++)
#pragma unroll
                for (int ntt = 0; ntt < 8; ntt++)
                    mma16816(acc[mt][ntt], ah[mt], bh[ntt]);
        }
        __syncthreads();
        if (t + 2 < nt) issue(t + 2);
    }

#pragma unroll
    for (int mt = 0; mt < 2; mt++)
#pragma unroll
        for (int ntt = 0; ntt < 8; ntt++) {
            int row = rowBase + wm * 32 + mt * 16 + (lane >> 2);
            int col = colBase + wn * 64 + ntt * 8 + (lane & 3) * 2;
            if (col < N) {
                float2 v0 = make_float2(acc[mt][ntt][0], acc[mt][ntt][1]);
                float2 v1 = make_float2(acc[mt][ntt][2], acc[mt][ntt][3]);
                if (res) {
                    float2 e0 = *(const float2*)&res[(size_t)row * ldr + col];
                    float2 e1 = *(const float2*)&res[(size_t)(row + 8) * ldr + col];
                    v0.x += e0.x; v0.y += e0.y; v1.x += e1.x; v1.y += e1.y;
                }
                *(float2*)&C[(size_t)row * ldc + col] = v0;
                *(float2*)&C[(size_t)(row + 8) * ldc + col] = v1;
            }
        }
}

// ---------------- fp32 SGEMM (small G matmul only) ----------------
__global__ __launch_bounds__(256, 2) void sgemm2_kernel(
    const float* __restrict__ A, int lda, size_t batchA,
    const float* __restrict__ W, int ldw, size_t batchW,
    float* __restrict__ C, int ldc, size_t batchC,
    int M, int N, int K)
{
    __shared__ float As[16][132];
    __shared__ float Ws[16][132];
    int tid = threadIdx.x;
    int tx = tid & 15, ty = tid >> 4;
    const float* Ab = A + (size_t)blockIdx.z * batchA;
    const float* Wb = W + (size_t)blockIdx.z * batchW;
    float*       Cb = C + (size_t)blockIdx.z * batchC;
    int rowBase = blockIdx.y * 128;
    int colBase = blockIdx.x * 128;

    float acc[8][8];
#pragma unroll
    for (int i = 0; i < 8; i++)
#pragma unroll
        for (int j = 0; j < 8; j++) acc[i][j] = 0.f;

    for (int k0 = 0; k0 < K; k0 += 16) {
#pragma unroll
        for (int i = 0; i < 2; i++) {
            int t = tid + i * 256;
            int r = t >> 2, kq = t & 3;
            float4 v = *(const float4*)&Ab[(size_t)(rowBase + r) * lda + k0 + kq * 4];
            As[kq * 4 + 0][r] = v.x; As[kq * 4 + 1][r] = v.y;
            As[kq * 4 + 2][r] = v.z; As[kq * 4 + 3][r] = v.w;
        }
#pragma unroll
        for (int i = 0; i < 2; i++) {
            int t = tid + i * 256;
            int r = t >> 2, kq = t & 3;
            float4 v = *(const float4*)&Wb[(size_t)(colBase + r) * ldw + k0 + kq * 4];
            Ws[kq * 4 + 0][r] = v.x; Ws[kq * 4 + 1][r] = v.y;
            Ws[kq * 4 + 2][r] = v.z; Ws[kq * 4 + 3][r] = v.w;
        }
        __syncthreads();
#pragma unroll
        for (int kk = 0; kk < 16; kk++) {
            float a[8], b[8];
            *(float4*)&a[0] = *(const float4*)&As[kk][ty * 8];
            *(float4*)&a[4] = *(const float4*)&As[kk][ty * 8 + 4];
            *(float4*)&b[0] = *(const float4*)&Ws[kk][tx * 8];
            *(float4*)&b[4] = *(const float4*)&Ws[kk][tx * 8 + 4];
#pragma unroll
            for (int i = 0; i < 8; i++)
#pragma unroll
                for (int j = 0; j < 8; j++) acc[i][j] += a[i] * b[j];
        }
        __syncthreads();
    }
#pragma unroll
    for (int i = 0; i < 8; i++) {
        int r = rowBase + ty * 8 + i;
        *(float4*)&Cb[(size_t)r * ldc + colBase + tx * 8]     = *(float4*)&acc[i][0];
        *(float4*)&Cb[(size_t)r * ldc + colBase + tx * 8 + 4] = *(float4*)&acc[i][4];
    }
}

// ---------------- depthwise causal conv(4) + SiLU ----------------
__global__ void conv_kernel(const float* __restrict__ conv_w, const float* __restrict__ conv_b) {
    int r = blockIdx.x;
    int bi = r / L_, l = r % L_;
    for (int c = threadIdx.x; c < CONV; c += 256) {
        float s = conv_b[c];
#pragma unroll
        for (int k = 0; k < DC; k++) {
            int lt = l + k - (DC - 1);
            if (lt >= 0)
                s += g_zx[(size_t)(bi * L_ + lt) * DIN + DI + c] * conv_w[c * DC + k];
        }
        float sig = 1.f / (1.f + __expf(-s));
        g_xBC[(size_t)r * CONV + c] = s * sig;
    }
}

// ---------------- fused: dt=softplus(dt+bias), dA=dt*A, per-chunk cumsum ----
__global__ void acs_kernel(const float* __restrict__ dt_bias, const float* __restrict__ A_log) {
    int blk = blockIdx.x, tid = threadIdx.x;
    int bi = blk / (NC * NH);
    int rem = blk % (NC * NH);
    int c = rem / NH, h = rem % NH;
    __shared__ float s[CS];
    int t = bi * L_ + c * CS + tid;
    float v = g_zx[(size_t)t * DIN + (DIN - NH) + h] + dt_bias[h];
    float dtv = (v > 20.f) ? v : log1pf(__expf(v));
    g_dt[t * NH + h] = dtv;
    s[tid] = -__expf(A_log[h]) * dtv;
    __syncthreads();
    for (int off = 1; off < CS; off <<= 1) {
        float p = (tid >= off) ? s[tid - off] : 0.f;
        __syncthreads();
        s[tid] += p;
        __syncthreads();
    }
    g_Acs[blk * CS + tid] = s[tid];
}

// ---------------- Y_diag + D*xh : running-product L, single pass ------------
constexpr int DIAG_SMEM = CS * 64 * 4;   // 64KB dynamic (X chunk)

__global__ __launch_bounds__(256) void diag_kernel(const float* __restrict__ Dp) {
    int blk = blockIdx.x, tid = threadIdx.x;
    int bi = blk / (NC * NH);
    int rem = blk % (NC * NH);
    int c = rem / NH, h = rem % NH;
    extern __shared__ float Xs[];        // [CS][64]
    __shared__ float Acss[CS];
    __shared__ float Es[CS];
    int rowBase = bi * L_ + c * CS;
    Acss[tid] = g_Acs[blk * CS + tid];
    __syncthreads();
    Es[tid] = __expf(tid ? Acss[tid] - Acss[tid - 1] : Acss[0]);

    {
        int p = tid & 63, s0 = tid >> 6;
        for (int i = 0; i < 64; i++) {
            int s = s0 + i * 4;
            int t = rowBase + s;
            Xs[s * 64 + p] = g_xBC[(size_t)t * CONV + h * HD + p] * g_dt[t * NH + h];
        }
    }
    __syncthreads();

    int l = tid;
    const float* GT = &g_G[(size_t)(bi * NC + c) * CS * CS];
    float y[64];
#pragma unroll
    for (int p = 0; p < 64; p++) y[p] = 0.f;

    float L = 0.f;
    for (int s = (l | 31); s >= 0; s--) {
        if (s == l) L = 1.f;
        if (s <= l) {
            float coef = GT[(size_t)s * CS + l] * L;
            const float* xr = &Xs[s * 64];
#pragma unroll
            for (int p = 0; p < 64; p++) y[p] += coef * xr[p];
        }
        L *= Es[s];
    }

    float dH = Dp[h];
    int t = rowBase + l;
    size_t ob = (size_t)t * DI + h * HD;
#pragma unroll
    for (int p = 0; p < 64; p++) {
        float xh = g_xBC[(size_t)t * CONV + h * HD + p];
        g_Y[ob + p] = y[p] + dH * xh;
    }
}

// ---------------- per-chunk state: states[p,n] = sum_l B[l,n]*decay*X[l,p] ---
__global__ __launch_bounds__(256) void states_kernel() {
    int blk = blockIdx.x, tid = threadIdx.x;
    int bi = blk / (NC * NH);
    int rem = blk % (NC * NH);
    int c = rem / NH, h = rem % NH;
    __shared__ float Xs[32][64];
    __shared__ float Bs[32][128];
    __shared__ float wdec[CS];
    int rowBase = bi * L_ + c * CS;
    float acsLast = g_Acs[blk * CS + (CS - 1)];
    wdec[tid] = __expf(acsLast - g_Acs[blk * CS + tid]);
    int tn = tid & 31, tp = tid >> 5;
    float acc[8][4];
#pragma unroll
    for (int i = 0; i < 8; i++)
#pragma unroll
        for (int j = 0; j < 4; j++) acc[i][j] = 0.f;

    for (int l0 = 0; l0 < CS; l0 += 32) {
        __syncthreads();
#pragma unroll
        for (int i = 0; i < 8; i++) {
            int lin = tid + i * 256;
            int s = lin >> 6, p = lin & 63;
            int t = rowBase + l0 + s;
            Xs[s][p] = g_xBC[(size_t)t * CONV + h * HD + p] * g_dt[t * NH + h] * wdec[l0 + s];
        }
#pragma unroll
        for (int i = 0; i < 16; i++) {
            int lin = tid + i * 256;
            int s = lin >> 7, n = lin & 127;
            Bs[s][n] = g_xBC[(size_t)(rowBase + l0 + s) * CONV + DI + n];
        }
        __syncthreads();
#pragma unroll 4
        for (int ll = 0; ll < 32; ll++) {
            float4 xa = *(const float4*)&Xs[ll][tp * 8];
            float4 xb = *(const float4*)&Xs[ll][tp * 8 + 4];
            float4 bv = *(const float4*)&Bs[ll][tn * 4];
            float xv[8] = {xa.x, xa.y, xa.z, xa.w, xb.x, xb.y, xb.z, xb.w};
            float bw[4] = {bv.x, bv.y, bv.z, bv.w};
#pragma unroll
            for (int i = 0; i < 8; i++)
#pragma unroll
                for (int j = 0; j < 4; j++) acc[i][j] += xv[i] * bw[j];
        }
    }
    size_t base = (size_t)blk * HD * DS;
#pragma unroll
    for (int i = 0; i < 8; i++) {
        int p = tp * 8 + i;
#pragma unroll
        for (int j = 0; j < 4; j++) {
            int n = tn * 4 + j;
            g_states[base + (size_t)p * DS + n] = acc[i][j];
        }
    }
}

// ---------------- inter-chunk scan (8-way element-parallel) ----------------
__global__ void cscan_kernel() {
    int part = blockIdx.x & 7;
    int hh = blockIdx.x >> 3;
    int bi = hh / NH, h = hh % NH;
    int tid = threadIdx.x;
    int ebase = part * 1024;
    float P[4];
#pragma unroll
    for (int j = 0; j < 4; j++) P[j] = 0.f;
    for (int c = 0; c < NC; c++) {
        int cb = (bi * NC + c) * NH + h;
        size_t sb = (size_t)cb * HD * DS;
        float T = __expf(g_Acs[cb * CS + (CS - 1)]);
#pragma unroll
        for (int j = 0; j < 4; j++) {
            int e = ebase + tid + j * 256;
            g_Sprev[sb + e] = P[j];
            P[j] = P[j] * T + g_states[sb + e];
        }
    }
}

// ---------------- Y_off : staged C + Sprev in smem (coalesced) --------------
constexpr int YOFF_SMEM = 2 * 64 * 129 * 4;   // 66048 bytes

__global__ __launch_bounds__(256) void yoff_kernel() {
    int blk = blockIdx.x, tid = threadIdx.x;
    int bi = blk / (NC * NH);
    int rem = blk % (NC * NH);
    int c = rem / NH, h = rem % NH;
    extern __shared__ float ysm[];
    float* Ss = ysm;                 // [64][129] : Sprev[p][n]
    float* Cs = ysm + 64 * 129;      // [64][129] : C chunk [l_local][n]
    int rowBase = bi * L_ + c * CS;
    size_t sb = (size_t)blk * HD * DS;

#pragma unroll
    for (int i = 0; i < 8; i++) {
        int idx = (tid + i * 256) * 4;
        int p = idx >> 7, n = idx & 127;
        float4 v = *(const float4*)&g_Sprev[sb + idx];
        float* d = &Ss[p * 129 + n];
        d[0] = v.x; d[1] = v.y; d[2] = v.z; d[3] = v.w;
    }

    int l_local = tid & 63;
    int pg = tid >> 6;

    for (int lc = 0; lc < 4; lc++) {
        __syncthreads();
#pragma unroll
        for (int i = 0; i < 8; i++) {
            int idx = (tid + i * 256) * 4;
            int r = idx >> 7, n = idx & 127;
            int t = rowBase + lc * 64 + r;
            float4 v = *(const float4*)&g_xBC[(size_t)t * CONV + DI + DS + n];
            float* d = &Cs[r * 129 + n];
            d[0] = v.x; d[1] = v.y; d[2] = v.z; d[3] = v.w;
        }
        __syncthreads();

        float acc[16];
#pragma unroll
        for (int pi = 0; pi < 16; pi++) acc[pi] = 0.f;
        const float* Crow = &Cs[l_local * 129];
        for (int n = 0; n < DS; n++) {
            float cv = Crow[n];
#pragma unroll
            for (int pi = 0; pi < 16; pi++) acc[pi] += cv * Ss[(pg * 16 + pi) * 129 + n];
        }

        int l = lc * 64 + l_local;
        float scale = __expf(g_Acs[blk * CS + l]);
        int t = rowBase + l;
        size_t ob = (size_t)t * DI + h * HD + pg * 16;
#pragma unroll
        for (int q = 0; q < 4; q++) {
            float4 y = *(float4*)&g_Y[ob + q * 4];
            y.x += scale * acc[q * 4 + 0];
            y.y += scale * acc[q * 4 + 1];
            y.z += scale * acc[q * 4 + 2];
            y.w += scale * acc[q * 4 + 3];
            *(float4*)&g_Y[ob + q * 4] = y;
        }
    }
}

// ---------------- gate with silu(z), group-RMS -> fp16 ---------------
__global__ void gate_kernel(const float* __restrict__ gnorm_w) {
    int r = blockIdx.x, tid = threadIdx.x;
    __shared__ float red[256];
    float g[8]; float sum = 0.f;
#pragma unroll
    for (int j = 0; j < 8; j++) {
        int i = tid + j * 256;
        float yv = g_Y[(size_t)r * DI + i];
        float z = g_zx[(size_t)r * DIN + i];
        float s = 1.f / (1.f + __expf(-z));
        float gv = yv * z * s;
        g[j] = gv; sum += gv * gv;
    }
    red[tid] = sum; __syncthreads();
    for (int s = 128; s > 0; s >>= 1) { if (tid < s) red[tid] += red[tid + s]; __syncthreads(); }
    float rinv = rsqrtf(red[0] / DI + EPS);
#pragma unroll
    for (int j = 0; j < 8; j++) {
        int i = tid + j * 256;
        g_yn[(size_t)r * DI + i] = __float2half_rn(g[j] * rinv * gnorm_w[i]);
    }
}

// ---------------- launch ----------------
extern "C" void kernel_launch(void* const* d_in, const int* in_sizes, int n_in,
                              void* d_out, int out_size) {
    const float* x          = (const float*)d_in[0];
    const float* norm_w     = (const float*)d_in[1];
    const float* in_proj_w  = (const float*)d_in[2];
    const float* conv_w     = (const float*)d_in[3];
    const float* conv_b     = (const float*)d_in[4];
    const float* dt_bias    = (const float*)d_in[5];
    const float* A_log      = (const float*)d_in[6];
    const float* Dp         = (const float*)d_in[7];
    const float* gnorm_w    = (const float*)d_in[8];
    const float* out_proj_w = (const float*)d_in[9];
    float* out = (float*)d_out;

    float *zx, *xBC, *Gb;
    __half *xn, *wi, *yn, *wo;
    cudaGetSymbolAddress((void**)&zx,  g_zx);
    cudaGetSymbolAddress((void**)&xBC, g_xBC);
    cudaGetSymbolAddress((void**)&Gb,  g_G);
    cudaGetSymbolAddress((void**)&xn,  g_xn);
    cudaGetSymbolAddress((void**)&wi,  g_wi);
    cudaGetSymbolAddress((void**)&yn,  g_yn);
    cudaGetSymbolAddress((void**)&wo,  g_wo);

    cudaFuncSetAttribute(mma_gemm_kernel,
                         cudaFuncAttributeMaxDynamicSharedMemorySize, GEMM_SMEM);
    cudaFuncSetAttribute(diag_kernel,
                         cudaFuncAttributeMaxDynamicSharedMemorySize, DIAG_SMEM);
    cudaFuncSetAttribute(yoff_kernel,
                         cudaFuncAttributeMaxDynamicSharedMemorySize, YOFF_SMEM);

    // launches 1-3 (ncu capture window lands on the in_proj GEMM, #4)
    rms_kernel<<<BL, 256>>>(x, norm_w);
    wconv_kernel<<<(DIN * DM / 4 + 255) / 256, 256>>>(in_proj_w, wi, DIN * DM / 4);
    wconv_kernel<<<(DM * DI / 4 + 255) / 256, 256>>>(out_proj_w, wo, DM * DI / 4);

    // #4: zxbcdt = xn @ in_proj_w^T   (4096 x 4384 x 1024)
    mma_gemm_kernel<<<dim3((DIN + 127) / 128, BL / 128), 256, GEMM_SMEM>>>(
        xn, wi, zx, DIN, nullptr, 0, BL, DIN, DM);

    conv_kernel<<<BL, 256>>>(conv_w, conv_b);
    acs_kernel<<<B_ * NC * NH, 256>>>(dt_bias, A_log);

    // GT[b,c] = Bm @ Cm^T per chunk (transposed G for coalesced diag reads)
    sgemm2_kernel<<<dim3(CS / 128, CS / 128, B_ * NC), 256>>>(
        xBC + DI,      CONV, (size_t)CS * CONV,
        xBC + DI + DS, CONV, (size_t)CS * CONV,
        Gb, CS, (size_t)CS * CS,
        CS, CS, DS);

    diag_kernel<<<B_ * NC * NH, 256, DIAG_SMEM>>>(Dp);
    states_kernel<<<B_ * NC * NH, 256>>>();
    cscan_kernel<<<B_ * NH * 8, 256>>>();
    yoff_kernel<<<B_ * NC * NH, 256, YOFF_SMEM>>>();
    gate_kernel<<<BL, 256>>>(gnorm_w);

    // out = x + yn @ out_proj_w^T   (4096 x 1024 x 2048)
    mma_gemm_kernel<<<dim3(DM / 128, BL / 128), 256, GEMM_SMEM>>>(
        yn, wo, out, DM, x, DM, BL, DM, DI);
}

// round 13
// speedup vs baseline: 4.0840x; 1.0943x over previous
#include <cuda_runtime.h>
#include <cuda_fp16.h>
#include <math.h>
#include <stdint.h>

// ---------------- problem constants ----------------
constexpr int B_  = 2;
constexpr int L_  = 2048;
constexpr int DM  = 1024;
constexpr int DS  = 128;
constexpr int DC  = 4;
constexpr int HD  = 64;
constexpr int DI  = 2048;      // EXP*DM
constexpr int NH  = 32;        // DI/HD
constexpr int CONV = DI + 2*DS;        // 2304
constexpr int DIN  = 2*DI + 2*DS + NH; // 4384
constexpr int CS  = 256;
constexpr int NC  = L_ / CS;   // 8
constexpr int BL  = B_ * L_;   // 4096
constexpr float EPS = 1e-5f;

// ---------------- scratch (static device globals; no cudaMalloc allowed) ----
__device__ float g_zx[(size_t)BL * DIN];
__device__ float g_xBC[(size_t)BL * CONV];
__device__ float g_dt[BL * NH];
__device__ float g_Acs[B_ * NC * NH * CS];
__device__ float g_G[(size_t)B_ * NC * CS * CS];   // TRANSPOSED: GT[s][l]
__device__ float g_states[(size_t)B_ * NC * NH * HD * DS];
__device__ float g_Sprev[(size_t)B_ * NC * NH * HD * DS];
__device__ float g_Y[(size_t)BL * DI];

// fp16 buffers for tensor-core GEMMs
__device__ __half g_xn[(size_t)BL * DM];
__device__ __half g_wi[(size_t)DIN * DM];
__device__ __half g_yn[(size_t)BL * DI];
__device__ __half g_wo[(size_t)DM * DI];

// ---------------- helpers ----------------
__device__ __forceinline__ void ldsm4(uint32_t &r0, uint32_t &r1, uint32_t &r2, uint32_t &r3,
                                      const __half* p) {
    uint32_t addr = (uint32_t)__cvta_generic_to_shared(p);
    asm volatile("ldmatrix.sync.aligned.m8n8.x4.shared.b16 {%0,%1,%2,%3}, [%4];"
                 : "=r"(r0), "=r"(r1), "=r"(r2), "=r"(r3) : "r"(addr));
}

__device__ __forceinline__ void mma16816(float* c, const uint32_t* a, const uint32_t* b) {
    asm volatile("mma.sync.aligned.m16n8k16.row.col.f32.f16.f16.f32 "
                 "{%0,%1,%2,%3}, {%4,%5,%6,%7}, {%8,%9}, {%0,%1,%2,%3};"
                 : "+f"(c[0]), "+f"(c[1]), "+f"(c[2]), "+f"(c[3])
                 : "r"(a[0]), "r"(a[1]), "r"(a[2]), "r"(a[3]), "r"(b[0]), "r"(b[1]));
}

__device__ __forceinline__ void cpa16(uint32_t saddr, const void* g, int sz) {
    asm volatile("cp.async.cg.shared.global [%0], [%1], 16, %2;"
                 :: "r"(saddr), "l"(g), "r"(sz));
}
__device__ __forceinline__ void cpa_commit() { asm volatile("cp.async.commit_group;"); }
template <int N>
__device__ __forceinline__ void cpa_wait() { asm volatile("cp.async.wait_group %0;" :: "n"(N)); }

// ---------------- weight convert: fp32 -> fp16 ----------------
__global__ void wconv_kernel(const float* __restrict__ src,
                             __half* __restrict__ dst, int n4) {
    int i = blockIdx.x * 256 + threadIdx.x;
    if (i >= n4) return;
    float4 v = ((const float4*)src)[i];
    __half2 a = make_half2(__float2half_rn(v.x), __float2half_rn(v.y));
    __half2 b = make_half2(__float2half_rn(v.z), __float2half_rn(v.w));
    ((__half2*)dst)[i * 2]     = a;
    ((__half2*)dst)[i * 2 + 1] = b;
}

// ---------------- RMSNorm on input -> fp16 ----------------
__global__ void rms_kernel(const float* __restrict__ x, const float* __restrict__ norm_w) {
    int r = blockIdx.x, tid = threadIdx.x;
    __shared__ float red[256];
    float v[4]; float sum = 0.f;
#pragma unroll
    for (int j = 0; j < 4; j++) {
        int i = tid + j * 256;
        v[j] = x[(size_t)r * DM + i];
        sum += v[j] * v[j];
    }
    red[tid] = sum; __syncthreads();
    for (int s = 128; s > 0; s >>= 1) { if (tid < s) red[tid] += red[tid + s]; __syncthreads(); }
    float rinv = rsqrtf(red[0] / DM + EPS);
#pragma unroll
    for (int j = 0; j < 4; j++) {
        int i = tid + j * 256;
        g_xn[(size_t)r * DM + i] = __float2half_rn(v[j] * rinv * norm_w[i]);
    }
}

// ---------------- fp16 tensor-core GEMM: C[M,N] = A[M,K] @ W[N,K]^T (+res) --
constexpr int ASTR = 72;             // smem half-stride (64 + 8 pad)
constexpr int ARR_H = 128 * ASTR;    // halfs per array (9216)
constexpr int STG_B = 2 * ARR_H * 2;               // bytes per stage (36864)
constexpr int GEMM_SMEM = 2 * STG_B;               // 73728

__global__ __launch_bounds__(256, 2) void mma_gemm_kernel(
    const __half* __restrict__ Ah,
    const __half* __restrict__ Wh,
    float* __restrict__ C, int ldc,
    const float* __restrict__ res, int ldr,
    int M, int N, int K)
{
    extern __shared__ __half smem[];
    int tid = threadIdx.x;
    int lane = tid & 31, warp = tid >> 5;
    int wm = warp >> 1, wn = warp & 1;
    int rowBase = blockIdx.y * 128;
    int colBase = blockIdx.x * 128;

    uint32_t sbase = (uint32_t)__cvta_generic_to_shared(smem);

    int rowA[4], seg[4], so[4], nW[4], wsz[4];
#pragma unroll
    for (int i = 0; i < 4; i++) {
        int id = tid + i * 256;
        rowA[i] = id >> 3; seg[i] = id & 7;
        so[i] = (rowA[i] * ASTR + seg[i] * 8) * 2;
        int n = colBase + rowA[i];
        wsz[i] = (n < N) ? 16 : 0;
        nW[i] = (n < N) ? n : 0;
    }

    int nt = K / 64;
    auto issue = [&](int t) {
        int st = t & 1;
        int k0 = t * 64;
        uint32_t sb = sbase + st * STG_B;
#pragma unroll
        for (int i = 0; i < 4; i++) {
            size_t ga = (size_t)(rowBase + rowA[i]) * K + k0 + seg[i] * 8;
            size_t gw = (size_t)nW[i] * K + k0 + seg[i] * 8;
            cpa16(sb + so[i],             Ah + ga, 16);
            cpa16(sb + ARR_H*2 + so[i],   Wh + gw, wsz[i]);
        }
        cpa_commit();
    };

    float acc[2][8][4];
#pragma unroll
    for (int mt = 0; mt < 2; mt++)
#pragma unroll
        for (int ntt = 0; ntt < 8; ntt++)
#pragma unroll
            for (int q = 0; q < 4; q++) acc[mt][ntt][q] = 0.f;

    issue(0);
    if (nt > 1) issue(1);

    for (int t = 0; t < nt; t++) {
        if (t + 1 < nt) cpa_wait<1>(); else cpa_wait<0>();
        __syncthreads();

        int st = t & 1;
        __half* Ash = smem + st * 2 * ARR_H;
        __half* Wsh = Ash + ARR_H;

#pragma unroll
        for (int kk = 0; kk < 64; kk += 16) {
            uint32_t ah[2][4];
#pragma unroll
            for (int mt = 0; mt < 2; mt++) {
                int r = wm * 32 + mt * 16 + (lane & 15);
                int c = kk + (lane >> 4) * 8;
                ldsm4(ah[mt][0], ah[mt][1], ah[mt][2], ah[mt][3], &Ash[r * ASTR + c]);
            }
            uint32_t bh[8][2];
#pragma unroll
            for (int np = 0; np < 4; np++) {
                int nb = wn * 64 + np * 16;
                int grp = lane >> 3;
                int r = nb + (grp >> 1) * 8 + (lane & 7);
                int c = kk + (grp & 1) * 8;
                ldsm4(bh[np*2][0], bh[np*2][1], bh[np*2+1][0], bh[np*2+1][1], &Wsh[r * ASTR + c]);
            }
#pragma unroll
            for (int mt = 0; mt < 2; mt++)
#pragma unroll
                for (int ntt = 0; ntt < 8; ntt++)
                    mma16816(acc[mt][ntt], ah[mt], bh[ntt]);
        }
        __syncthreads();
        if (t + 2 < nt) issue(t + 2);
    }

#pragma unroll
    for (int mt = 0; mt < 2; mt++)
#pragma unroll
        for (int ntt = 0; ntt < 8; ntt++) {
            int row = rowBase + wm * 32 + mt * 16 + (lane >> 2);
            int col = colBase + wn * 64 + ntt * 8 + (lane & 3) * 2;
            if (col < N) {
                float2 v0 = make_float2(acc[mt][ntt][0], acc[mt][ntt][1]);
                float2 v1 = make_float2(acc[mt][ntt][2], acc[mt][ntt][3]);
                if (res) {
                    float2 e0 = *(const float2*)&res[(size_t)row * ldr + col];
                    float2 e1 = *(const float2*)&res[(size_t)(row + 8) * ldr + col];
                    v0.x += e0.x; v0.y += e0.y; v1.x += e1.x; v1.y += e1.y;
                }
                *(float2*)&C[(size_t)row * ldc + col] = v0;
                *(float2*)&C[(size_t)(row + 8) * ldc + col] = v1;
            }
        }
}

// ---------------- fp32 SGEMM (small G matmul only) ----------------
__global__ __launch_bounds__(256, 2) void sgemm2_kernel(
    const float* __restrict__ A, int lda, size_t batchA,
    const float* __restrict__ W, int ldw, size_t batchW,
    float* __restrict__ C, int ldc, size_t batchC,
    int M, int N, int K)
{
    __shared__ float As[16][132];
    __shared__ float Ws[16][132];
    int tid = threadIdx.x;
    int tx = tid & 15, ty = tid >> 4;
    const float* Ab = A + (size_t)blockIdx.z * batchA;
    const float* Wb = W + (size_t)blockIdx.z * batchW;
    float*       Cb = C + (size_t)blockIdx.z * batchC;
    int rowBase = blockIdx.y * 128;
    int colBase = blockIdx.x * 128;

    float acc[8][8];
#pragma unroll
    for (int i = 0; i < 8; i++)
#pragma unroll
        for (int j = 0; j < 8; j++) acc[i][j] = 0.f;

    for (int k0 = 0; k0 < K; k0 += 16) {
#pragma unroll
        for (int i = 0; i < 2; i++) {
            int t = tid + i * 256;
            int r = t >> 2, kq = t & 3;
            float4 v = *(const float4*)&Ab[(size_t)(rowBase + r) * lda + k0 + kq * 4];
            As[kq * 4 + 0][r] = v.x; As[kq * 4 + 1][r] = v.y;
            As[kq * 4 + 2][r] = v.z; As[kq * 4 + 3][r] = v.w;
        }
#pragma unroll
        for (int i = 0; i < 2; i++) {
            int t = tid + i * 256;
            int r = t >> 2, kq = t & 3;
            float4 v = *(const float4*)&Wb[(size_t)(colBase + r) * ldw + k0 + kq * 4];
            Ws[kq * 4 + 0][r] = v.x; Ws[kq * 4 + 1][r] = v.y;
            Ws[kq * 4 + 2][r] = v.z; Ws[kq * 4 + 3][r] = v.w;
        }
        __syncthreads();
#pragma unroll
        for (int kk = 0; kk < 16; kk++) {
            float a[8], b[8];
            *(float4*)&a[0] = *(const float4*)&As[kk][ty * 8];
            *(float4*)&a[4] = *(const float4*)&As[kk][ty * 8 + 4];
            *(float4*)&b[0] = *(const float4*)&Ws[kk][tx * 8];
            *(float4*)&b[4] = *(const float4*)&Ws[kk][tx * 8 + 4];
#pragma unroll
            for (int i = 0; i < 8; i++)
#pragma unroll
                for (int j = 0; j < 8; j++) acc[i][j] += a[i] * b[j];
        }
        __syncthreads();
    }
#pragma unroll
    for (int i = 0; i < 8; i++) {
        int r = rowBase + ty * 8 + i;
        *(float4*)&Cb[(size_t)r * ldc + colBase + tx * 8]     = *(float4*)&acc[i][0];
        *(float4*)&Cb[(size_t)r * ldc + colBase + tx * 8 + 4] = *(float4*)&acc[i][4];
    }
}

// ---------------- depthwise causal conv(4) + SiLU ----------------
__global__ void conv_kernel(const float* __restrict__ conv_w, const float* __restrict__ conv_b) {
    int r = blockIdx.x;
    int bi = r / L_, l = r % L_;
    for (int c = threadIdx.x; c < CONV; c += 256) {
        float s = conv_b[c];
#pragma unroll
        for (int k = 0; k < DC; k++) {
            int lt = l + k - (DC - 1);
            if (lt >= 0)
                s += g_zx[(size_t)(bi * L_ + lt) * DIN + DI + c] * conv_w[c * DC + k];
        }
        float sig = 1.f / (1.f + __expf(-s));
        g_xBC[(size_t)r * CONV + c] = s * sig;
    }
}

// ---------------- fused: dt=softplus(dt+bias), dA=dt*A, per-chunk cumsum ----
__global__ void acs_kernel(const float* __restrict__ dt_bias, const float* __restrict__ A_log) {
    int blk = blockIdx.x, tid = threadIdx.x;
    int bi = blk / (NC * NH);
    int rem = blk % (NC * NH);
    int c = rem / NH, h = rem % NH;
    __shared__ float s[CS];
    int t = bi * L_ + c * CS + tid;
    float v = g_zx[(size_t)t * DIN + (DIN - NH) + h] + dt_bias[h];
    float dtv = (v > 20.f) ? v : log1pf(__expf(v));
    g_dt[t * NH + h] = dtv;
    s[tid] = -__expf(A_log[h]) * dtv;
    __syncthreads();
    for (int off = 1; off < CS; off <<= 1) {
        float p = (tid >= off) ? s[tid - off] : 0.f;
        __syncthreads();
        s[tid] += p;
        __syncthreads();
    }
    g_Acs[blk * CS + tid] = s[tid];
}

// ---------------- Y_diag via tensor cores ------------------------------------
// M[l][s] = GT[s][l] * L(l,s)  (causal, running-product decay), fp16 in smem.
// Xt[p][s] = X[s][p]*dt fp16 (same [N][K] shape as the GEMM's W operand).
// Y = M @ X via m16n8k16; warp wm handles rows [wm*32, wm*32+32), k <= wm*32+32.
constexpr int MSTR = 264;   // 256 + 8 pad (halfs)
constexpr int DIAG_SMEM = (256 * MSTR + 64 * MSTR) * 2;   // 168960 bytes

__global__ __launch_bounds__(256, 1) void diag_kernel(const float* __restrict__ Dp) {
    int blk = blockIdx.x, tid = threadIdx.x;
    int bi = blk / (NC * NH);
    int rem = blk % (NC * NH);
    int c = rem / NH, h = rem % NH;
    int lane = tid & 31, warp = tid >> 5;
    extern __shared__ __half dsm[];
    __half* Mh = dsm;                  // [256][MSTR]
    __half* Xt = dsm + 256 * MSTR;     // [64][MSTR]  Xt[p][s]
    __shared__ float Acss[CS];
    __shared__ float Es[CS];
    int rowBase = bi * L_ + c * CS;

    Acss[tid] = g_Acs[blk * CS + tid];
    __syncthreads();
    Es[tid] = __expf(tid ? Acss[tid] - Acss[tid - 1] : Acss[0]);

    // stage X transposed: Xt[p][s] = xBC[s][p] * dt[s]
    {
        int p = tid & 63, s0 = tid >> 6;
        for (int i = 0; i < 64; i++) {
            int s = s0 + i * 4;
            int t = rowBase + s;
            float v = g_xBC[(size_t)t * CONV + h * HD + p] * g_dt[t * NH + h];
            Xt[p * MSTR + s] = __float2half_rn(v);
        }
    }

    // build M row l (zeros for s>l within the warp's k-range)
    {
        int l = tid;
        const float* GT = &g_G[(size_t)(bi * NC + c) * CS * CS];
        float L = 0.f;
        for (int s = (l | 31); s >= 0; s--) {
            float v = 0.f;
            if (s == l) L = 1.f;
            if (s <= l) v = GT[(size_t)s * CS + l] * L;
            Mh[l * MSTR + s] = __float2half_rn(v);
            L *= Es[s];
        }
    }
    __syncthreads();

    // MMA: 8 warps, warp tile 32(m) x 64(n), k up to warp's causal bound
    float acc[2][8][4];
#pragma unroll
    for (int mt = 0; mt < 2; mt++)
#pragma unroll
        for (int ntt = 0; ntt < 8; ntt++)
#pragma unroll
            for (int q = 0; q < 4; q++) acc[mt][ntt][q] = 0.f;

    int kmax = warp * 32 + 32;
    for (int kk = 0; kk < kmax; kk += 16) {
        uint32_t ah[2][4];
#pragma unroll
        for (int mt = 0; mt < 2; mt++) {
            int r = warp * 32 + mt * 16 + (lane & 15);
            int cc = kk + (lane >> 4) * 8;
            ldsm4(ah[mt][0], ah[mt][1], ah[mt][2], ah[mt][3], &Mh[r * MSTR + cc]);
        }
        uint32_t bh[8][2];
#pragma unroll
        for (int np = 0; np < 4; np++) {
            int nb = np * 16;
            int grp = lane >> 3;
            int r = nb + (grp >> 1) * 8 + (lane & 7);
            int cc = kk + (grp & 1) * 8;
            ldsm4(bh[np*2][0], bh[np*2][1], bh[np*2+1][0], bh[np*2+1][1], &Xt[r * MSTR + cc]);
        }
#pragma unroll
        for (int mt = 0; mt < 2; mt++)
#pragma unroll
            for (int ntt = 0; ntt < 8; ntt++)
                mma16816(acc[mt][ntt], ah[mt], bh[ntt]);
    }

    // epilogue: Y = acc + D*xh
    float dH = Dp[h];
#pragma unroll
    for (int mt = 0; mt < 2; mt++)
#pragma unroll
        for (int ntt = 0; ntt < 8; ntt++) {
            int row = warp * 32 + mt * 16 + (lane >> 2);
            int col = ntt * 8 + (lane & 3) * 2;
#pragma unroll
            for (int half_ = 0; half_ < 2; half_++) {
                int r2 = row + half_ * 8;
                int t = rowBase + r2;
                float2 xh = *(const float2*)&g_xBC[(size_t)t * CONV + h * HD + col];
                float2 yv;
                yv.x = acc[mt][ntt][half_ * 2 + 0] + dH * xh.x;
                yv.y = acc[mt][ntt][half_ * 2 + 1] + dH * xh.y;
                *(float2*)&g_Y[(size_t)t * DI + h * HD + col] = yv;
            }
        }
}

// ---------------- per-chunk state: states[p,n] = sum_l B[l,n]*decay*X[l,p] ---
__global__ __launch_bounds__(256) void states_kernel() {
    int blk = blockIdx.x, tid = threadIdx.x;
    int bi = blk / (NC * NH);
    int rem = blk % (NC * NH);
    int c = rem / NH, h = rem % NH;
    __shared__ float Xs[32][64];
    __shared__ float Bs[32][128];
    __shared__ float wdec[CS];
    int rowBase = bi * L_ + c * CS;
    float acsLast = g_Acs[blk * CS + (CS - 1)];
    wdec[tid] = __expf(acsLast - g_Acs[blk * CS + tid]);
    int tn = tid & 31, tp = tid >> 5;
    float acc[8][4];
#pragma unroll
    for (int i = 0; i < 8; i++)
#pragma unroll
        for (int j = 0; j < 4; j++) acc[i][j] = 0.f;

    for (int l0 = 0; l0 < CS; l0 += 32) {
        __syncthreads();
#pragma unroll
        for (int i = 0; i < 8; i++) {
            int lin = tid + i * 256;
            int s = lin >> 6, p = lin & 63;
            int t = rowBase + l0 + s;
            Xs[s][p] = g_xBC[(size_t)t * CONV + h * HD + p] * g_dt[t * NH + h] * wdec[l0 + s];
        }
#pragma unroll
        for (int i = 0; i < 16; i++) {
            int lin = tid + i * 256;
            int s = lin >> 7, n = lin & 127;
            Bs[s][n] = g_xBC[(size_t)(rowBase + l0 + s) * CONV + DI + n];
        }
        __syncthreads();
#pragma unroll 4
        for (int ll = 0; ll < 32; ll++) {
            float4 xa = *(const float4*)&Xs[ll][tp * 8];
            float4 xb = *(const float4*)&Xs[ll][tp * 8 + 4];
            float4 bv = *(const float4*)&Bs[ll][tn * 4];
            float xv[8] = {xa.x, xa.y, xa.z, xa.w, xb.x, xb.y, xb.z, xb.w};
            float bw[4] = {bv.x, bv.y, bv.z, bv.w};
#pragma unroll
            for (int i = 0; i < 8; i++)
#pragma unroll
                for (int j = 0; j < 4; j++) acc[i][j] += xv[i] * bw[j];
        }
    }
    size_t base = (size_t)blk * HD * DS;
#pragma unroll
    for (int i = 0; i < 8; i++) {
        int p = tp * 8 + i;
#pragma unroll
        for (int j = 0; j < 4; j++) {
            int n = tn * 4 + j;
            g_states[base + (size_t)p * DS + n] = acc[i][j];
        }
    }
}

// ---------------- inter-chunk scan (8-way element-parallel) ----------------
__global__ void cscan_kernel() {
    int part = blockIdx.x & 7;
    int hh = blockIdx.x >> 3;
    int bi = hh / NH, h = hh % NH;
    int tid = threadIdx.x;
    int ebase = part * 1024;
    float P[4];
#pragma unroll
    for (int j = 0; j < 4; j++) P[j] = 0.f;
    for (int c = 0; c < NC; c++) {
        int cb = (bi * NC + c) * NH + h;
        size_t sb = (size_t)cb * HD * DS;
        float T = __expf(g_Acs[cb * CS + (CS - 1)]);
#pragma unroll
        for (int j = 0; j < 4; j++) {
            int e = ebase + tid + j * 256;
            g_Sprev[sb + e] = P[j];
            P[j] = P[j] * T + g_states[sb + e];
        }
    }
}

// ---------------- Y_off : staged C + Sprev in smem (coalesced) --------------
constexpr int YOFF_SMEM = 2 * 64 * 129 * 4;   // 66048 bytes

__global__ __launch_bounds__(256) void yoff_kernel() {
    int blk = blockIdx.x, tid = threadIdx.x;
    int bi = blk / (NC * NH);
    int rem = blk % (NC * NH);
    int c = rem / NH, h = rem % NH;
    extern __shared__ float ysm[];
    float* Ss = ysm;                 // [64][129] : Sprev[p][n]
    float* Cs = ysm + 64 * 129;      // [64][129] : C chunk [l_local][n]
    int rowBase = bi * L_ + c * CS;
    size_t sb = (size_t)blk * HD * DS;

#pragma unroll
    for (int i = 0; i < 8; i++) {
        int idx = (tid + i * 256) * 4;
        int p = idx >> 7, n = idx & 127;
        float4 v = *(const float4*)&g_Sprev[sb + idx];
        float* d = &Ss[p * 129 + n];
        d[0] = v.x; d[1] = v.y; d[2] = v.z; d[3] = v.w;
    }

    int l_local = tid & 63;
    int pg = tid >> 6;

    for (int lc = 0; lc < 4; lc++) {
        __syncthreads();
#pragma unroll
        for (int i = 0; i < 8; i++) {
            int idx = (tid + i * 256) * 4;
            int r = idx >> 7, n = idx & 127;
            int t = rowBase + lc * 64 + r;
            float4 v = *(const float4*)&g_xBC[(size_t)t * CONV + DI + DS + n];
            float* d = &Cs[r * 129 + n];
            d[0] = v.x; d[1] = v.y; d[2] = v.z; d[3] = v.w;
        }
        __syncthreads();

        float acc[16];
#pragma unroll
        for (int pi = 0; pi < 16; pi++) acc[pi] = 0.f;
        const float* Crow = &Cs[l_local * 129];
        for (int n = 0; n < DS; n++) {
            float cv = Crow[n];
#pragma unroll
            for (int pi = 0; pi < 16; pi++) acc[pi] += cv * Ss[(pg * 16 + pi) * 129 + n];
        }

        int l = lc * 64 + l_local;
        float scale = __expf(g_Acs[blk * CS + l]);
        int t = rowBase + l;
        size_t ob = (size_t)t * DI + h * HD + pg * 16;
#pragma unroll
        for (int q = 0; q < 4; q++) {
            float4 y = *(float4*)&g_Y[ob + q * 4];
            y.x += scale * acc[q * 4 + 0];
            y.y += scale * acc[q * 4 + 1];
            y.z += scale * acc[q * 4 + 2];
            y.w += scale * acc[q * 4 + 3];
            *(float4*)&g_Y[ob + q * 4] = y;
        }
    }
}

// ---------------- gate with silu(z), group-RMS -> fp16 ---------------
__global__ void gate_kernel(const float* __restrict__ gnorm_w) {
    int r = blockIdx.x, tid = threadIdx.x;
    __shared__ float red[256];
    float g[8]; float sum = 0.f;
#pragma unroll
    for (int j = 0; j < 8; j++) {
        int i = tid + j * 256;
        float yv = g_Y[(size_t)r * DI + i];
        float z = g_zx[(size_t)r * DIN + i];
        float s = 1.f / (1.f + __expf(-z));
        float gv = yv * z * s;
        g[j] = gv; sum += gv * gv;
    }
    red[tid] = sum; __syncthreads();
    for (int s = 128; s > 0; s >>= 1) { if (tid < s) red[tid] += red[tid + s]; __syncthreads(); }
    float rinv = rsqrtf(red[0] / DI + EPS);
#pragma unroll
    for (int j = 0; j < 8; j++) {
        int i = tid + j * 256;
        g_yn[(size_t)r * DI + i] = __float2half_rn(g[j] * rinv * gnorm_w[i]);
    }
}

// ---------------- launch ----------------
extern "C" void kernel_launch(void* const* d_in, const int* in_sizes, int n_in,
                              void* d_out, int out_size) {
    const float* x          = (const float*)d_in[0];
    const float* norm_w     = (const float*)d_in[1];
    const float* in_proj_w  = (const float*)d_in[2];
    const float* conv_w     = (const float*)d_in[3];
    const float* conv_b     = (const float*)d_in[4];
    const float* dt_bias    = (const float*)d_in[5];
    const float* A_log      = (const float*)d_in[6];
    const float* Dp         = (const float*)d_in[7];
    const float* gnorm_w    = (const float*)d_in[8];
    const float* out_proj_w = (const float*)d_in[9];
    float* out = (float*)d_out;

    float *zx, *xBC, *Gb;
    __half *xn, *wi, *yn, *wo;
    cudaGetSymbolAddress((void**)&zx,  g_zx);
    cudaGetSymbolAddress((void**)&xBC, g_xBC);
    cudaGetSymbolAddress((void**)&Gb,  g_G);
    cudaGetSymbolAddress((void**)&xn,  g_xn);
    cudaGetSymbolAddress((void**)&wi,  g_wi);
    cudaGetSymbolAddress((void**)&yn,  g_yn);
    cudaGetSymbolAddress((void**)&wo,  g_wo);

    cudaFuncSetAttribute(mma_gemm_kernel,
                         cudaFuncAttributeMaxDynamicSharedMemorySize, GEMM_SMEM);
    cudaFuncSetAttribute(diag_kernel,
                         cudaFuncAttributeMaxDynamicSharedMemorySize, DIAG_SMEM);
    cudaFuncSetAttribute(yoff_kernel,
                         cudaFuncAttributeMaxDynamicSharedMemorySize, YOFF_SMEM);

    // launches 1-3 (ncu capture window lands on the in_proj GEMM, #4)
    rms_kernel<<<BL, 256>>>(x, norm_w);
    wconv_kernel<<<(DIN * DM / 4 + 255) / 256, 256>>>(in_proj_w, wi, DIN * DM / 4);
    wconv_kernel<<<(DM * DI / 4 + 255) / 256, 256>>>(out_proj_w, wo, DM * DI / 4);

    // #4: zxbcdt = xn @ in_proj_w^T   (4096 x 4384 x 1024)
    mma_gemm_kernel<<<dim3((DIN + 127) / 128, BL / 128), 256, GEMM_SMEM>>>(
        xn, wi, zx, DIN, nullptr, 0, BL, DIN, DM);

    conv_kernel<<<BL, 256>>>(conv_w, conv_b);
    acs_kernel<<<B_ * NC * NH, 256>>>(dt_bias, A_log);

    // GT[b,c] = Bm @ Cm^T per chunk (transposed G for coalesced diag reads)
    sgemm2_kernel<<<dim3(CS / 128, CS / 128, B_ * NC), 256>>>(
        xBC + DI,      CONV, (size_t)CS * CONV,
        xBC + DI + DS, CONV, (size_t)CS * CONV,
        Gb, CS, (size_t)CS * CS,
        CS, CS, DS);

    diag_kernel<<<B_ * NC * NH, 256, DIAG_SMEM>>>(Dp);
    states_kernel<<<B_ * NC * NH, 256>>>();
    cscan_kernel<<<B_ * NH * 8, 256>>>();
    yoff_kernel<<<B_ * NC * NH, 256, YOFF_SMEM>>>();
    gate_kernel<<<BL, 256>>>(gnorm_w);

    // out = x + yn @ out_proj_w^T   (4096 x 1024 x 2048)
    mma_gemm_kernel<<<dim3(DM / 128, BL / 128), 256, GEMM_SMEM>>>(
        yn, wo, out, DM, x, DM, BL, DM, DI);
}

// round 14
// speedup vs baseline: 5.2132x; 1.2765x over previous
#include <cuda_runtime.h>
#include <cuda_fp16.h>
#include <math.h>
#include <stdint.h>

// ---------------- problem constants ----------------
constexpr int B_  = 2;
constexpr int L_  = 2048;
constexpr int DM  = 1024;
constexpr int DS  = 128;
constexpr int DC  = 4;
constexpr int HD  = 64;
constexpr int DI  = 2048;      // EXP*DM
constexpr int NH  = 32;        // DI/HD
constexpr int CONV = DI + 2*DS;        // 2304
constexpr int DIN  = 2*DI + 2*DS + NH; // 4384
constexpr int CS  = 256;
constexpr int NC  = L_ / CS;   // 8
constexpr int BL  = B_ * L_;   // 4096
constexpr float EPS = 1e-5f;

// ---------------- scratch (static device globals; no cudaMalloc allowed) ----
__device__ float g_zx[(size_t)BL * DIN];
__device__ float g_xBC[(size_t)BL * CONV];
__device__ float g_dt[BL * NH];
__device__ float g_Acs[B_ * NC * NH * CS];
__device__ float g_G[(size_t)B_ * NC * CS * CS];   // TRANSPOSED: GT[s][l]
__device__ float g_states[(size_t)B_ * NC * NH * HD * DS];
__device__ float g_Sprev[(size_t)B_ * NC * NH * HD * DS];
__device__ float g_Y[(size_t)BL * DI];

// fp16 buffers for tensor-core GEMMs
__device__ __half g_xn[(size_t)BL * DM];
__device__ __half g_wi[(size_t)DIN * DM];
__device__ __half g_yn[(size_t)BL * DI];
__device__ __half g_wo[(size_t)DM * DI];

// ---------------- helpers ----------------
__device__ __forceinline__ void ldsm4(uint32_t &r0, uint32_t &r1, uint32_t &r2, uint32_t &r3,
                                      const __half* p) {
    uint32_t addr = (uint32_t)__cvta_generic_to_shared(p);
    asm volatile("ldmatrix.sync.aligned.m8n8.x4.shared.b16 {%0,%1,%2,%3}, [%4];"
                 : "=r"(r0), "=r"(r1), "=r"(r2), "=r"(r3) : "r"(addr));
}

__device__ __forceinline__ void mma16816(float* c, const uint32_t* a, const uint32_t* b) {
    asm volatile("mma.sync.aligned.m16n8k16.row.col.f32.f16.f16.f32 "
                 "{%0,%1,%2,%3}, {%4,%5,%6,%7}, {%8,%9}, {%0,%1,%2,%3};"
                 : "+f"(c[0]), "+f"(c[1]), "+f"(c[2]), "+f"(c[3])
                 : "r"(a[0]), "r"(a[1]), "r"(a[2]), "r"(a[3]), "r"(b[0]), "r"(b[1]));
}

__device__ __forceinline__ void cpa16(uint32_t saddr, const void* g, int sz) {
    asm volatile("cp.async.cg.shared.global [%0], [%1], 16, %2;"
                 :: "r"(saddr), "l"(g), "r"(sz));
}
__device__ __forceinline__ void cpa_commit() { asm volatile("cp.async.commit_group;"); }
template <int N>
__device__ __forceinline__ void cpa_wait() { asm volatile("cp.async.wait_group %0;" :: "n"(N)); }

// ---------------- weight convert: fp32 -> fp16 ----------------
__global__ void wconv_kernel(const float* __restrict__ src,
                             __half* __restrict__ dst, int n4) {
    int i = blockIdx.x * 256 + threadIdx.x;
    if (i >= n4) return;
    float4 v = ((const float4*)src)[i];
    __half2 a = make_half2(__float2half_rn(v.x), __float2half_rn(v.y));
    __half2 b = make_half2(__float2half_rn(v.z), __float2half_rn(v.w));
    ((__half2*)dst)[i * 2]     = a;
    ((__half2*)dst)[i * 2 + 1] = b;
}

// ---------------- RMSNorm on input -> fp16 ----------------
__global__ void rms_kernel(const float* __restrict__ x, const float* __restrict__ norm_w) {
    int r = blockIdx.x, tid = threadIdx.x;
    __shared__ float red[256];
    float v[4]; float sum = 0.f;
#pragma unroll
    for (int j = 0; j < 4; j++) {
        int i = tid + j * 256;
        v[j] = x[(size_t)r * DM + i];
        sum += v[j] * v[j];
    }
    red[tid] = sum; __syncthreads();
    for (int s = 128; s > 0; s >>= 1) { if (tid < s) red[tid] += red[tid + s]; __syncthreads(); }
    float rinv = rsqrtf(red[0] / DM + EPS);
#pragma unroll
    for (int j = 0; j < 4; j++) {
        int i = tid + j * 256;
        g_xn[(size_t)r * DM + i] = __float2half_rn(v[j] * rinv * norm_w[i]);
    }
}

// ---------------- fp16 tensor-core GEMM: C[M,N] = A[M,K] @ W[N,K]^T (+res) --
constexpr int ASTR = 72;             // smem half-stride (64 + 8 pad)
constexpr int ARR_H = 128 * ASTR;    // halfs per array (9216)
constexpr int STG_B = 2 * ARR_H * 2;               // bytes per stage (36864)
constexpr int GEMM_SMEM = 2 * STG_B;               // 73728

__global__ __launch_bounds__(256, 2) void mma_gemm_kernel(
    const __half* __restrict__ Ah,
    const __half* __restrict__ Wh,
    float* __restrict__ C, int ldc,
    const float* __restrict__ res, int ldr,
    int M, int N, int K)
{
    extern __shared__ __half smem[];
    int tid = threadIdx.x;
    int lane = tid & 31, warp = tid >> 5;
    int wm = warp >> 1, wn = warp & 1;
    int rowBase = blockIdx.y * 128;
    int colBase = blockIdx.x * 128;

    uint32_t sbase = (uint32_t)__cvta_generic_to_shared(smem);

    int rowA[4], seg[4], so[4], nW[4], wsz[4];
#pragma unroll
    for (int i = 0; i < 4; i++) {
        int id = tid + i * 256;
        rowA[i] = id >> 3; seg[i] = id & 7;
        so[i] = (rowA[i] * ASTR + seg[i] * 8) * 2;
        int n = colBase + rowA[i];
        wsz[i] = (n < N) ? 16 : 0;
        nW[i] = (n < N) ? n : 0;
    }

    int nt = K / 64;
    auto issue = [&](int t) {
        int st = t & 1;
        int k0 = t * 64;
        uint32_t sb = sbase + st * STG_B;
#pragma unroll
        for (int i = 0; i < 4; i++) {
            size_t ga = (size_t)(rowBase + rowA[i]) * K + k0 + seg[i] * 8;
            size_t gw = (size_t)nW[i] * K + k0 + seg[i] * 8;
            cpa16(sb + so[i],             Ah + ga, 16);
            cpa16(sb + ARR_H*2 + so[i],   Wh + gw, wsz[i]);
        }
        cpa_commit();
    };

    float acc[2][8][4];
#pragma unroll
    for (int mt = 0; mt < 2; mt++)
#pragma unroll
        for (int ntt = 0; ntt < 8; ntt++)
#pragma unroll
            for (int q = 0; q < 4; q++) acc[mt][ntt][q] = 0.f;

    issue(0);
    if (nt > 1) issue(1);

    for (int t = 0; t < nt; t++) {
        if (t + 1 < nt) cpa_wait<1>(); else cpa_wait<0>();
        __syncthreads();

        int st = t & 1;
        __half* Ash = smem + st * 2 * ARR_H;
        __half* Wsh = Ash + ARR_H;

#pragma unroll
        for (int kk = 0; kk < 64; kk += 16) {
            uint32_t ah[2][4];
#pragma unroll
            for (int mt = 0; mt < 2; mt++) {
                int r = wm * 32 + mt * 16 + (lane & 15);
                int c = kk + (lane >> 4) * 8;
                ldsm4(ah[mt][0], ah[mt][1], ah[mt][2], ah[mt][3], &Ash[r * ASTR + c]);
            }
            uint32_t bh[8][2];
#pragma unroll
            for (int np = 0; np < 4; np++) {
                int nb = wn * 64 + np * 16;
                int grp = lane >> 3;
                int r = nb + (grp >> 1) * 8 + (lane & 7);
                int c = kk + (grp & 1) * 8;
                ldsm4(bh[np*2][0], bh[np*2][1], bh[np*2+1][0], bh[np*2+1][1], &Wsh[r * ASTR + c]);
            }
#pragma unroll
            for (int mt = 0; mt < 2; mt++)
#pragma unroll
                for (int ntt = 0; ntt < 8; ntt++)
                    mma16816(acc[mt][ntt], ah[mt], bh[ntt]);
        }
        __syncthreads();
        if (t + 2 < nt) issue(t + 2);
    }

#pragma unroll
    for (int mt = 0; mt < 2; mt++)
#pragma unroll
        for (int ntt = 0; ntt < 8; ntt++) {
            int row = rowBase + wm * 32 + mt * 16 + (lane >> 2);
            int col = colBase + wn * 64 + ntt * 8 + (lane & 3) * 2;
            if (col < N) {
                float2 v0 = make_float2(acc[mt][ntt][0], acc[mt][ntt][1]);
                float2 v1 = make_float2(acc[mt][ntt][2], acc[mt][ntt][3]);
                if (res) {
                    float2 e0 = *(const float2*)&res[(size_t)row * ldr + col];
                    float2 e1 = *(const float2*)&res[(size_t)(row + 8) * ldr + col];
                    v0.x += e0.x; v0.y += e0.y; v1.x += e1.x; v1.y += e1.y;
                }
                *(float2*)&C[(size_t)row * ldc + col] = v0;
                *(float2*)&C[(size_t)(row + 8) * ldc + col] = v1;
            }
        }
}

// ---------------- fp32 SGEMM (small G matmul only) ----------------
__global__ __launch_bounds__(256, 2) void sgemm2_kernel(
    const float* __restrict__ A, int lda, size_t batchA,
    const float* __restrict__ W, int ldw, size_t batchW,
    float* __restrict__ C, int ldc, size_t batchC,
    int M, int N, int K)
{
    __shared__ float As[16][132];
    __shared__ float Ws[16][132];
    int tid = threadIdx.x;
    int tx = tid & 15, ty = tid >> 4;
    const float* Ab = A + (size_t)blockIdx.z * batchA;
    const float* Wb = W + (size_t)blockIdx.z * batchW;
    float*       Cb = C + (size_t)blockIdx.z * batchC;
    int rowBase = blockIdx.y * 128;
    int colBase = blockIdx.x * 128;

    float acc[8][8];
#pragma unroll
    for (int i = 0; i < 8; i++)
#pragma unroll
        for (int j = 0; j < 8; j++) acc[i][j] = 0.f;

    for (int k0 = 0; k0 < K; k0 += 16) {
#pragma unroll
        for (int i = 0; i < 2; i++) {
            int t = tid + i * 256;
            int r = t >> 2, kq = t & 3;
            float4 v = *(const float4*)&Ab[(size_t)(rowBase + r) * lda + k0 + kq * 4];
            As[kq * 4 + 0][r] = v.x; As[kq * 4 + 1][r] = v.y;
            As[kq * 4 + 2][r] = v.z; As[kq * 4 + 3][r] = v.w;
        }
#pragma unroll
        for (int i = 0; i < 2; i++) {
            int t = tid + i * 256;
            int r = t >> 2, kq = t & 3;
            float4 v = *(const float4*)&Wb[(size_t)(colBase + r) * ldw + k0 + kq * 4];
            Ws[kq * 4 + 0][r] = v.x; Ws[kq * 4 + 1][r] = v.y;
            Ws[kq * 4 + 2][r] = v.z; Ws[kq * 4 + 3][r] = v.w;
        }
        __syncthreads();
#pragma unroll
        for (int kk = 0; kk < 16; kk++) {
            float a[8], b[8];
            *(float4*)&a[0] = *(const float4*)&As[kk][ty * 8];
            *(float4*)&a[4] = *(const float4*)&As[kk][ty * 8 + 4];
            *(float4*)&b[0] = *(const float4*)&Ws[kk][tx * 8];
            *(float4*)&b[4] = *(const float4*)&Ws[kk][tx * 8 + 4];
#pragma unroll
            for (int i = 0; i < 8; i++)
#pragma unroll
                for (int j = 0; j < 8; j++) acc[i][j] += a[i] * b[j];
        }
        __syncthreads();
    }
#pragma unroll
    for (int i = 0; i < 8; i++) {
        int r = rowBase + ty * 8 + i;
        *(float4*)&Cb[(size_t)r * ldc + colBase + tx * 8]     = *(float4*)&acc[i][0];
        *(float4*)&Cb[(size_t)r * ldc + colBase + tx * 8 + 4] = *(float4*)&acc[i][4];
    }
}

// ---------------- depthwise causal conv(4) + SiLU ----------------
__global__ void conv_kernel(const float* __restrict__ conv_w, const float* __restrict__ conv_b) {
    int r = blockIdx.x;
    int bi = r / L_, l = r % L_;
    for (int c = threadIdx.x; c < CONV; c += 256) {
        float s = conv_b[c];
#pragma unroll
        for (int k = 0; k < DC; k++) {
            int lt = l + k - (DC - 1);
            if (lt >= 0)
                s += g_zx[(size_t)(bi * L_ + lt) * DIN + DI + c] * conv_w[c * DC + k];
        }
        float sig = 1.f / (1.f + __expf(-s));
        g_xBC[(size_t)r * CONV + c] = s * sig;
    }
}

// ---------------- fused: dt=softplus(dt+bias), dA=dt*A, per-chunk cumsum ----
__global__ void acs_kernel(const float* __restrict__ dt_bias, const float* __restrict__ A_log) {
    int blk = blockIdx.x, tid = threadIdx.x;
    int bi = blk / (NC * NH);
    int rem = blk % (NC * NH);
    int c = rem / NH, h = rem % NH;
    __shared__ float s[CS];
    int t = bi * L_ + c * CS + tid;
    float v = g_zx[(size_t)t * DIN + (DIN - NH) + h] + dt_bias[h];
    float dtv = (v > 20.f) ? v : log1pf(__expf(v));
    g_dt[t * NH + h] = dtv;
    s[tid] = -__expf(A_log[h]) * dtv;
    __syncthreads();
    for (int off = 1; off < CS; off <<= 1) {
        float p = (tid >= off) ? s[tid - off] : 0.f;
        __syncthreads();
        s[tid] += p;
        __syncthreads();
    }
    g_Acs[blk * CS + tid] = s[tid];
}

// ---------------- Y_diag via tensor cores ------------------------------------
constexpr int MSTR = 264;   // 256 + 8 pad (halfs)
constexpr int DIAG_SMEM = (256 * MSTR + 64 * MSTR) * 2;   // 168960 bytes

__global__ __launch_bounds__(256, 1) void diag_kernel(const float* __restrict__ Dp) {
    int blk = blockIdx.x, tid = threadIdx.x;
    int bi = blk / (NC * NH);
    int rem = blk % (NC * NH);
    int c = rem / NH, h = rem % NH;
    int lane = tid & 31, warp = tid >> 5;
    extern __shared__ __half dsm[];
    __half* Mh = dsm;                  // [256][MSTR]
    __half* Xt = dsm + 256 * MSTR;     // [64][MSTR]  Xt[p][s]
    __shared__ float Acss[CS];
    __shared__ float Es[CS];
    int rowBase = bi * L_ + c * CS;

    Acss[tid] = g_Acs[blk * CS + tid];
    __syncthreads();
    Es[tid] = __expf(tid ? Acss[tid] - Acss[tid - 1] : Acss[0]);

    {
        int p = tid & 63, s0 = tid >> 6;
        for (int i = 0; i < 64; i++) {
            int s = s0 + i * 4;
            int t = rowBase + s;
            float v = g_xBC[(size_t)t * CONV + h * HD + p] * g_dt[t * NH + h];
            Xt[p * MSTR + s] = __float2half_rn(v);
        }
    }

    {
        int l = tid;
        const float* GT = &g_G[(size_t)(bi * NC + c) * CS * CS];
        float L = 0.f;
        for (int s = (l | 31); s >= 0; s--) {
            float v = 0.f;
            if (s == l) L = 1.f;
            if (s <= l) v = GT[(size_t)s * CS + l] * L;
            Mh[l * MSTR + s] = __float2half_rn(v);
            L *= Es[s];
        }
    }
    __syncthreads();

    float acc[2][8][4];
#pragma unroll
    for (int mt = 0; mt < 2; mt++)
#pragma unroll
        for (int ntt = 0; ntt < 8; ntt++)
#pragma unroll
            for (int q = 0; q < 4; q++) acc[mt][ntt][q] = 0.f;

    int kmax = warp * 32 + 32;
    for (int kk = 0; kk < kmax; kk += 16) {
        uint32_t ah[2][4];
#pragma unroll
        for (int mt = 0; mt < 2; mt++) {
            int r = warp * 32 + mt * 16 + (lane & 15);
            int cc = kk + (lane >> 4) * 8;
            ldsm4(ah[mt][0], ah[mt][1], ah[mt][2], ah[mt][3], &Mh[r * MSTR + cc]);
        }
        uint32_t bh[8][2];
#pragma unroll
        for (int np = 0; np < 4; np++) {
            int nb = np * 16;
            int grp = lane >> 3;
            int r = nb + (grp >> 1) * 8 + (lane & 7);
            int cc = kk + (grp & 1) * 8;
            ldsm4(bh[np*2][0], bh[np*2][1], bh[np*2+1][0], bh[np*2+1][1], &Xt[r * MSTR + cc]);
        }
#pragma unroll
        for (int mt = 0; mt < 2; mt++)
#pragma unroll
            for (int ntt = 0; ntt < 8; ntt++)
                mma16816(acc[mt][ntt], ah[mt], bh[ntt]);
    }

    float dH = Dp[h];
#pragma unroll
    for (int mt = 0; mt < 2; mt++)
#pragma unroll
        for (int ntt = 0; ntt < 8; ntt++) {
            int row = warp * 32 + mt * 16 + (lane >> 2);
            int col = ntt * 8 + (lane & 3) * 2;
#pragma unroll
            for (int half_ = 0; half_ < 2; half_++) {
                int r2 = row + half_ * 8;
                int t = rowBase + r2;
                float2 xh = *(const float2*)&g_xBC[(size_t)t * CONV + h * HD + col];
                float2 yv;
                yv.x = acc[mt][ntt][half_ * 2 + 0] + dH * xh.x;
                yv.y = acc[mt][ntt][half_ * 2 + 1] + dH * xh.y;
                *(float2*)&g_Y[(size_t)t * DI + h * HD + col] = yv;
            }
        }
}

// ---------------- per-chunk state via tensor cores ---------------------------
// states[p][n] = sum_l Xw[l][p] * B[l][n];  A=Xt[p][l], W=Bt[n][l] fp16.
// M=64, N=128, K=256; 8 warps (2m x 4n), warp tile 32x32.
constexpr int SSTR = 264;   // 256 + 8 pad
constexpr int STATES_SMEM = (64 * SSTR + 128 * SSTR) * 2;   // 101376 bytes

__global__ __launch_bounds__(256, 1) void states_kernel() {
    int blk = blockIdx.x, tid = threadIdx.x;
    int bi = blk / (NC * NH);
    int rem = blk % (NC * NH);
    int c = rem / NH, h = rem % NH;
    int lane = tid & 31, warp = tid >> 5;
    int wm = warp >> 2, wn = warp & 3;
    extern __shared__ __half ssm[];
    __half* Xt = ssm;                  // [64][SSTR]  Xt[p][l]
    __half* Bt = ssm + 64 * SSTR;      // [128][SSTR] Bt[n][l]
    __shared__ float wdec[CS];
    int rowBase = bi * L_ + c * CS;
    float acsLast = g_Acs[blk * CS + (CS - 1)];
    wdec[tid] = __expf(acsLast - g_Acs[blk * CS + tid]);
    __syncthreads();

    // stage Xt: coalesced reads over p
    {
        int p = tid & 63, l0 = tid >> 6;
        for (int i = 0; i < 64; i++) {
            int l = l0 + i * 4;
            int t = rowBase + l;
            float v = g_xBC[(size_t)t * CONV + h * HD + p] * g_dt[t * NH + h] * wdec[l];
            Xt[p * SSTR + l] = __float2half_rn(v);
        }
    }
    // stage Bt: coalesced reads over n
    {
        int n = tid & 127, l0 = tid >> 7;
        for (int i = 0; i < 128; i++) {
            int l = l0 + i * 2;
            float v = g_xBC[(size_t)(rowBase + l) * CONV + DI + n];
            Bt[n * SSTR + l] = __float2half_rn(v);
        }
    }
    __syncthreads();

    float acc[2][4][4];
#pragma unroll
    for (int mt = 0; mt < 2; mt++)
#pragma unroll
        for (int ntt = 0; ntt < 4; ntt++)
#pragma unroll
            for (int q = 0; q < 4; q++) acc[mt][ntt][q] = 0.f;

    for (int kk = 0; kk < 256; kk += 16) {
        uint32_t ah[2][4];
#pragma unroll
        for (int mt = 0; mt < 2; mt++) {
            int r = wm * 32 + mt * 16 + (lane & 15);
            int cc = kk + (lane >> 4) * 8;
            ldsm4(ah[mt][0], ah[mt][1], ah[mt][2], ah[mt][3], &Xt[r * SSTR + cc]);
        }
        uint32_t bh[4][2];
#pragma unroll
        for (int np = 0; np < 2; np++) {
            int nb = wn * 32 + np * 16;
            int grp = lane >> 3;
            int r = nb + (grp >> 1) * 8 + (lane & 7);
            int cc = kk + (grp & 1) * 8;
            ldsm4(bh[np*2][0], bh[np*2][1], bh[np*2+1][0], bh[np*2+1][1], &Bt[r * SSTR + cc]);
        }
#pragma unroll
        for (int mt = 0; mt < 2; mt++)
#pragma unroll
            for (int ntt = 0; ntt < 4; ntt++)
                mma16816(acc[mt][ntt], ah[mt], bh[ntt]);
    }

    size_t base = (size_t)blk * HD * DS;
#pragma unroll
    for (int mt = 0; mt < 2; mt++)
#pragma unroll
        for (int ntt = 0; ntt < 4; ntt++) {
            int p = wm * 32 + mt * 16 + (lane >> 2);
            int n = wn * 32 + ntt * 8 + (lane & 3) * 2;
            *(float2*)&g_states[base + (size_t)p * DS + n] =
                make_float2(acc[mt][ntt][0], acc[mt][ntt][1]);
            *(float2*)&g_states[base + (size_t)(p + 8) * DS + n] =
                make_float2(acc[mt][ntt][2], acc[mt][ntt][3]);
        }
}

// ---------------- inter-chunk scan (8-way element-parallel) ----------------
__global__ void cscan_kernel() {
    int part = blockIdx.x & 7;
    int hh = blockIdx.x >> 3;
    int bi = hh / NH, h = hh % NH;
    int tid = threadIdx.x;
    int ebase = part * 1024;
    float P[4];
#pragma unroll
    for (int j = 0; j < 4; j++) P[j] = 0.f;
    for (int c = 0; c < NC; c++) {
        int cb = (bi * NC + c) * NH + h;
        size_t sb = (size_t)cb * HD * DS;
        float T = __expf(g_Acs[cb * CS + (CS - 1)]);
#pragma unroll
        for (int j = 0; j < 4; j++) {
            int e = ebase + tid + j * 256;
            g_Sprev[sb + e] = P[j];
            P[j] = P[j] * T + g_states[sb + e];
        }
    }
}

// ---------------- Y_off via tensor cores -------------------------------------
// Yoff[l][p] = scale[l] * sum_n C[l][n]*Sprev[p][n]; A=Ch[l][n], W=Sh[p][n].
// M=256, N=64, K=128; 8 warps (4m x 2n), warp tile 64x32.
constexpr int YSTR = 136;   // 128 + 8 pad
constexpr int YOFF_SMEM = (256 * YSTR + 64 * YSTR) * 2;   // 87040 bytes

__global__ __launch_bounds__(256, 1) void yoff_kernel() {
    int blk = blockIdx.x, tid = threadIdx.x;
    int bi = blk / (NC * NH);
    int rem = blk % (NC * NH);
    int c = rem / NH, h = rem % NH;
    int lane = tid & 31, warp = tid >> 5;
    int wm = warp >> 1, wn = warp & 1;
    extern __shared__ __half ysm2[];
    __half* Ch = ysm2;                 // [256][YSTR]
    __half* Sh = ysm2 + 256 * YSTR;    // [64][YSTR]
    __shared__ float scl[CS];
    int rowBase = bi * L_ + c * CS;
    size_t sb = (size_t)blk * HD * DS;

    scl[tid] = __expf(g_Acs[blk * CS + tid]);

    // stage C: coalesced over n
    {
        int n = tid & 127, l0 = tid >> 7;
        for (int i = 0; i < 128; i++) {
            int l = l0 + i * 2;
            float v = g_xBC[(size_t)(rowBase + l) * CONV + DI + DS + n];
            Ch[l * YSTR + n] = __float2half_rn(v);
        }
    }
    // stage Sprev: coalesced over n
    {
        int n = tid & 127, p0 = tid >> 7;
        for (int i = 0; i < 32; i++) {
            int p = p0 + i * 2;
            Sh[p * YSTR + n] = __float2half_rn(g_Sprev[sb + (size_t)p * DS + n]);
        }
    }
    __syncthreads();

    float acc[4][4][4];
#pragma unroll
    for (int mt = 0; mt < 4; mt++)
#pragma unroll
        for (int ntt = 0; ntt < 4; ntt++)
#pragma unroll
            for (int q = 0; q < 4; q++) acc[mt][ntt][q] = 0.f;

    for (int kk = 0; kk < 128; kk += 16) {
        uint32_t ah[4][4];
#pragma unroll
        for (int mt = 0; mt < 4; mt++) {
            int r = wm * 64 + mt * 16 + (lane & 15);
            int cc = kk + (lane >> 4) * 8;
            ldsm4(ah[mt][0], ah[mt][1], ah[mt][2], ah[mt][3], &Ch[r * YSTR + cc]);
        }
        uint32_t bh[4][2];
#pragma unroll
        for (int np = 0; np < 2; np++) {
            int nb = wn * 32 + np * 16;
            int grp = lane >> 3;
            int r = nb + (grp >> 1) * 8 + (lane & 7);
            int cc = kk + (grp & 1) * 8;
            ldsm4(bh[np*2][0], bh[np*2][1], bh[np*2+1][0], bh[np*2+1][1], &Sh[r * YSTR + cc]);
        }
#pragma unroll
        for (int mt = 0; mt < 4; mt++)
#pragma unroll
            for (int ntt = 0; ntt < 4; ntt++)
                mma16816(acc[mt][ntt], ah[mt], bh[ntt]);
    }

#pragma unroll
    for (int mt = 0; mt < 4; mt++)
#pragma unroll
        for (int ntt = 0; ntt < 4; ntt++) {
            int row = wm * 64 + mt * 16 + (lane >> 2);
            int col = wn * 32 + ntt * 8 + (lane & 3) * 2;
#pragma unroll
            for (int half_ = 0; half_ < 2; half_++) {
                int l = row + half_ * 8;
                int t = rowBase + l;
                float sc = scl[l];
                size_t ob = (size_t)t * DI + h * HD + col;
                float2 y = *(float2*)&g_Y[ob];
                y.x += sc * acc[mt][ntt][half_ * 2 + 0];
                y.y += sc * acc[mt][ntt][half_ * 2 + 1];
                *(float2*)&g_Y[ob] = y;
            }
        }
}

// ---------------- gate with silu(z), group-RMS -> fp16 ---------------
__global__ void gate_kernel(const float* __restrict__ gnorm_w) {
    int r = blockIdx.x, tid = threadIdx.x;
    __shared__ float red[256];
    float g[8]; float sum = 0.f;
#pragma unroll
    for (int j = 0; j < 8; j++) {
        int i = tid + j * 256;
        float yv = g_Y[(size_t)r * DI + i];
        float z = g_zx[(size_t)r * DIN + i];
        float s = 1.f / (1.f + __expf(-z));
        float gv = yv * z * s;
        g[j] = gv; sum += gv * gv;
    }
    red[tid] = sum; __syncthreads();
    for (int s = 128; s > 0; s >>= 1) { if (tid < s) red[tid] += red[tid + s]; __syncthreads(); }
    float rinv = rsqrtf(red[0] / DI + EPS);
#pragma unroll
    for (int j = 0; j < 8; j++) {
        int i = tid + j * 256;
        g_yn[(size_t)r * DI + i] = __float2half_rn(g[j] * rinv * gnorm_w[i]);
    }
}

// ---------------- launch ----------------
extern "C" void kernel_launch(void* const* d_in, const int* in_sizes, int n_in,
                              void* d_out, int out_size) {
    const float* x          = (const float*)d_in[0];
    const float* norm_w     = (const float*)d_in[1];
    const float* in_proj_w  = (const float*)d_in[2];
    const float* conv_w     = (const float*)d_in[3];
    const float* conv_b     = (const float*)d_in[4];
    const float* dt_bias    = (const float*)d_in[5];
    const float* A_log      = (const float*)d_in[6];
    const float* Dp         = (const float*)d_in[7];
    const float* gnorm_w    = (const float*)d_in[8];
    const float* out_proj_w = (const float*)d_in[9];
    float* out = (float*)d_out;

    float *zx, *xBC, *Gb;
    __half *xn, *wi, *yn, *wo;
    cudaGetSymbolAddress((void**)&zx,  g_zx);
    cudaGetSymbolAddress((void**)&xBC, g_xBC);
    cudaGetSymbolAddress((void**)&Gb,  g_G);
    cudaGetSymbolAddress((void**)&xn,  g_xn);
    cudaGetSymbolAddress((void**)&wi,  g_wi);
    cudaGetSymbolAddress((void**)&yn,  g_yn);
    cudaGetSymbolAddress((void**)&wo,  g_wo);

    cudaFuncSetAttribute(mma_gemm_kernel,
                         cudaFuncAttributeMaxDynamicSharedMemorySize, GEMM_SMEM);
    cudaFuncSetAttribute(diag_kernel,
                         cudaFuncAttributeMaxDynamicSharedMemorySize, DIAG_SMEM);
    cudaFuncSetAttribute(states_kernel,
                         cudaFuncAttributeMaxDynamicSharedMemorySize, STATES_SMEM);
    cudaFuncSetAttribute(yoff_kernel,
                         cudaFuncAttributeMaxDynamicSharedMemorySize, YOFF_SMEM);

    // launches 1-3 (ncu capture window lands on the in_proj GEMM, #4)
    rms_kernel<<<BL, 256>>>(x, norm_w);
    wconv_kernel<<<(DIN * DM / 4 + 255) / 256, 256>>>(in_proj_w, wi, DIN * DM / 4);
    wconv_kernel<<<(DM * DI / 4 + 255) / 256, 256>>>(out_proj_w, wo, DM * DI / 4);

    // #4: zxbcdt = xn @ in_proj_w^T   (4096 x 4384 x 1024)
    mma_gemm_kernel<<<dim3((DIN + 127) / 128, BL / 128), 256, GEMM_SMEM>>>(
        xn, wi, zx, DIN, nullptr, 0, BL, DIN, DM);

    conv_kernel<<<BL, 256>>>(conv_w, conv_b);
    acs_kernel<<<B_ * NC * NH, 256>>>(dt_bias, A_log);

    // GT[b,c] = Bm @ Cm^T per chunk (transposed G for coalesced diag reads)
    sgemm2_kernel<<<dim3(CS / 128, CS / 128, B_ * NC), 256>>>(
        xBC + DI,      CONV, (size_t)CS * CONV,
        xBC + DI + DS, CONV, (size_t)CS * CONV,
        Gb, CS, (size_t)CS * CS,
        CS, CS, DS);

    diag_kernel<<<B_ * NC * NH, 256, DIAG_SMEM>>>(Dp);
    states_kernel<<<B_ * NC * NH, 256, STATES_SMEM>>>();
    cscan_kernel<<<B_ * NH * 8, 256>>>();
    yoff_kernel<<<B_ * NC * NH, 256, YOFF_SMEM>>>();
    gate_kernel<<<BL, 256>>>(gnorm_w);

    // out = x + yn @ out_proj_w^T   (4096 x 1024 x 2048)
    mma_gemm_kernel<<<dim3(DM / 128, BL / 128), 256, GEMM_SMEM>>>(
        yn, wo, out, DM, x, DM, BL, DM, DI);
}